// round 12
// baseline (speedup 1.0000x reference)
#include <cuda_runtime.h>
#include <cuda_bf16.h>
#include <cstdint>
#include <cstddef>

#define BB 32
#define CC 384
#define C3 1152
#define HH 56
#define WW 56
#define NN 3136
#define NH 12
#define HD 32
#define AG 49
#define NSEG 7
#define SCALE 0.17677669529663687f  // 32^-0.5

#define SA 136   // qkv A smem row stride (bf16)
#define SB 136   // B smem row stride (bf16)
#define SAP 40   // proj/stage2 A smem row stride (bf16)
#define SKV 40   // stage1/2 K/V smem row stride (bf16)

#define VROWS 244   // stage2 v tile rows (128 + 2*57 halo, padded even)
#define VSTR 20     // stage2 v tile row stride in 32-bit words

// ---------------- scratch (device globals; no allocation allowed) ----------------
__device__ __nv_bfloat16 g_qkv_bf[(size_t)BB * NN * C3];   // [b][n][3c] bf16
__device__ __nv_bfloat16 g_agentbf[(size_t)BB * AG * CC];  // agents * SCALE, bf16
__device__ float g_pb1[(size_t)NH * AG * NN];              // stage1 bias [h][a][n]
__device__ float g_ab1t[(size_t)NH * NN * 64];             // stage2 bias [h][n][64pad]
__device__ __nv_bfloat16 g_agentv_bf[(size_t)BB * NH * 64 * HD]; // [b][h][64pad][d]
__device__ __nv_bfloat16 g_x_bf[(size_t)BB * CC * NN];     // bf16 copy of x
__device__ __nv_bfloat16 g_qkvw_bf[(size_t)CC * C3];
__device__ __nv_bfloat16 g_projw_bf[(size_t)CC * CC];
__device__ __nv_bfloat16 g_omid_bf[(size_t)BB * NN * CC];  // attn out + dwconv
// stage-1 split-K partials
__device__ float g_s1m[(size_t)BB * NH * NSEG * AG];
__device__ float g_s1l[(size_t)BB * NH * NSEG * AG];
__device__ float g_s1acc[(size_t)BB * NH * NSEG * AG * HD];

// ---------------- asm helpers ---------------------------------------------------
__device__ __forceinline__ void cp16(uint32_t dst, const void* src, int sz) {
    asm volatile("cp.async.cg.shared.global [%0], [%1], 16, %2;\n"
                 :: "r"(dst), "l"(src), "r"(sz));
}
__device__ __forceinline__ void ldsm4t(uint32_t* r, uint32_t addr) {
    asm volatile("ldmatrix.sync.aligned.m8n8.x4.trans.shared.b16 {%0,%1,%2,%3}, [%4];\n"
                 : "=r"(r[0]), "=r"(r[1]), "=r"(r[2]), "=r"(r[3]) : "r"(addr));
}
__device__ __forceinline__ void ldsm4(uint32_t* r, uint32_t addr) {
    asm volatile("ldmatrix.sync.aligned.m8n8.x4.shared.b16 {%0,%1,%2,%3}, [%4];\n"
                 : "=r"(r[0]), "=r"(r[1]), "=r"(r[2]), "=r"(r[3]) : "r"(addr));
}
__device__ __forceinline__ void mma_bf16(float* d, const uint32_t* a,
                                         uint32_t b0, uint32_t b1) {
    asm volatile(
        "mma.sync.aligned.m16n8k16.row.col.f32.bf16.bf16.f32 "
        "{%0,%1,%2,%3}, {%4,%5,%6,%7}, {%8,%9}, {%0,%1,%2,%3};\n"
        : "+f"(d[0]), "+f"(d[1]), "+f"(d[2]), "+f"(d[3])
        : "r"(a[0]), "r"(a[1]), "r"(a[2]), "r"(a[3]), "r"(b0), "r"(b1));
}
__device__ __forceinline__ uint32_t packbf(float x, float y) {
    __nv_bfloat162 h = __floats2bfloat162_rn(x, y);
    return *(uint32_t*)&h;
}
__device__ __forceinline__ uint32_t smem_u32(const void* p) {
    return (uint32_t)__cvta_generic_to_shared(p);
}

// ---------------- kernel 0: fp32 -> bf16 conversion -----------------------------
__global__ void f2bf_kernel(const float* __restrict__ s, __nv_bfloat16* __restrict__ d,
                            size_t n) {
    size_t i = ((size_t)blockIdx.x * 256 + threadIdx.x) * 4;
    if (i >= n) return;
    float4 v = *(const float4*)(s + i);
    *(__nv_bfloat162*)(d + i)     = __floats2bfloat162_rn(v.x, v.y);
    *(__nv_bfloat162*)(d + i + 2) = __floats2bfloat162_rn(v.z, v.w);
}

// ---------------- kernel 1: bilinear upsample of position biases ----------------
__global__ void upsample_bias_kernel(const float* __restrict__ an,
                                     const float* __restrict__ na) {
    int idx = blockIdx.x * 256 + threadIdx.x;
    const int total = NH * AG * NN;
    if (idx >= total) return;
    int n  = idx % NN;
    int ha = idx / NN;
    int h  = ha / AG, a = ha % AG;
    int x = n % WW, y = n / WW;

    float fy = (y + 0.5f) * 0.125f - 0.5f;
    float fx = (x + 0.5f) * 0.125f - 0.5f;
    int y0 = (int)floorf(fy), x0 = (int)floorf(fx);
    float wy = fy - (float)y0, wx = fx - (float)x0;
    int iy0 = min(max(y0, 0), 6), iy1 = min(max(y0 + 1, 0), 6);
    int ix0 = min(max(x0, 0), 6), ix1 = min(max(x0 + 1, 0), 6);
    float w00 = (1.f - wy) * (1.f - wx), w01 = (1.f - wy) * wx;
    float w10 = wy * (1.f - wx),         w11 = wy * wx;

    const float* a_base = an + (size_t)ha * 49;
    const float* n_base = na + (size_t)ha * 49;
    g_pb1[idx] = w00 * a_base[iy0 * 7 + ix0] + w01 * a_base[iy0 * 7 + ix1]
               + w10 * a_base[iy1 * 7 + ix0] + w11 * a_base[iy1 * 7 + ix1];
    float nb = w00 * n_base[iy0 * 7 + ix0] + w01 * n_base[iy0 * 7 + ix1]
             + w10 * n_base[iy1 * 7 + ix0] + w11 * n_base[iy1 * 7 + ix1];
    g_ab1t[((size_t)h * NN + n) * 64 + a] = nb;
}

// ---------------- kernel 2: qkv GEMM via bf16 mma (L2-reuse grid order) ---------
// blockIdx.x = column tile (fast) so co-resident blocks share the x m-tile in L2.
__global__ __launch_bounds__(256) void qkv_bf16_kernel(const float* __restrict__ bias) {
    __shared__ __nv_bfloat16 As[2][32 * SA];
    __shared__ __nv_bfloat16 Bs[2][32 * SB];
    const int b  = blockIdx.z;
    const int m0 = blockIdx.y * 128;
    const int n0 = blockIdx.x * 128;
    const int tid = threadIdx.x, lane = tid & 31, wid = tid >> 5;
    const int wm = (wid & 1) * 64, wn = (wid >> 1) * 32;
    const int g = lane >> 2, t = lane & 3;
    const __nv_bfloat16* xb = g_x_bf + (size_t)b * CC * NN;

    uint32_t sAu[2], sBu[2];
    sAu[0] = smem_u32(As[0]); sAu[1] = smem_u32(As[1]);
    sBu[0] = smem_u32(Bs[0]); sBu[1] = smem_u32(Bs[1]);

    float d[4][4][4];
#pragma unroll
    for (int i = 0; i < 4; i++)
#pragma unroll
        for (int j = 0; j < 4; j++)
#pragma unroll
            for (int q = 0; q < 4; q++) d[i][j][q] = 0.f;

    auto issue = [&](int k0, int buf) {
#pragma unroll
        for (int r = 0; r < 2; r++) {
            int ci = tid + r * 256;
            int row = ci >> 4, c = ci & 15;
            int mcol = m0 + c * 8;
            cp16(sAu[buf] + (row * SA + c * 8) * 2,
                 xb + (size_t)(k0 + row) * NN + mcol, mcol < NN ? 16 : 0);
            cp16(sBu[buf] + (row * SB + c * 8) * 2,
                 g_qkvw_bf + (size_t)(k0 + row) * C3 + n0 + c * 8, 16);
        }
        asm volatile("cp.async.commit_group;\n");
    };

    issue(0, 0);
    const int rsel = (lane & 7) + ((lane >> 4) << 3);
    const int csel = ((lane >> 3) & 1) * 8;

    for (int s = 0; s < 12; s++) {
        if (s < 11) {
            issue((s + 1) * 32, (s + 1) & 1);
            asm volatile("cp.async.wait_group 1;\n");
        } else {
            asm volatile("cp.async.wait_group 0;\n");
        }
        __syncthreads();
        const uint32_t sa = sAu[s & 1], sb = sBu[s & 1];
#pragma unroll
        for (int kk = 0; kk < 32; kk += 16) {
            uint32_t a[4][4], bfr[2][4];
            int rA = kk + rsel;
#pragma unroll
            for (int mt = 0; mt < 4; mt++)
                ldsm4t(a[mt], sa + (rA * SA + wm + mt * 16 + csel) * 2);
#pragma unroll
            for (int bt = 0; bt < 2; bt++)
                ldsm4t(bfr[bt], sb + (rA * SB + wn + bt * 16 + csel) * 2);
#pragma unroll
            for (int mt = 0; mt < 4; mt++)
#pragma unroll
                for (int j = 0; j < 4; j++)
                    mma_bf16(d[mt][j], a[mt], bfr[j >> 1][j & 1], bfr[j >> 1][2 + (j & 1)]);
        }
        __syncthreads();
    }

#pragma unroll
    for (int mt = 0; mt < 4; mt++)
#pragma unroll
        for (int j = 0; j < 4; j++) {
            int row = m0 + wm + mt * 16 + g;
            int col = n0 + wn + j * 8 + 2 * t;
            float bv0 = __ldg(&bias[col]), bv1 = __ldg(&bias[col + 1]);
            if (row < NN)
                *(__nv_bfloat162*)&g_qkv_bf[((size_t)b * NN + row) * C3 + col] =
                    __floats2bfloat162_rn(d[mt][j][0] + bv0, d[mt][j][1] + bv1);
            if (row + 8 < NN)
                *(__nv_bfloat162*)&g_qkv_bf[((size_t)b * NN + row + 8) * C3 + col] =
                    __floats2bfloat162_rn(d[mt][j][2] + bv0, d[mt][j][3] + bv1);
        }
}

// ---------------- kernel 3: agent pooling -> scaled bf16 agents -----------------
__global__ void pool_kernel() {
    int idx = blockIdx.x * 256 + threadIdx.x;
    const int total = BB * AG * CC;
    if (idx >= total) return;
    int c = idx % CC;
    int a = (idx / CC) % AG;
    int b = idx / (CC * AG);
    int py = a / 7, px = a % 7;
    const __nv_bfloat16* q = g_qkv_bf + (size_t)b * NN * C3 + c;
    float s = 0.f;
#pragma unroll
    for (int dy = 0; dy < 8; dy++) {
        int row = (py * 8 + dy) * WW + px * 8;
#pragma unroll
        for (int dx = 0; dx < 8; dx++)
            s += __bfloat162float(q[(size_t)(row + dx) * C3]);
    }
    g_agentbf[idx] = __float2bfloat16_rn(s * 0.015625f * SCALE);
}

// ---------------- kernel 4: stage-1 agent attention via bf16 mma (split-K) ------
__global__ __launch_bounds__(128) void stage1_kernel() {
    __shared__ __nv_bfloat16 sK[2][64 * SKV];
    __shared__ __nv_bfloat16 sV[2][64 * SKV];

    const int tid = threadIdx.x, lane = tid & 31, warp = tid >> 5;
    const int bh = blockIdx.x, seg = blockIdx.y;
    const int b = bh / NH, h = bh % NH;
    const int g = lane >> 2, t = lane & 3;
    const int a_row0 = warp * 16 + g, a_row1 = a_row0 + 8;

    uint32_t skU[2], svU[2];
    skU[0] = smem_u32(sK[0]); skU[1] = smem_u32(sK[1]);
    svU[0] = smem_u32(sV[0]); svU[1] = smem_u32(sV[1]);

    uint32_t afrag[2][4];
    const __nv_bfloat16* agb = g_agentbf + (size_t)b * AG * CC + h * HD;
#pragma unroll
    for (int kt = 0; kt < 2; kt++) {
        int kb = kt * 16 + 2 * t;
        afrag[kt][0] = (a_row0 < AG) ? *(const uint32_t*)(agb + (size_t)a_row0 * CC + kb) : 0u;
        afrag[kt][1] = (a_row1 < AG) ? *(const uint32_t*)(agb + (size_t)a_row1 * CC + kb) : 0u;
        afrag[kt][2] = (a_row0 < AG) ? *(const uint32_t*)(agb + (size_t)a_row0 * CC + kb + 8) : 0u;
        afrag[kt][3] = (a_row1 < AG) ? *(const uint32_t*)(agb + (size_t)a_row1 * CC + kb + 8) : 0u;
    }

    float oacc[4][4];
#pragma unroll
    for (int i = 0; i < 4; i++)
#pragma unroll
        for (int j = 0; j < 4; j++) oacc[i][j] = 0.f;
    float rm0 = -1e30f, rm1 = -1e30f, rl0 = 0.f, rl1 = 0.f;

    const int krow = (lane & 7) + ((lane >> 4) & 1) * 8;
    const int koff = ((lane >> 3) & 1) * 8;
    const int rsel = (lane & 7) + ((lane >> 4) << 3);
    const int csel = ((lane >> 3) & 1) * 8;

    auto issue = [&](int chunk, int buf) {
        int n0 = chunk * 64;
#pragma unroll
        for (int r = 0; r < 2; r++) {
            int c = tid + r * 128;
            int row = c >> 2, sg = c & 3;
            const __nv_bfloat16* gk = g_qkv_bf
                + ((size_t)b * NN + n0 + row) * C3 + CC + h * HD + sg * 8;
            cp16(skU[buf] + (row * SKV + sg * 8) * 2, gk, 16);
            cp16(svU[buf] + (row * SKV + sg * 8) * 2, gk + CC, 16);
        }
        asm volatile("cp.async.commit_group;\n");
    };

    const float* bp0 = g_pb1 + ((size_t)h * AG + (a_row0 < AG ? a_row0 : 0)) * NN;
    const float* bp1 = g_pb1 + ((size_t)h * AG + (a_row1 < AG ? a_row1 : 0)) * NN;

    issue(seg * 7, 0);
    for (int ci = 0; ci < 7; ci++) {
        if (ci < 6) {
            issue(seg * 7 + ci + 1, (ci + 1) & 1);
            asm volatile("cp.async.wait_group 1;\n");
        } else {
            asm volatile("cp.async.wait_group 0;\n");
        }
        __syncthreads();
        const uint32_t sk = skU[ci & 1], sv = svU[ci & 1];
        const int n0 = (seg * 7 + ci) * 64;

        float sc[8][4];
#pragma unroll
        for (int j = 0; j < 8; j++) {
            float2 b0 = (a_row0 < AG) ? *(const float2*)(bp0 + n0 + j * 8 + 2 * t)
                                      : make_float2(0.f, 0.f);
            float2 b1 = (a_row1 < AG) ? *(const float2*)(bp1 + n0 + j * 8 + 2 * t)
                                      : make_float2(0.f, 0.f);
            sc[j][0] = b0.x; sc[j][1] = b0.y; sc[j][2] = b1.x; sc[j][3] = b1.y;
        }
#pragma unroll
        for (int jp = 0; jp < 4; jp++) {
            uint32_t kf0[4], kf1[4];
            ldsm4(kf0, sk + ((jp * 16 + krow) * SKV + koff) * 2);
            ldsm4(kf1, sk + ((jp * 16 + krow) * SKV + 16 + koff) * 2);
            mma_bf16(sc[jp * 2],     afrag[0], kf0[0], kf0[1]);
            mma_bf16(sc[jp * 2],     afrag[1], kf1[0], kf1[1]);
            mma_bf16(sc[jp * 2 + 1], afrag[0], kf0[2], kf0[3]);
            mma_bf16(sc[jp * 2 + 1], afrag[1], kf1[2], kf1[3]);
        }
        float mx0 = sc[0][0], mx1 = sc[0][2];
#pragma unroll
        for (int j = 0; j < 8; j++) {
            mx0 = fmaxf(mx0, fmaxf(sc[j][0], sc[j][1]));
            mx1 = fmaxf(mx1, fmaxf(sc[j][2], sc[j][3]));
        }
        mx0 = fmaxf(mx0, __shfl_xor_sync(0xffffffffu, mx0, 1));
        mx0 = fmaxf(mx0, __shfl_xor_sync(0xffffffffu, mx0, 2));
        mx1 = fmaxf(mx1, __shfl_xor_sync(0xffffffffu, mx1, 1));
        mx1 = fmaxf(mx1, __shfl_xor_sync(0xffffffffu, mx1, 2));
        float nm0 = fmaxf(rm0, mx0), nm1 = fmaxf(rm1, mx1);
        float corr0 = __expf(rm0 - nm0), corr1 = __expf(rm1 - nm1);
        float ls0 = 0.f, ls1 = 0.f;
#pragma unroll
        for (int j = 0; j < 8; j++) {
            sc[j][0] = __expf(sc[j][0] - nm0); ls0 += sc[j][0];
            sc[j][1] = __expf(sc[j][1] - nm0); ls0 += sc[j][1];
            sc[j][2] = __expf(sc[j][2] - nm1); ls1 += sc[j][2];
            sc[j][3] = __expf(sc[j][3] - nm1); ls1 += sc[j][3];
        }
        ls0 += __shfl_xor_sync(0xffffffffu, ls0, 1);
        ls0 += __shfl_xor_sync(0xffffffffu, ls0, 2);
        ls1 += __shfl_xor_sync(0xffffffffu, ls1, 1);
        ls1 += __shfl_xor_sync(0xffffffffu, ls1, 2);
        rl0 = rl0 * corr0 + ls0;
        rl1 = rl1 * corr1 + ls1;
        rm0 = nm0; rm1 = nm1;
#pragma unroll
        for (int nt = 0; nt < 4; nt++) {
            oacc[nt][0] *= corr0; oacc[nt][1] *= corr0;
            oacc[nt][2] *= corr1; oacc[nt][3] *= corr1;
        }
#pragma unroll
        for (int kt = 0; kt < 4; kt++) {
            uint32_t pf[4];
            pf[0] = packbf(sc[2 * kt][0], sc[2 * kt][1]);
            pf[1] = packbf(sc[2 * kt][2], sc[2 * kt][3]);
            pf[2] = packbf(sc[2 * kt + 1][0], sc[2 * kt + 1][1]);
            pf[3] = packbf(sc[2 * kt + 1][2], sc[2 * kt + 1][3]);
            uint32_t vb0[4], vb1[4];
            ldsm4t(vb0, sv + ((kt * 16 + rsel) * SKV + csel) * 2);
            ldsm4t(vb1, sv + ((kt * 16 + rsel) * SKV + 16 + csel) * 2);
            mma_bf16(oacc[0], pf, vb0[0], vb0[2]);
            mma_bf16(oacc[1], pf, vb0[1], vb0[3]);
            mma_bf16(oacc[2], pf, vb1[0], vb1[2]);
            mma_bf16(oacc[3], pf, vb1[1], vb1[3]);
        }
        __syncthreads();
    }

    const size_t base = ((size_t)bh * NSEG + seg) * AG;
#pragma unroll
    for (int nt = 0; nt < 4; nt++) {
        if (a_row0 < AG)
            *(float2*)&g_s1acc[(base + a_row0) * HD + nt * 8 + 2 * t] =
                make_float2(oacc[nt][0], oacc[nt][1]);
        if (a_row1 < AG)
            *(float2*)&g_s1acc[(base + a_row1) * HD + nt * 8 + 2 * t] =
                make_float2(oacc[nt][2], oacc[nt][3]);
    }
    if (t == 0) {
        if (a_row0 < AG) { g_s1m[base + a_row0] = rm0; g_s1l[base + a_row0] = rl0; }
        if (a_row1 < AG) { g_s1m[base + a_row1] = rm1; g_s1l[base + a_row1] = rl1; }
    }
}

// ---------------- kernel 4b: combine split-K partials -> bf16 agent_v -----------
__global__ __launch_bounds__(256) void stage1_reduce_kernel() {
    __shared__ float sW[NSEG][AG];
    __shared__ float sLs[AG];
    const int bh = blockIdx.x;
    const int tid = threadIdx.x;
    const size_t base = (size_t)bh * NSEG * AG;
    if (tid < AG) {
        float M = -1e30f;
#pragma unroll
        for (int s = 0; s < NSEG; s++)
            M = fmaxf(M, g_s1m[base + s * AG + tid]);
        float ls = 0.f;
#pragma unroll
        for (int s = 0; s < NSEG; s++) {
            float wv = __expf(g_s1m[base + s * AG + tid] - M);
            sW[s][tid] = wv;
            ls += wv * g_s1l[base + s * AG + tid];
        }
        sLs[tid] = ls;
    }
    __syncthreads();
    for (int i = tid; i < 64 * HD; i += 256) {
        int a = i >> 5, dd = i & 31;
        float r = 0.f;
        if (a < AG) {
            float acc = 0.f;
#pragma unroll
            for (int s = 0; s < NSEG; s++)
                acc += sW[s][a] * g_s1acc[(base + s * AG + a) * HD + dd];
            r = acc / sLs[a];
        }
        g_agentv_bf[(size_t)bh * 64 * HD + i] = __float2bfloat16_rn(r);
    }
}

// ---------------- kernel 5: stage-2 via bf16 mma + dwconv (smem-staged v) -------
__global__ __launch_bounds__(128) void stage2_mma_kernel(const float* __restrict__ dwc_w,
                                                         const float* __restrict__ dwc_b) {
    __shared__ __nv_bfloat16 sQ[128 * SAP];
    __shared__ __nv_bfloat16 sA[64 * SKV];
    __shared__ __nv_bfloat16 sV[64 * SKV];
    __shared__ uint32_t sVC[VROWS * VSTR];   // v tile with halo, bf16x2 words

    const int b = blockIdx.z, h = blockIdx.y, n0 = blockIdx.x * 128;
    const int tid = threadIdx.x, lane = tid & 31, warp = tid >> 5;
    const int g = lane >> 2, t = lane & 3;
    const int wm = warp * 32;

    uint32_t sQu = smem_u32(sQ);
    uint32_t sAu = smem_u32(sA);
    uint32_t sVu = smem_u32(sV);
    uint32_t sVCu = smem_u32(sVC);

#pragma unroll
    for (int r = 0; r < 4; r++) {
        int c = tid + r * 128;
        int row = c >> 2, sg = c & 3;
        int n = n0 + row;
        cp16(sQu + (row * SAP + sg * 8) * 2,
             g_qkv_bf + ((size_t)b * NN + (n < NN ? n : 0)) * C3 + h * HD + sg * 8,
             n < NN ? 16 : 0);
    }
    for (int c = tid; c < AG * 4; c += 128) {
        int row = c >> 2, sg = c & 3;
        cp16(sAu + (row * SKV + sg * 8) * 2,
             g_agentbf + ((size_t)b * AG + row) * CC + h * HD + sg * 8, 16);
    }
#pragma unroll
    for (int r = 0; r < 2; r++) {
        int c = tid + r * 128;
        int row = c >> 2, sg = c & 3;
        cp16(sVu + (row * SKV + sg * 8) * 2,
             g_agentv_bf + ((size_t)(b * NH + h) * 64 + row) * HD + sg * 8, 16);
    }
    {
        const __nv_bfloat16* vsrc = g_qkv_bf + (size_t)b * NN * C3 + 2 * CC + h * HD;
        for (int c = tid; c < VROWS * 4; c += 128) {
            int row = c >> 2, sg = c & 3;
            int n = n0 - 57 + row;
            int valid = (n >= 0 && n < NN);
            cp16(sVCu + (row * VSTR + sg * 4) * 4,
                 vsrc + (size_t)(valid ? n : 0) * C3 + sg * 8, valid ? 16 : 0);
        }
    }
    asm volatile("cp.async.commit_group;\n");
    asm volatile("cp.async.wait_group 0;\n");
    __syncthreads();

    const int rmA = (lane & 7) + ((lane >> 3) & 1) * 8;
    const int ckA = ((lane >> 4) << 3);
    const int krow = (lane & 7) + ((lane >> 4) & 1) * 8;
    const int koff = ((lane >> 3) & 1) * 8;
    const int rsel = (lane & 7) + ((lane >> 4) << 3);
    const int csel = ((lane >> 3) & 1) * 8;

    float sc[2][8][4];
#pragma unroll
    for (int mt = 0; mt < 2; mt++) {
        int r0 = n0 + wm + mt * 16 + g;
        int r1 = r0 + 8;
        const float* bq0 = g_ab1t + ((size_t)h * NN + (r0 < NN ? r0 : 0)) * 64;
        const float* bq1 = g_ab1t + ((size_t)h * NN + (r1 < NN ? r1 : 0)) * 64;
#pragma unroll
        for (int j = 0; j < 8; j++) {
            float2 v0 = *(const float2*)(bq0 + j * 8 + 2 * t);
            float2 v1 = *(const float2*)(bq1 + j * 8 + 2 * t);
            sc[mt][j][0] = v0.x; sc[mt][j][1] = v0.y;
            sc[mt][j][2] = v1.x; sc[mt][j][3] = v1.y;
        }
    }
#pragma unroll
    for (int kk = 0; kk < 32; kk += 16) {
        uint32_t a[2][4];
#pragma unroll
        for (int mt = 0; mt < 2; mt++)
            ldsm4(a[mt], sQu + ((wm + mt * 16 + rmA) * SAP + kk + ckA) * 2);
#pragma unroll
        for (int jp = 0; jp < 4; jp++) {
            uint32_t bf4[4];
            ldsm4(bf4, sAu + ((jp * 16 + krow) * SKV + kk + koff) * 2);
#pragma unroll
            for (int mt = 0; mt < 2; mt++) {
                mma_bf16(sc[mt][jp * 2],     a[mt], bf4[0], bf4[1]);
                mma_bf16(sc[mt][jp * 2 + 1], a[mt], bf4[2], bf4[3]);
            }
        }
    }
#pragma unroll
    for (int mt = 0; mt < 2; mt++)
#pragma unroll
        for (int j = 0; j < 8; j++) {
            int c0 = j * 8 + 2 * t;
            if (c0 >= AG)     { sc[mt][j][0] = -1e30f; sc[mt][j][2] = -1e30f; }
            if (c0 + 1 >= AG) { sc[mt][j][1] = -1e30f; sc[mt][j][3] = -1e30f; }
        }
#pragma unroll
    for (int mt = 0; mt < 2; mt++) {
        float mx0 = -1e30f, mx1 = -1e30f;
#pragma unroll
        for (int j = 0; j < 8; j++) {
            mx0 = fmaxf(mx0, fmaxf(sc[mt][j][0], sc[mt][j][1]));
            mx1 = fmaxf(mx1, fmaxf(sc[mt][j][2], sc[mt][j][3]));
        }
        mx0 = fmaxf(mx0, __shfl_xor_sync(0xffffffffu, mx0, 1));
        mx0 = fmaxf(mx0, __shfl_xor_sync(0xffffffffu, mx0, 2));
        mx1 = fmaxf(mx1, __shfl_xor_sync(0xffffffffu, mx1, 1));
        mx1 = fmaxf(mx1, __shfl_xor_sync(0xffffffffu, mx1, 2));
        float l0 = 0.f, l1 = 0.f;
#pragma unroll
        for (int j = 0; j < 8; j++) {
            sc[mt][j][0] = __expf(sc[mt][j][0] - mx0); l0 += sc[mt][j][0];
            sc[mt][j][1] = __expf(sc[mt][j][1] - mx0); l0 += sc[mt][j][1];
            sc[mt][j][2] = __expf(sc[mt][j][2] - mx1); l1 += sc[mt][j][2];
            sc[mt][j][3] = __expf(sc[mt][j][3] - mx1); l1 += sc[mt][j][3];
        }
        l0 += __shfl_xor_sync(0xffffffffu, l0, 1);
        l0 += __shfl_xor_sync(0xffffffffu, l0, 2);
        l1 += __shfl_xor_sync(0xffffffffu, l1, 1);
        l1 += __shfl_xor_sync(0xffffffffu, l1, 2);
        float i0 = 1.f / l0, i1 = 1.f / l1;
#pragma unroll
        for (int j = 0; j < 8; j++) {
            sc[mt][j][0] *= i0; sc[mt][j][1] *= i0;
            sc[mt][j][2] *= i1; sc[mt][j][3] *= i1;
        }
    }
    float oacc[2][4][4];
#pragma unroll
    for (int mt = 0; mt < 2; mt++)
#pragma unroll
        for (int j = 0; j < 4; j++)
#pragma unroll
            for (int q = 0; q < 4; q++) oacc[mt][j][q] = 0.f;
#pragma unroll
    for (int kt = 0; kt < 4; kt++) {
        uint32_t vb0[4], vb1[4];
        ldsm4t(vb0, sVu + ((kt * 16 + rsel) * SKV + csel) * 2);
        ldsm4t(vb1, sVu + ((kt * 16 + rsel) * SKV + 16 + csel) * 2);
#pragma unroll
        for (int mt = 0; mt < 2; mt++) {
            uint32_t pf[4];
            pf[0] = packbf(sc[mt][2 * kt][0], sc[mt][2 * kt][1]);
            pf[1] = packbf(sc[mt][2 * kt][2], sc[mt][2 * kt][3]);
            pf[2] = packbf(sc[mt][2 * kt + 1][0], sc[mt][2 * kt + 1][1]);
            pf[3] = packbf(sc[mt][2 * kt + 1][2], sc[mt][2 * kt + 1][3]);
            mma_bf16(oacc[mt][0], pf, vb0[0], vb0[2]);
            mma_bf16(oacc[mt][1], pf, vb0[1], vb0[3]);
            mma_bf16(oacc[mt][2], pf, vb1[0], vb1[2]);
            mma_bf16(oacc[mt][3], pf, vb1[1], vb1[3]);
        }
    }
#pragma unroll
    for (int nt = 0; nt < 4; nt++) {
        int c0l = nt * 8 + 2 * t;
        int c0  = h * HD + c0l;
        int cw  = nt * 4 + t;
        float bw0 = __ldg(&dwc_b[c0]), bw1 = __ldg(&dwc_b[c0 + 1]);
        float w0[9], w1[9];
#pragma unroll
        for (int k = 0; k < 9; k++) {
            w0[k] = __ldg(&dwc_w[c0 * 9 + k]);
            w1[k] = __ldg(&dwc_w[(c0 + 1) * 9 + k]);
        }
#pragma unroll
        for (int mt = 0; mt < 2; mt++)
#pragma unroll
            for (int rr = 0; rr < 2; rr++) {
                int n = n0 + wm + mt * 16 + g + rr * 8;
                if (n >= NN) continue;
                int y = n / WW, x = n % WW;
                float a0 = bw0, a1 = bw1;
#pragma unroll
                for (int ky = 0; ky < 3; ky++) {
                    int yy = y + ky - 1;
                    if (yy < 0 || yy >= HH) continue;
#pragma unroll
                    for (int kx = 0; kx < 3; kx++) {
                        int xx = x + kx - 1;
                        if (xx < 0 || xx >= WW) continue;
                        int tap = (yy * WW + xx) - n0 + 57;
                        uint32_t vw = sVC[tap * VSTR + cw];
                        float2 vf = __bfloat1622float2(*(__nv_bfloat162*)&vw);
                        a0 += vf.x * w0[ky * 3 + kx];
                        a1 += vf.y * w1[ky * 3 + kx];
                    }
                }
                float d0 = oacc[mt][nt][rr * 2] + a0;
                float d1 = oacc[mt][nt][rr * 2 + 1] + a1;
                *(__nv_bfloat162*)&g_omid_bf[((size_t)b * NN + n) * CC + c0] =
                    __floats2bfloat162_rn(d0, d1);
            }
    }
}

// ---------------- kernel 7: proj GEMM via bf16 mma (L2-reuse grid order) --------
__global__ __launch_bounds__(256) void proj_bf16_kernel(const float* __restrict__ bias,
                                                        const float* __restrict__ x,
                                                        float* __restrict__ out) {
    union Sm {
        struct { __nv_bfloat16 As[2][128 * SAP]; __nv_bfloat16 Bs[2][32 * SB]; } p;
        float tile[128 * 33];
    };
    __shared__ Sm sm;
    const int b  = blockIdx.z;
    const int m0 = blockIdx.y * 128;
    const int n0 = blockIdx.x * 128;
    const int tid = threadIdx.x, lane = tid & 31, wid = tid >> 5;
    const int wm = (wid & 1) * 64, wn = (wid >> 1) * 32;
    const int g = lane >> 2, t = lane & 3;

    uint32_t sAu[2], sBu[2];
    sAu[0] = smem_u32(sm.p.As[0]); sAu[1] = smem_u32(sm.p.As[1]);
    sBu[0] = smem_u32(sm.p.Bs[0]); sBu[1] = smem_u32(sm.p.Bs[1]);

    float d[4][4][4];
#pragma unroll
    for (int i = 0; i < 4; i++)
#pragma unroll
        for (int j = 0; j < 4; j++)
#pragma unroll
            for (int q = 0; q < 4; q++) d[i][j][q] = 0.f;

    const __nv_bfloat16* ab = g_omid_bf + ((size_t)b * NN + m0) * CC;

    auto issue = [&](int k0, int buf) {
#pragma unroll
        for (int r = 0; r < 2; r++) {
            int ci = tid + r * 256;
            int rowA = ci >> 2, cA = ci & 3;
            cp16(sAu[buf] + (rowA * SAP + cA * 8) * 2,
                 ab + (size_t)rowA * CC + k0 + cA * 8, (m0 + rowA) < NN ? 16 : 0);
            int rowB = ci >> 4, cB = ci & 15;
            cp16(sBu[buf] + (rowB * SB + cB * 8) * 2,
                 g_projw_bf + (size_t)(k0 + rowB) * CC + n0 + cB * 8, 16);
        }
        asm volatile("cp.async.commit_group;\n");
    };

    issue(0, 0);
    const int rmA = (lane & 7) + ((lane >> 3) & 1) * 8;
    const int ckA = ((lane >> 4) << 3);
    const int rsel = (lane & 7) + ((lane >> 4) << 3);
    const int csel = ((lane >> 3) & 1) * 8;

    for (int s = 0; s < 12; s++) {
        if (s < 11) {
            issue((s + 1) * 32, (s + 1) & 1);
            asm volatile("cp.async.wait_group 1;\n");
        } else {
            asm volatile("cp.async.wait_group 0;\n");
        }
        __syncthreads();
        const uint32_t sa = sAu[s & 1], sb = sBu[s & 1];
#pragma unroll
        for (int kk = 0; kk < 32; kk += 16) {
            uint32_t a[4][4], bfr[2][4];
#pragma unroll
            for (int mt = 0; mt < 4; mt++)
                ldsm4(a[mt], sa + ((wm + mt * 16 + rmA) * SAP + kk + ckA) * 2);
            int rB = kk + rsel;
#pragma unroll
            for (int bt = 0; bt < 2; bt++)
                ldsm4t(bfr[bt], sb + (rB * SB + wn + bt * 16 + csel) * 2);
#pragma unroll
            for (int mt = 0; mt < 4; mt++)
#pragma unroll
                for (int j = 0; j < 4; j++)
                    mma_bf16(d[mt][j], a[mt], bfr[j >> 1][j & 1], bfr[j >> 1][2 + (j & 1)]);
        }
        __syncthreads();
    }

#pragma unroll
    for (int p = 0; p < 4; p++) {
        __syncthreads();
        if ((wid >> 1) == p) {
#pragma unroll
            for (int mt = 0; mt < 4; mt++)
#pragma unroll
                for (int j = 0; j < 4; j++) {
                    int row = wm + mt * 16 + g;
                    int colL = j * 8 + 2 * t;
                    sm.tile[row * 33 + colL]           = d[mt][j][0];
                    sm.tile[row * 33 + colL + 1]       = d[mt][j][1];
                    sm.tile[(row + 8) * 33 + colL]     = d[mt][j][2];
                    sm.tile[(row + 8) * 33 + colL + 1] = d[mt][j][3];
                }
        }
        __syncthreads();
        int colc = tid >> 3;
        int ch = n0 + p * 32 + colc;
        float bvv = __ldg(&bias[ch]);
        size_t obase = ((size_t)b * CC + ch) * NN + m0;
#pragma unroll
        for (int jj = 0; jj < 4; jj++) {
            int m = (tid & 7) * 4 + 32 * jj;
            if (m0 + m + 4 > NN) continue;
            float v0 = sm.tile[(m + 0) * 33 + colc];
            float v1 = sm.tile[(m + 1) * 33 + colc];
            float v2 = sm.tile[(m + 2) * 33 + colc];
            float v3 = sm.tile[(m + 3) * 33 + colc];
            float4 xv = *(const float4*)&x[obase + m];
            float4 o;
            o.x = xv.x / (1.f + __expf(-(v0 + bvv)));
            o.y = xv.y / (1.f + __expf(-(v1 + bvv)));
            o.z = xv.z / (1.f + __expf(-(v2 + bvv)));
            o.w = xv.w / (1.f + __expf(-(v3 + bvv)));
            *(float4*)&out[obase + m] = o;
        }
    }
}

// ---------------- launch -------------------------------------------------------
extern "C" void kernel_launch(void* const* d_in, const int* in_sizes, int n_in,
                              void* d_out, int out_size) {
    const float* x      = (const float*)d_in[0];
    const float* qkv_w  = (const float*)d_in[1];
    const float* qkv_b  = (const float*)d_in[2];
    const float* proj_w = (const float*)d_in[3];
    const float* proj_b = (const float*)d_in[4];
    const float* an     = (const float*)d_in[5];
    const float* na     = (const float*)d_in[6];
    const float* dwc_w  = (const float*)d_in[7];
    const float* dwc_b  = (const float*)d_in[8];
    float* out = (float*)d_out;

    __nv_bfloat16* xbf; cudaGetSymbolAddress((void**)&xbf, g_x_bf);
    __nv_bfloat16* qwbf; cudaGetSymbolAddress((void**)&qwbf, g_qkvw_bf);
    __nv_bfloat16* pwbf; cudaGetSymbolAddress((void**)&pwbf, g_projw_bf);

    {
        size_t nx = (size_t)BB * CC * NN;
        f2bf_kernel<<<(unsigned)((nx / 4 + 255) / 256), 256>>>(x, xbf, nx);
        size_t nw = (size_t)CC * C3;
        f2bf_kernel<<<(unsigned)((nw / 4 + 255) / 256), 256>>>(qkv_w, qwbf, nw);
        size_t np = (size_t)CC * CC;
        f2bf_kernel<<<(unsigned)((np / 4 + 255) / 256), 256>>>(proj_w, pwbf, np);
    }
    upsample_bias_kernel<<<(NH * AG * NN + 255) / 256, 256>>>(an, na);
    qkv_bf16_kernel<<<dim3(C3 / 128, (NN + 127) / 128, BB), 256>>>(qkv_b);
    pool_kernel<<<(BB * AG * CC + 255) / 256, 256>>>();
    stage1_kernel<<<dim3(BB * NH, NSEG), 128>>>();
    stage1_reduce_kernel<<<BB * NH, 256>>>();
    stage2_mma_kernel<<<dim3((NN + 127) / 128, NH, BB), 128>>>(dwc_w, dwc_b);
    proj_bf16_kernel<<<dim3(CC / 128, (NN + 127) / 128, BB), 256>>>(proj_b, x, out);
}

// round 13
// speedup vs baseline: 1.0246x; 1.0246x over previous
#include <cuda_runtime.h>
#include <cuda_bf16.h>
#include <cstdint>
#include <cstddef>

#define BB 32
#define CC 384
#define C3 1152
#define HH 56
#define WW 56
#define NN 3136
#define NH 12
#define HD 32
#define AG 49
#define NSEG 7
#define SCALE 0.17677669529663687f  // 32^-0.5

#define SA 136   // qkv A smem row stride (bf16)
#define SB 136   // B smem row stride (bf16)
#define SAP 40   // proj/stage2 A smem row stride (bf16)
#define SKV 40   // stage1/2 K/V smem row stride (bf16)

// stage2 BM=256 tile
#define S2M 256
#define VROWS 372   // 256 + 2*57 halo, padded
#define VSTR 20     // v tile row stride in 32-bit words
// dynamic smem offsets (bytes)
#define S2_Q 0
#define S2_A (S2_Q + S2M * SAP * 2)        // 20480
#define S2_V (S2_A + 64 * SKV * 2)         // 25600
#define S2_VC (S2_V + 64 * SKV * 2)        // 30720
#define S2_TOTAL (S2_VC + VROWS * VSTR * 4) // 60480

// ---------------- scratch (device globals; no allocation allowed) ----------------
__device__ __nv_bfloat16 g_qkv_bf[(size_t)BB * NN * C3];   // [b][n][3c] bf16
__device__ __nv_bfloat16 g_agentbf[(size_t)BB * AG * CC];  // agents * SCALE, bf16
__device__ float g_pb1[(size_t)NH * AG * NN];              // stage1 bias [h][a][n]
__device__ float g_ab1t[(size_t)NH * NN * 64];             // stage2 bias [h][n][64pad]
__device__ __nv_bfloat16 g_agentv_bf[(size_t)BB * NH * 64 * HD]; // [b][h][64pad][d]
__device__ __nv_bfloat16 g_x_bf[(size_t)BB * CC * NN];     // bf16 copy of x
__device__ __nv_bfloat16 g_qkvw_bf[(size_t)CC * C3];
__device__ __nv_bfloat16 g_projw_bf[(size_t)CC * CC];
__device__ __nv_bfloat16 g_omid_bf[(size_t)BB * NN * CC];  // attn out + dwconv
// stage-1 split-K partials
__device__ float g_s1m[(size_t)BB * NH * NSEG * AG];
__device__ float g_s1l[(size_t)BB * NH * NSEG * AG];
__device__ float g_s1acc[(size_t)BB * NH * NSEG * AG * HD];

// ---------------- asm helpers ---------------------------------------------------
__device__ __forceinline__ void cp16(uint32_t dst, const void* src, int sz) {
    asm volatile("cp.async.cg.shared.global [%0], [%1], 16, %2;\n"
                 :: "r"(dst), "l"(src), "r"(sz));
}
__device__ __forceinline__ void ldsm4t(uint32_t* r, uint32_t addr) {
    asm volatile("ldmatrix.sync.aligned.m8n8.x4.trans.shared.b16 {%0,%1,%2,%3}, [%4];\n"
                 : "=r"(r[0]), "=r"(r[1]), "=r"(r[2]), "=r"(r[3]) : "r"(addr));
}
__device__ __forceinline__ void ldsm4(uint32_t* r, uint32_t addr) {
    asm volatile("ldmatrix.sync.aligned.m8n8.x4.shared.b16 {%0,%1,%2,%3}, [%4];\n"
                 : "=r"(r[0]), "=r"(r[1]), "=r"(r[2]), "=r"(r[3]) : "r"(addr));
}
__device__ __forceinline__ void mma_bf16(float* d, const uint32_t* a,
                                         uint32_t b0, uint32_t b1) {
    asm volatile(
        "mma.sync.aligned.m16n8k16.row.col.f32.bf16.bf16.f32 "
        "{%0,%1,%2,%3}, {%4,%5,%6,%7}, {%8,%9}, {%0,%1,%2,%3};\n"
        : "+f"(d[0]), "+f"(d[1]), "+f"(d[2]), "+f"(d[3])
        : "r"(a[0]), "r"(a[1]), "r"(a[2]), "r"(a[3]), "r"(b0), "r"(b1));
}
__device__ __forceinline__ uint32_t packbf(float x, float y) {
    __nv_bfloat162 h = __floats2bfloat162_rn(x, y);
    return *(uint32_t*)&h;
}
__device__ __forceinline__ uint32_t smem_u32(const void* p) {
    return (uint32_t)__cvta_generic_to_shared(p);
}

// ---------------- kernel 0: fp32 -> bf16 conversion -----------------------------
__global__ void f2bf_kernel(const float* __restrict__ s, __nv_bfloat16* __restrict__ d,
                            size_t n) {
    size_t i = ((size_t)blockIdx.x * 256 + threadIdx.x) * 4;
    if (i >= n) return;
    float4 v = *(const float4*)(s + i);
    *(__nv_bfloat162*)(d + i)     = __floats2bfloat162_rn(v.x, v.y);
    *(__nv_bfloat162*)(d + i + 2) = __floats2bfloat162_rn(v.z, v.w);
}

// ---------------- kernel 1: bilinear upsample of position biases ----------------
__global__ void upsample_bias_kernel(const float* __restrict__ an,
                                     const float* __restrict__ na) {
    int idx = blockIdx.x * 256 + threadIdx.x;
    const int total = NH * AG * NN;
    if (idx >= total) return;
    int n  = idx % NN;
    int ha = idx / NN;
    int h  = ha / AG, a = ha % AG;
    int x = n % WW, y = n / WW;

    float fy = (y + 0.5f) * 0.125f - 0.5f;
    float fx = (x + 0.5f) * 0.125f - 0.5f;
    int y0 = (int)floorf(fy), x0 = (int)floorf(fx);
    float wy = fy - (float)y0, wx = fx - (float)x0;
    int iy0 = min(max(y0, 0), 6), iy1 = min(max(y0 + 1, 0), 6);
    int ix0 = min(max(x0, 0), 6), ix1 = min(max(x0 + 1, 0), 6);
    float w00 = (1.f - wy) * (1.f - wx), w01 = (1.f - wy) * wx;
    float w10 = wy * (1.f - wx),         w11 = wy * wx;

    const float* a_base = an + (size_t)ha * 49;
    const float* n_base = na + (size_t)ha * 49;
    g_pb1[idx] = w00 * a_base[iy0 * 7 + ix0] + w01 * a_base[iy0 * 7 + ix1]
               + w10 * a_base[iy1 * 7 + ix0] + w11 * a_base[iy1 * 7 + ix1];
    float nb = w00 * n_base[iy0 * 7 + ix0] + w01 * n_base[iy0 * 7 + ix1]
             + w10 * n_base[iy1 * 7 + ix0] + w11 * n_base[iy1 * 7 + ix1];
    g_ab1t[((size_t)h * NN + n) * 64 + a] = nb;
}

// ---------------- kernel 2: qkv GEMM via bf16 mma, 2-stage (R11 proven) ---------
__global__ __launch_bounds__(256) void qkv_bf16_kernel(const float* __restrict__ bias) {
    __shared__ __nv_bfloat16 As[2][32 * SA];
    __shared__ __nv_bfloat16 Bs[2][32 * SB];
    const int b  = blockIdx.z;
    const int m0 = blockIdx.x * 128;
    const int n0 = blockIdx.y * 128;
    const int tid = threadIdx.x, lane = tid & 31, wid = tid >> 5;
    const int wm = (wid & 1) * 64, wn = (wid >> 1) * 32;
    const int g = lane >> 2, t = lane & 3;
    const __nv_bfloat16* xb = g_x_bf + (size_t)b * CC * NN;

    uint32_t sAu[2], sBu[2];
    sAu[0] = smem_u32(As[0]); sAu[1] = smem_u32(As[1]);
    sBu[0] = smem_u32(Bs[0]); sBu[1] = smem_u32(Bs[1]);

    float d[4][4][4];
#pragma unroll
    for (int i = 0; i < 4; i++)
#pragma unroll
        for (int j = 0; j < 4; j++)
#pragma unroll
            for (int q = 0; q < 4; q++) d[i][j][q] = 0.f;

    auto issue = [&](int k0, int buf) {
#pragma unroll
        for (int r = 0; r < 2; r++) {
            int ci = tid + r * 256;
            int row = ci >> 4, c = ci & 15;
            int mcol = m0 + c * 8;
            cp16(sAu[buf] + (row * SA + c * 8) * 2,
                 xb + (size_t)(k0 + row) * NN + mcol, mcol < NN ? 16 : 0);
            cp16(sBu[buf] + (row * SB + c * 8) * 2,
                 g_qkvw_bf + (size_t)(k0 + row) * C3 + n0 + c * 8, 16);
        }
        asm volatile("cp.async.commit_group;\n");
    };

    issue(0, 0);
    const int rsel = (lane & 7) + ((lane >> 4) << 3);
    const int csel = ((lane >> 3) & 1) * 8;

    for (int s = 0; s < 12; s++) {
        if (s < 11) {
            issue((s + 1) * 32, (s + 1) & 1);
            asm volatile("cp.async.wait_group 1;\n");
        } else {
            asm volatile("cp.async.wait_group 0;\n");
        }
        __syncthreads();
        const uint32_t sa = sAu[s & 1], sb = sBu[s & 1];
#pragma unroll
        for (int kk = 0; kk < 32; kk += 16) {
            uint32_t a[4][4], bfr[2][4];
            int rA = kk + rsel;
#pragma unroll
            for (int mt = 0; mt < 4; mt++)
                ldsm4t(a[mt], sa + (rA * SA + wm + mt * 16 + csel) * 2);
#pragma unroll
            for (int bt = 0; bt < 2; bt++)
                ldsm4t(bfr[bt], sb + (rA * SB + wn + bt * 16 + csel) * 2);
#pragma unroll
            for (int mt = 0; mt < 4; mt++)
#pragma unroll
                for (int j = 0; j < 4; j++)
                    mma_bf16(d[mt][j], a[mt], bfr[j >> 1][j & 1], bfr[j >> 1][2 + (j & 1)]);
        }
        __syncthreads();
    }

#pragma unroll
    for (int mt = 0; mt < 4; mt++)
#pragma unroll
        for (int j = 0; j < 4; j++) {
            int row = m0 + wm + mt * 16 + g;
            int col = n0 + wn + j * 8 + 2 * t;
            float bv0 = __ldg(&bias[col]), bv1 = __ldg(&bias[col + 1]);
            if (row < NN)
                *(__nv_bfloat162*)&g_qkv_bf[((size_t)b * NN + row) * C3 + col] =
                    __floats2bfloat162_rn(d[mt][j][0] + bv0, d[mt][j][1] + bv1);
            if (row + 8 < NN)
                *(__nv_bfloat162*)&g_qkv_bf[((size_t)b * NN + row + 8) * C3 + col] =
                    __floats2bfloat162_rn(d[mt][j][2] + bv0, d[mt][j][3] + bv1);
        }
}

// ---------------- kernel 3: agent pooling -> scaled bf16 agents -----------------
__global__ void pool_kernel() {
    int idx = blockIdx.x * 256 + threadIdx.x;
    const int total = BB * AG * CC;
    if (idx >= total) return;
    int c = idx % CC;
    int a = (idx / CC) % AG;
    int b = idx / (CC * AG);
    int py = a / 7, px = a % 7;
    const __nv_bfloat16* q = g_qkv_bf + (size_t)b * NN * C3 + c;
    float s = 0.f;
#pragma unroll
    for (int dy = 0; dy < 8; dy++) {
        int row = (py * 8 + dy) * WW + px * 8;
#pragma unroll
        for (int dx = 0; dx < 8; dx++)
            s += __bfloat162float(q[(size_t)(row + dx) * C3]);
    }
    g_agentbf[idx] = __float2bfloat16_rn(s * 0.015625f * SCALE);
}

// ---------------- kernel 4: stage-1 agent attention via bf16 mma (split-K) ------
__global__ __launch_bounds__(128) void stage1_kernel() {
    __shared__ __nv_bfloat16 sK[2][64 * SKV];
    __shared__ __nv_bfloat16 sV[2][64 * SKV];

    const int tid = threadIdx.x, lane = tid & 31, warp = tid >> 5;
    const int bh = blockIdx.x, seg = blockIdx.y;
    const int b = bh / NH, h = bh % NH;
    const int g = lane >> 2, t = lane & 3;
    const int a_row0 = warp * 16 + g, a_row1 = a_row0 + 8;

    uint32_t skU[2], svU[2];
    skU[0] = smem_u32(sK[0]); skU[1] = smem_u32(sK[1]);
    svU[0] = smem_u32(sV[0]); svU[1] = smem_u32(sV[1]);

    uint32_t afrag[2][4];
    const __nv_bfloat16* agb = g_agentbf + (size_t)b * AG * CC + h * HD;
#pragma unroll
    for (int kt = 0; kt < 2; kt++) {
        int kb = kt * 16 + 2 * t;
        afrag[kt][0] = (a_row0 < AG) ? *(const uint32_t*)(agb + (size_t)a_row0 * CC + kb) : 0u;
        afrag[kt][1] = (a_row1 < AG) ? *(const uint32_t*)(agb + (size_t)a_row1 * CC + kb) : 0u;
        afrag[kt][2] = (a_row0 < AG) ? *(const uint32_t*)(agb + (size_t)a_row0 * CC + kb + 8) : 0u;
        afrag[kt][3] = (a_row1 < AG) ? *(const uint32_t*)(agb + (size_t)a_row1 * CC + kb + 8) : 0u;
    }

    float oacc[4][4];
#pragma unroll
    for (int i = 0; i < 4; i++)
#pragma unroll
        for (int j = 0; j < 4; j++) oacc[i][j] = 0.f;
    float rm0 = -1e30f, rm1 = -1e30f, rl0 = 0.f, rl1 = 0.f;

    const int krow = (lane & 7) + ((lane >> 4) & 1) * 8;
    const int koff = ((lane >> 3) & 1) * 8;
    const int rsel = (lane & 7) + ((lane >> 4) << 3);
    const int csel = ((lane >> 3) & 1) * 8;

    auto issue = [&](int chunk, int buf) {
        int n0 = chunk * 64;
#pragma unroll
        for (int r = 0; r < 2; r++) {
            int c = tid + r * 128;
            int row = c >> 2, sg = c & 3;
            const __nv_bfloat16* gk = g_qkv_bf
                + ((size_t)b * NN + n0 + row) * C3 + CC + h * HD + sg * 8;
            cp16(skU[buf] + (row * SKV + sg * 8) * 2, gk, 16);
            cp16(svU[buf] + (row * SKV + sg * 8) * 2, gk + CC, 16);
        }
        asm volatile("cp.async.commit_group;\n");
    };

    const float* bp0 = g_pb1 + ((size_t)h * AG + (a_row0 < AG ? a_row0 : 0)) * NN;
    const float* bp1 = g_pb1 + ((size_t)h * AG + (a_row1 < AG ? a_row1 : 0)) * NN;

    issue(seg * 7, 0);
    for (int ci = 0; ci < 7; ci++) {
        if (ci < 6) {
            issue(seg * 7 + ci + 1, (ci + 1) & 1);
            asm volatile("cp.async.wait_group 1;\n");
        } else {
            asm volatile("cp.async.wait_group 0;\n");
        }
        __syncthreads();
        const uint32_t sk = skU[ci & 1], sv = svU[ci & 1];
        const int n0 = (seg * 7 + ci) * 64;

        float sc[8][4];
#pragma unroll
        for (int j = 0; j < 8; j++) {
            float2 b0 = (a_row0 < AG) ? *(const float2*)(bp0 + n0 + j * 8 + 2 * t)
                                      : make_float2(0.f, 0.f);
            float2 b1 = (a_row1 < AG) ? *(const float2*)(bp1 + n0 + j * 8 + 2 * t)
                                      : make_float2(0.f, 0.f);
            sc[j][0] = b0.x; sc[j][1] = b0.y; sc[j][2] = b1.x; sc[j][3] = b1.y;
        }
#pragma unroll
        for (int jp = 0; jp < 4; jp++) {
            uint32_t kf0[4], kf1[4];
            ldsm4(kf0, sk + ((jp * 16 + krow) * SKV + koff) * 2);
            ldsm4(kf1, sk + ((jp * 16 + krow) * SKV + 16 + koff) * 2);
            mma_bf16(sc[jp * 2],     afrag[0], kf0[0], kf0[1]);
            mma_bf16(sc[jp * 2],     afrag[1], kf1[0], kf1[1]);
            mma_bf16(sc[jp * 2 + 1], afrag[0], kf0[2], kf0[3]);
            mma_bf16(sc[jp * 2 + 1], afrag[1], kf1[2], kf1[3]);
        }
        float mx0 = sc[0][0], mx1 = sc[0][2];
#pragma unroll
        for (int j = 0; j < 8; j++) {
            mx0 = fmaxf(mx0, fmaxf(sc[j][0], sc[j][1]));
            mx1 = fmaxf(mx1, fmaxf(sc[j][2], sc[j][3]));
        }
        mx0 = fmaxf(mx0, __shfl_xor_sync(0xffffffffu, mx0, 1));
        mx0 = fmaxf(mx0, __shfl_xor_sync(0xffffffffu, mx0, 2));
        mx1 = fmaxf(mx1, __shfl_xor_sync(0xffffffffu, mx1, 1));
        mx1 = fmaxf(mx1, __shfl_xor_sync(0xffffffffu, mx1, 2));
        float nm0 = fmaxf(rm0, mx0), nm1 = fmaxf(rm1, mx1);
        float corr0 = __expf(rm0 - nm0), corr1 = __expf(rm1 - nm1);
        float ls0 = 0.f, ls1 = 0.f;
#pragma unroll
        for (int j = 0; j < 8; j++) {
            sc[j][0] = __expf(sc[j][0] - nm0); ls0 += sc[j][0];
            sc[j][1] = __expf(sc[j][1] - nm0); ls0 += sc[j][1];
            sc[j][2] = __expf(sc[j][2] - nm1); ls1 += sc[j][2];
            sc[j][3] = __expf(sc[j][3] - nm1); ls1 += sc[j][3];
        }
        ls0 += __shfl_xor_sync(0xffffffffu, ls0, 1);
        ls0 += __shfl_xor_sync(0xffffffffu, ls0, 2);
        ls1 += __shfl_xor_sync(0xffffffffu, ls1, 1);
        ls1 += __shfl_xor_sync(0xffffffffu, ls1, 2);
        rl0 = rl0 * corr0 + ls0;
        rl1 = rl1 * corr1 + ls1;
        rm0 = nm0; rm1 = nm1;
#pragma unroll
        for (int nt = 0; nt < 4; nt++) {
            oacc[nt][0] *= corr0; oacc[nt][1] *= corr0;
            oacc[nt][2] *= corr1; oacc[nt][3] *= corr1;
        }
#pragma unroll
        for (int kt = 0; kt < 4; kt++) {
            uint32_t pf[4];
            pf[0] = packbf(sc[2 * kt][0], sc[2 * kt][1]);
            pf[1] = packbf(sc[2 * kt][2], sc[2 * kt][3]);
            pf[2] = packbf(sc[2 * kt + 1][0], sc[2 * kt + 1][1]);
            pf[3] = packbf(sc[2 * kt + 1][2], sc[2 * kt + 1][3]);
            uint32_t vb0[4], vb1[4];
            ldsm4t(vb0, sv + ((kt * 16 + rsel) * SKV + csel) * 2);
            ldsm4t(vb1, sv + ((kt * 16 + rsel) * SKV + 16 + csel) * 2);
            mma_bf16(oacc[0], pf, vb0[0], vb0[2]);
            mma_bf16(oacc[1], pf, vb0[1], vb0[3]);
            mma_bf16(oacc[2], pf, vb1[0], vb1[2]);
            mma_bf16(oacc[3], pf, vb1[1], vb1[3]);
        }
        __syncthreads();
    }

    const size_t base = ((size_t)bh * NSEG + seg) * AG;
#pragma unroll
    for (int nt = 0; nt < 4; nt++) {
        if (a_row0 < AG)
            *(float2*)&g_s1acc[(base + a_row0) * HD + nt * 8 + 2 * t] =
                make_float2(oacc[nt][0], oacc[nt][1]);
        if (a_row1 < AG)
            *(float2*)&g_s1acc[(base + a_row1) * HD + nt * 8 + 2 * t] =
                make_float2(oacc[nt][2], oacc[nt][3]);
    }
    if (t == 0) {
        if (a_row0 < AG) { g_s1m[base + a_row0] = rm0; g_s1l[base + a_row0] = rl0; }
        if (a_row1 < AG) { g_s1m[base + a_row1] = rm1; g_s1l[base + a_row1] = rl1; }
    }
}

// ---------------- kernel 4b: combine split-K partials -> bf16 agent_v -----------
__global__ __launch_bounds__(256) void stage1_reduce_kernel() {
    __shared__ float sW[NSEG][AG];
    __shared__ float sLs[AG];
    const int bh = blockIdx.x;
    const int tid = threadIdx.x;
    const size_t base = (size_t)bh * NSEG * AG;
    if (tid < AG) {
        float M = -1e30f;
#pragma unroll
        for (int s = 0; s < NSEG; s++)
            M = fmaxf(M, g_s1m[base + s * AG + tid]);
        float ls = 0.f;
#pragma unroll
        for (int s = 0; s < NSEG; s++) {
            float wv = __expf(g_s1m[base + s * AG + tid] - M);
            sW[s][tid] = wv;
            ls += wv * g_s1l[base + s * AG + tid];
        }
        sLs[tid] = ls;
    }
    __syncthreads();
    for (int i = tid; i < 64 * HD; i += 256) {
        int a = i >> 5, dd = i & 31;
        float r = 0.f;
        if (a < AG) {
            float acc = 0.f;
#pragma unroll
            for (int s = 0; s < NSEG; s++)
                acc += sW[s][a] * g_s1acc[(base + s * AG + a) * HD + dd];
            r = acc / sLs[a];
        }
        g_agentv_bf[(size_t)bh * 64 * HD + i] = __float2bfloat16_rn(r);
    }
}

// ---------------- kernel 5: stage-2 BM=256 via bf16 mma + dwconv (smem v) -------
__global__ __launch_bounds__(256) void stage2_mma_kernel(const float* __restrict__ dwc_w,
                                                         const float* __restrict__ dwc_b) {
    extern __shared__ char dsm[];
    __nv_bfloat16* sQ = (__nv_bfloat16*)(dsm + S2_Q);
    __nv_bfloat16* sA = (__nv_bfloat16*)(dsm + S2_A);
    __nv_bfloat16* sV = (__nv_bfloat16*)(dsm + S2_V);
    uint32_t* sVC = (uint32_t*)(dsm + S2_VC);

    const int b = blockIdx.z, h = blockIdx.y, n0 = blockIdx.x * S2M;
    const int tid = threadIdx.x, lane = tid & 31, warp = tid >> 5;
    const int g = lane >> 2, t = lane & 3;
    const int wm = warp * 32;

    uint32_t sQu = smem_u32(sQ);
    uint32_t sAu = smem_u32(sA);
    uint32_t sVu = smem_u32(sV);
    uint32_t sVCu = smem_u32(sVC);

    // q tile: 256 rows x 4 chunks
#pragma unroll
    for (int r = 0; r < 4; r++) {
        int c = tid + r * 256;
        int row = c >> 2, sg = c & 3;
        int n = n0 + row;
        cp16(sQu + (row * SAP + sg * 8) * 2,
             g_qkv_bf + ((size_t)b * NN + (n < NN ? n : 0)) * C3 + h * HD + sg * 8,
             n < NN ? 16 : 0);
    }
    // agents
    if (tid < AG * 4) {
        int row = tid >> 2, sg = tid & 3;
        cp16(sAu + (row * SKV + sg * 8) * 2,
             g_agentbf + ((size_t)b * AG + row) * CC + h * HD + sg * 8, 16);
    }
    // agent_v (padded 64)
    {
        int row = tid >> 2, sg = tid & 3;
        cp16(sVu + (row * SKV + sg * 8) * 2,
             g_agentv_bf + ((size_t)(b * NH + h) * 64 + row) * HD + sg * 8, 16);
    }
    // v halo tile for dwconv: rows n0-57 .. n0+314
    {
        const __nv_bfloat16* vsrc = g_qkv_bf + (size_t)b * NN * C3 + 2 * CC + h * HD;
        for (int c = tid; c < VROWS * 4; c += 256) {
            int row = c >> 2, sg = c & 3;
            int n = n0 - 57 + row;
            int valid = (n >= 0 && n < NN);
            cp16(sVCu + (row * VSTR + sg * 4) * 4,
                 vsrc + (size_t)(valid ? n : 0) * C3 + sg * 8, valid ? 16 : 0);
        }
    }
    asm volatile("cp.async.commit_group;\n");
    asm volatile("cp.async.wait_group 0;\n");
    __syncthreads();

    const int rmA = (lane & 7) + ((lane >> 3) & 1) * 8;
    const int ckA = ((lane >> 4) << 3);
    const int krow = (lane & 7) + ((lane >> 4) & 1) * 8;
    const int koff = ((lane >> 3) & 1) * 8;
    const int rsel = (lane & 7) + ((lane >> 4) << 3);
    const int csel = ((lane >> 3) & 1) * 8;

    float sc[2][8][4];
#pragma unroll
    for (int mt = 0; mt < 2; mt++) {
        int r0 = n0 + wm + mt * 16 + g;
        int r1 = r0 + 8;
        const float* bq0 = g_ab1t + ((size_t)h * NN + (r0 < NN ? r0 : 0)) * 64;
        const float* bq1 = g_ab1t + ((size_t)h * NN + (r1 < NN ? r1 : 0)) * 64;
#pragma unroll
        for (int j = 0; j < 8; j++) {
            float2 v0 = *(const float2*)(bq0 + j * 8 + 2 * t);
            float2 v1 = *(const float2*)(bq1 + j * 8 + 2 * t);
            sc[mt][j][0] = v0.x; sc[mt][j][1] = v0.y;
            sc[mt][j][2] = v1.x; sc[mt][j][3] = v1.y;
        }
    }
#pragma unroll
    for (int kk = 0; kk < 32; kk += 16) {
        uint32_t a[2][4];
#pragma unroll
        for (int mt = 0; mt < 2; mt++)
            ldsm4(a[mt], sQu + ((wm + mt * 16 + rmA) * SAP + kk + ckA) * 2);
#pragma unroll
        for (int jp = 0; jp < 4; jp++) {
            uint32_t bf4[4];
            ldsm4(bf4, sAu + ((jp * 16 + krow) * SKV + kk + koff) * 2);
#pragma unroll
            for (int mt = 0; mt < 2; mt++) {
                mma_bf16(sc[mt][jp * 2],     a[mt], bf4[0], bf4[1]);
                mma_bf16(sc[mt][jp * 2 + 1], a[mt], bf4[2], bf4[3]);
            }
        }
    }
#pragma unroll
    for (int mt = 0; mt < 2; mt++)
#pragma unroll
        for (int j = 0; j < 8; j++) {
            int c0 = j * 8 + 2 * t;
            if (c0 >= AG)     { sc[mt][j][0] = -1e30f; sc[mt][j][2] = -1e30f; }
            if (c0 + 1 >= AG) { sc[mt][j][1] = -1e30f; sc[mt][j][3] = -1e30f; }
        }
#pragma unroll
    for (int mt = 0; mt < 2; mt++) {
        float mx0 = -1e30f, mx1 = -1e30f;
#pragma unroll
        for (int j = 0; j < 8; j++) {
            mx0 = fmaxf(mx0, fmaxf(sc[mt][j][0], sc[mt][j][1]));
            mx1 = fmaxf(mx1, fmaxf(sc[mt][j][2], sc[mt][j][3]));
        }
        mx0 = fmaxf(mx0, __shfl_xor_sync(0xffffffffu, mx0, 1));
        mx0 = fmaxf(mx0, __shfl_xor_sync(0xffffffffu, mx0, 2));
        mx1 = fmaxf(mx1, __shfl_xor_sync(0xffffffffu, mx1, 1));
        mx1 = fmaxf(mx1, __shfl_xor_sync(0xffffffffu, mx1, 2));
        float l0 = 0.f, l1 = 0.f;
#pragma unroll
        for (int j = 0; j < 8; j++) {
            sc[mt][j][0] = __expf(sc[mt][j][0] - mx0); l0 += sc[mt][j][0];
            sc[mt][j][1] = __expf(sc[mt][j][1] - mx0); l0 += sc[mt][j][1];
            sc[mt][j][2] = __expf(sc[mt][j][2] - mx1); l1 += sc[mt][j][2];
            sc[mt][j][3] = __expf(sc[mt][j][3] - mx1); l1 += sc[mt][j][3];
        }
        l0 += __shfl_xor_sync(0xffffffffu, l0, 1);
        l0 += __shfl_xor_sync(0xffffffffu, l0, 2);
        l1 += __shfl_xor_sync(0xffffffffu, l1, 1);
        l1 += __shfl_xor_sync(0xffffffffu, l1, 2);
        float i0 = 1.f / l0, i1 = 1.f / l1;
#pragma unroll
        for (int j = 0; j < 8; j++) {
            sc[mt][j][0] *= i0; sc[mt][j][1] *= i0;
            sc[mt][j][2] *= i1; sc[mt][j][3] *= i1;
        }
    }
    float oacc[2][4][4];
#pragma unroll
    for (int mt = 0; mt < 2; mt++)
#pragma unroll
        for (int j = 0; j < 4; j++)
#pragma unroll
            for (int q = 0; q < 4; q++) oacc[mt][j][q] = 0.f;
#pragma unroll
    for (int kt = 0; kt < 4; kt++) {
        uint32_t vb0[4], vb1[4];
        ldsm4t(vb0, sVu + ((kt * 16 + rsel) * SKV + csel) * 2);
        ldsm4t(vb1, sVu + ((kt * 16 + rsel) * SKV + 16 + csel) * 2);
#pragma unroll
        for (int mt = 0; mt < 2; mt++) {
            uint32_t pf[4];
            pf[0] = packbf(sc[mt][2 * kt][0], sc[mt][2 * kt][1]);
            pf[1] = packbf(sc[mt][2 * kt][2], sc[mt][2 * kt][3]);
            pf[2] = packbf(sc[mt][2 * kt + 1][0], sc[mt][2 * kt + 1][1]);
            pf[3] = packbf(sc[mt][2 * kt + 1][2], sc[mt][2 * kt + 1][3]);
            mma_bf16(oacc[mt][0], pf, vb0[0], vb0[2]);
            mma_bf16(oacc[mt][1], pf, vb0[1], vb0[3]);
            mma_bf16(oacc[mt][2], pf, vb1[0], vb1[2]);
            mma_bf16(oacc[mt][3], pf, vb1[1], vb1[3]);
        }
    }
#pragma unroll
    for (int nt = 0; nt < 4; nt++) {
        int c0l = nt * 8 + 2 * t;
        int c0  = h * HD + c0l;
        int cw  = nt * 4 + t;
        float bw0 = __ldg(&dwc_b[c0]), bw1 = __ldg(&dwc_b[c0 + 1]);
        float w0[9], w1[9];
#pragma unroll
        for (int k = 0; k < 9; k++) {
            w0[k] = __ldg(&dwc_w[c0 * 9 + k]);
            w1[k] = __ldg(&dwc_w[(c0 + 1) * 9 + k]);
        }
#pragma unroll
        for (int mt = 0; mt < 2; mt++)
#pragma unroll
            for (int rr = 0; rr < 2; rr++) {
                int n = n0 + wm + mt * 16 + g + rr * 8;
                if (n >= NN) continue;
                int y = n / WW, x = n % WW;
                float a0 = bw0, a1 = bw1;
#pragma unroll
                for (int ky = 0; ky < 3; ky++) {
                    int yy = y + ky - 1;
                    if (yy < 0 || yy >= HH) continue;
#pragma unroll
                    for (int kx = 0; kx < 3; kx++) {
                        int xx = x + kx - 1;
                        if (xx < 0 || xx >= WW) continue;
                        int tap = (yy * WW + xx) - n0 + 57;
                        uint32_t vw = sVC[tap * VSTR + cw];
                        float2 vf = __bfloat1622float2(*(__nv_bfloat162*)&vw);
                        a0 += vf.x * w0[ky * 3 + kx];
                        a1 += vf.y * w1[ky * 3 + kx];
                    }
                }
                float d0 = oacc[mt][nt][rr * 2] + a0;
                float d1 = oacc[mt][nt][rr * 2 + 1] + a1;
                *(__nv_bfloat162*)&g_omid_bf[((size_t)b * NN + n) * CC + c0] =
                    __floats2bfloat162_rn(d0, d1);
            }
    }
}

// ---------------- kernel 7: proj GEMM via bf16 mma + transposed epilogue --------
__global__ __launch_bounds__(256) void proj_bf16_kernel(const float* __restrict__ bias,
                                                        const float* __restrict__ x,
                                                        float* __restrict__ out) {
    union Sm {
        struct { __nv_bfloat16 As[2][128 * SAP]; __nv_bfloat16 Bs[2][32 * SB]; } p;
        float tile[128 * 33];
    };
    __shared__ Sm sm;
    const int b  = blockIdx.z;
    const int m0 = blockIdx.x * 128;
    const int n0 = blockIdx.y * 128;
    const int tid = threadIdx.x, lane = tid & 31, wid = tid >> 5;
    const int wm = (wid & 1) * 64, wn = (wid >> 1) * 32;
    const int g = lane >> 2, t = lane & 3;

    uint32_t sAu[2], sBu[2];
    sAu[0] = smem_u32(sm.p.As[0]); sAu[1] = smem_u32(sm.p.As[1]);
    sBu[0] = smem_u32(sm.p.Bs[0]); sBu[1] = smem_u32(sm.p.Bs[1]);

    float d[4][4][4];
#pragma unroll
    for (int i = 0; i < 4; i++)
#pragma unroll
        for (int j = 0; j < 4; j++)
#pragma unroll
            for (int q = 0; q < 4; q++) d[i][j][q] = 0.f;

    const __nv_bfloat16* ab = g_omid_bf + ((size_t)b * NN + m0) * CC;

    auto issue = [&](int k0, int buf) {
#pragma unroll
        for (int r = 0; r < 2; r++) {
            int ci = tid + r * 256;
            int rowA = ci >> 2, cA = ci & 3;
            cp16(sAu[buf] + (rowA * SAP + cA * 8) * 2,
                 ab + (size_t)rowA * CC + k0 + cA * 8, (m0 + rowA) < NN ? 16 : 0);
            int rowB = ci >> 4, cB = ci & 15;
            cp16(sBu[buf] + (rowB * SB + cB * 8) * 2,
                 g_projw_bf + (size_t)(k0 + rowB) * CC + n0 + cB * 8, 16);
        }
        asm volatile("cp.async.commit_group;\n");
    };

    issue(0, 0);
    const int rmA = (lane & 7) + ((lane >> 3) & 1) * 8;
    const int ckA = ((lane >> 4) << 3);
    const int rsel = (lane & 7) + ((lane >> 4) << 3);
    const int csel = ((lane >> 3) & 1) * 8;

    for (int s = 0; s < 12; s++) {
        if (s < 11) {
            issue((s + 1) * 32, (s + 1) & 1);
            asm volatile("cp.async.wait_group 1;\n");
        } else {
            asm volatile("cp.async.wait_group 0;\n");
        }
        __syncthreads();
        const uint32_t sa = sAu[s & 1], sb = sBu[s & 1];
#pragma unroll
        for (int kk = 0; kk < 32; kk += 16) {
            uint32_t a[4][4], bfr[2][4];
#pragma unroll
            for (int mt = 0; mt < 4; mt++)
                ldsm4(a[mt], sa + ((wm + mt * 16 + rmA) * SAP + kk + ckA) * 2);
            int rB = kk + rsel;
#pragma unroll
            for (int bt = 0; bt < 2; bt++)
                ldsm4t(bfr[bt], sb + (rB * SB + wn + bt * 16 + csel) * 2);
#pragma unroll
            for (int mt = 0; mt < 4; mt++)
#pragma unroll
                for (int j = 0; j < 4; j++)
                    mma_bf16(d[mt][j], a[mt], bfr[j >> 1][j & 1], bfr[j >> 1][2 + (j & 1)]);
        }
        __syncthreads();
    }

#pragma unroll
    for (int p = 0; p < 4; p++) {
        __syncthreads();
        if ((wid >> 1) == p) {
#pragma unroll
            for (int mt = 0; mt < 4; mt++)
#pragma unroll
                for (int j = 0; j < 4; j++) {
                    int row = wm + mt * 16 + g;
                    int colL = j * 8 + 2 * t;
                    sm.tile[row * 33 + colL]           = d[mt][j][0];
                    sm.tile[row * 33 + colL + 1]       = d[mt][j][1];
                    sm.tile[(row + 8) * 33 + colL]     = d[mt][j][2];
                    sm.tile[(row + 8) * 33 + colL + 1] = d[mt][j][3];
                }
        }
        __syncthreads();
        int colc = tid >> 3;
        int ch = n0 + p * 32 + colc;
        float bvv = __ldg(&bias[ch]);
        size_t obase = ((size_t)b * CC + ch) * NN + m0;
#pragma unroll
        for (int jj = 0; jj < 4; jj++) {
            int m = (tid & 7) * 4 + 32 * jj;
            if (m0 + m + 4 > NN) continue;
            float v0 = sm.tile[(m + 0) * 33 + colc];
            float v1 = sm.tile[(m + 1) * 33 + colc];
            float v2 = sm.tile[(m + 2) * 33 + colc];
            float v3 = sm.tile[(m + 3) * 33 + colc];
            float4 xv = *(const float4*)&x[obase + m];
            float4 o;
            o.x = xv.x / (1.f + __expf(-(v0 + bvv)));
            o.y = xv.y / (1.f + __expf(-(v1 + bvv)));
            o.z = xv.z / (1.f + __expf(-(v2 + bvv)));
            o.w = xv.w / (1.f + __expf(-(v3 + bvv)));
            *(float4*)&out[obase + m] = o;
        }
    }
}

// ---------------- launch -------------------------------------------------------
extern "C" void kernel_launch(void* const* d_in, const int* in_sizes, int n_in,
                              void* d_out, int out_size) {
    const float* x      = (const float*)d_in[0];
    const float* qkv_w  = (const float*)d_in[1];
    const float* qkv_b  = (const float*)d_in[2];
    const float* proj_w = (const float*)d_in[3];
    const float* proj_b = (const float*)d_in[4];
    const float* an     = (const float*)d_in[5];
    const float* na     = (const float*)d_in[6];
    const float* dwc_w  = (const float*)d_in[7];
    const float* dwc_b  = (const float*)d_in[8];
    float* out = (float*)d_out;

    cudaFuncSetAttribute(stage2_mma_kernel,
                         cudaFuncAttributeMaxDynamicSharedMemorySize, S2_TOTAL);

    __nv_bfloat16* xbf; cudaGetSymbolAddress((void**)&xbf, g_x_bf);
    __nv_bfloat16* qwbf; cudaGetSymbolAddress((void**)&qwbf, g_qkvw_bf);
    __nv_bfloat16* pwbf; cudaGetSymbolAddress((void**)&pwbf, g_projw_bf);

    {
        size_t nx = (size_t)BB * CC * NN;
        f2bf_kernel<<<(unsigned)((nx / 4 + 255) / 256), 256>>>(x, xbf, nx);
        size_t nw = (size_t)CC * C3;
        f2bf_kernel<<<(unsigned)((nw / 4 + 255) / 256), 256>>>(qkv_w, qwbf, nw);
        size_t np = (size_t)CC * CC;
        f2bf_kernel<<<(unsigned)((np / 4 + 255) / 256), 256>>>(proj_w, pwbf, np);
    }
    upsample_bias_kernel<<<(NH * AG * NN + 255) / 256, 256>>>(an, na);
    qkv_bf16_kernel<<<dim3((NN + 127) / 128, C3 / 128, BB), 256>>>(qkv_b);
    pool_kernel<<<(BB * AG * CC + 255) / 256, 256>>>();
    stage1_kernel<<<dim3(BB * NH, NSEG), 128>>>();
    stage1_reduce_kernel<<<BB * NH, 256>>>();
    stage2_mma_kernel<<<dim3((NN + S2M - 1) / S2M, NH, BB), 256, S2_TOTAL>>>(dwc_w, dwc_b);
    proj_bf16_kernel<<<dim3((NN + 127) / 128, CC / 128, BB), 256>>>(proj_b, x, out);
}

// round 14
// speedup vs baseline: 1.0301x; 1.0053x over previous
#include <cuda_runtime.h>
#include <cuda_bf16.h>
#include <cstdint>
#include <cstddef>

#define BB 32
#define CC 384
#define C3 1152
#define HH 56
#define WW 56
#define NN 3136
#define NH 12
#define HD 32
#define AG 49
#define NSEG 7
#define SCALE 0.17677669529663687f  // 32^-0.5

#define SA 136   // qkv A smem row stride (bf16)
#define SB 136   // B smem row stride (bf16)
#define SAP 40   // proj/stage2 A smem row stride (bf16)
#define SKV 40   // stage1/2 K/V smem row stride (bf16)

// stage2 BM=256 tile
#define S2M 256
#define VROWS 372   // 256 + 2*57 halo, padded
#define VSTR 20     // v tile row stride in 32-bit words
// dynamic smem offsets (bytes)
#define S2_Q 0
#define S2_A (S2_Q + S2M * SAP * 2)        // 20480
#define S2_V (S2_A + 64 * SKV * 2)         // 25600
#define S2_VC (S2_V + 64 * SKV * 2)        // 30720
#define S2_TOTAL (S2_VC + VROWS * VSTR * 4) // 60480

// ---------------- scratch (device globals; no allocation allowed) ----------------
__device__ __nv_bfloat16 g_qkv_bf[(size_t)BB * NN * C3];   // [b][n][3c] bf16
__device__ __nv_bfloat16 g_agentbf[(size_t)BB * AG * CC];  // agents * SCALE, bf16
__device__ float g_pb1[(size_t)NH * AG * NN];              // stage1 bias [h][a][n]
__device__ float g_ab1t[(size_t)NH * NN * 64];             // stage2 bias [h][n][64pad]
__device__ __nv_bfloat16 g_agentv_bf[(size_t)BB * NH * 64 * HD]; // [b][h][64pad][d]
__device__ __nv_bfloat16 g_x_bf[(size_t)BB * CC * NN];     // bf16 copy of x
__device__ __nv_bfloat16 g_qkvw_bf[(size_t)CC * C3];
__device__ __nv_bfloat16 g_projw_bf[(size_t)CC * CC];
__device__ __nv_bfloat16 g_omid_bf[(size_t)BB * NN * CC];  // attn out + dwconv
// stage-1 split-K partials
__device__ float g_s1m[(size_t)BB * NH * NSEG * AG];
__device__ float g_s1l[(size_t)BB * NH * NSEG * AG];
__device__ float g_s1acc[(size_t)BB * NH * NSEG * AG * HD];

// ---------------- asm helpers ---------------------------------------------------
__device__ __forceinline__ void cp16(uint32_t dst, const void* src, int sz) {
    asm volatile("cp.async.cg.shared.global [%0], [%1], 16, %2;\n"
                 :: "r"(dst), "l"(src), "r"(sz));
}
__device__ __forceinline__ void ldsm4t(uint32_t* r, uint32_t addr) {
    asm volatile("ldmatrix.sync.aligned.m8n8.x4.trans.shared.b16 {%0,%1,%2,%3}, [%4];\n"
                 : "=r"(r[0]), "=r"(r[1]), "=r"(r[2]), "=r"(r[3]) : "r"(addr));
}
__device__ __forceinline__ void ldsm4(uint32_t* r, uint32_t addr) {
    asm volatile("ldmatrix.sync.aligned.m8n8.x4.shared.b16 {%0,%1,%2,%3}, [%4];\n"
                 : "=r"(r[0]), "=r"(r[1]), "=r"(r[2]), "=r"(r[3]) : "r"(addr));
}
__device__ __forceinline__ void mma_bf16(float* d, const uint32_t* a,
                                         uint32_t b0, uint32_t b1) {
    asm volatile(
        "mma.sync.aligned.m16n8k16.row.col.f32.bf16.bf16.f32 "
        "{%0,%1,%2,%3}, {%4,%5,%6,%7}, {%8,%9}, {%0,%1,%2,%3};\n"
        : "+f"(d[0]), "+f"(d[1]), "+f"(d[2]), "+f"(d[3])
        : "r"(a[0]), "r"(a[1]), "r"(a[2]), "r"(a[3]), "r"(b0), "r"(b1));
}
__device__ __forceinline__ uint32_t packbf(float x, float y) {
    __nv_bfloat162 h = __floats2bfloat162_rn(x, y);
    return *(uint32_t*)&h;
}
__device__ __forceinline__ uint32_t smem_u32(const void* p) {
    return (uint32_t)__cvta_generic_to_shared(p);
}

// ---------------- kernel 0: fp32 -> bf16 conversion -----------------------------
__global__ void f2bf_kernel(const float* __restrict__ s, __nv_bfloat16* __restrict__ d,
                            size_t n) {
    size_t i = ((size_t)blockIdx.x * 256 + threadIdx.x) * 4;
    if (i >= n) return;
    float4 v = *(const float4*)(s + i);
    *(__nv_bfloat162*)(d + i)     = __floats2bfloat162_rn(v.x, v.y);
    *(__nv_bfloat162*)(d + i + 2) = __floats2bfloat162_rn(v.z, v.w);
}

// ---------------- kernel 1: bilinear upsample of position biases ----------------
__global__ void upsample_bias_kernel(const float* __restrict__ an,
                                     const float* __restrict__ na) {
    int idx = blockIdx.x * 256 + threadIdx.x;
    const int total = NH * AG * NN;
    if (idx >= total) return;
    int n  = idx % NN;
    int ha = idx / NN;
    int h  = ha / AG, a = ha % AG;
    int x = n % WW, y = n / WW;

    float fy = (y + 0.5f) * 0.125f - 0.5f;
    float fx = (x + 0.5f) * 0.125f - 0.5f;
    int y0 = (int)floorf(fy), x0 = (int)floorf(fx);
    float wy = fy - (float)y0, wx = fx - (float)x0;
    int iy0 = min(max(y0, 0), 6), iy1 = min(max(y0 + 1, 0), 6);
    int ix0 = min(max(x0, 0), 6), ix1 = min(max(x0 + 1, 0), 6);
    float w00 = (1.f - wy) * (1.f - wx), w01 = (1.f - wy) * wx;
    float w10 = wy * (1.f - wx),         w11 = wy * wx;

    const float* a_base = an + (size_t)ha * 49;
    const float* n_base = na + (size_t)ha * 49;
    g_pb1[idx] = w00 * a_base[iy0 * 7 + ix0] + w01 * a_base[iy0 * 7 + ix1]
               + w10 * a_base[iy1 * 7 + ix0] + w11 * a_base[iy1 * 7 + ix1];
    float nb = w00 * n_base[iy0 * 7 + ix0] + w01 * n_base[iy0 * 7 + ix1]
             + w10 * n_base[iy1 * 7 + ix0] + w11 * n_base[iy1 * 7 + ix1];
    g_ab1t[((size_t)h * NN + n) * 64 + a] = nb;
}

// ---------------- kernel 2: qkv GEMM via bf16 mma, 2-stage (proven) -------------
__global__ __launch_bounds__(256) void qkv_bf16_kernel(const float* __restrict__ bias) {
    __shared__ __nv_bfloat16 As[2][32 * SA];
    __shared__ __nv_bfloat16 Bs[2][32 * SB];
    const int b  = blockIdx.z;
    const int m0 = blockIdx.x * 128;
    const int n0 = blockIdx.y * 128;
    const int tid = threadIdx.x, lane = tid & 31, wid = tid >> 5;
    const int wm = (wid & 1) * 64, wn = (wid >> 1) * 32;
    const int g = lane >> 2, t = lane & 3;
    const __nv_bfloat16* xb = g_x_bf + (size_t)b * CC * NN;

    uint32_t sAu[2], sBu[2];
    sAu[0] = smem_u32(As[0]); sAu[1] = smem_u32(As[1]);
    sBu[0] = smem_u32(Bs[0]); sBu[1] = smem_u32(Bs[1]);

    float d[4][4][4];
#pragma unroll
    for (int i = 0; i < 4; i++)
#pragma unroll
        for (int j = 0; j < 4; j++)
#pragma unroll
            for (int q = 0; q < 4; q++) d[i][j][q] = 0.f;

    auto issue = [&](int k0, int buf) {
#pragma unroll
        for (int r = 0; r < 2; r++) {
            int ci = tid + r * 256;
            int row = ci >> 4, c = ci & 15;
            int mcol = m0 + c * 8;
            cp16(sAu[buf] + (row * SA + c * 8) * 2,
                 xb + (size_t)(k0 + row) * NN + mcol, mcol < NN ? 16 : 0);
            cp16(sBu[buf] + (row * SB + c * 8) * 2,
                 g_qkvw_bf + (size_t)(k0 + row) * C3 + n0 + c * 8, 16);
        }
        asm volatile("cp.async.commit_group;\n");
    };

    issue(0, 0);
    const int rsel = (lane & 7) + ((lane >> 4) << 3);
    const int csel = ((lane >> 3) & 1) * 8;

    for (int s = 0; s < 12; s++) {
        if (s < 11) {
            issue((s + 1) * 32, (s + 1) & 1);
            asm volatile("cp.async.wait_group 1;\n");
        } else {
            asm volatile("cp.async.wait_group 0;\n");
        }
        __syncthreads();
        const uint32_t sa = sAu[s & 1], sb = sBu[s & 1];
#pragma unroll
        for (int kk = 0; kk < 32; kk += 16) {
            uint32_t a[4][4], bfr[2][4];
            int rA = kk + rsel;
#pragma unroll
            for (int mt = 0; mt < 4; mt++)
                ldsm4t(a[mt], sa + (rA * SA + wm + mt * 16 + csel) * 2);
#pragma unroll
            for (int bt = 0; bt < 2; bt++)
                ldsm4t(bfr[bt], sb + (rA * SB + wn + bt * 16 + csel) * 2);
#pragma unroll
            for (int mt = 0; mt < 4; mt++)
#pragma unroll
                for (int j = 0; j < 4; j++)
                    mma_bf16(d[mt][j], a[mt], bfr[j >> 1][j & 1], bfr[j >> 1][2 + (j & 1)]);
        }
        __syncthreads();
    }

#pragma unroll
    for (int mt = 0; mt < 4; mt++)
#pragma unroll
        for (int j = 0; j < 4; j++) {
            int row = m0 + wm + mt * 16 + g;
            int col = n0 + wn + j * 8 + 2 * t;
            float bv0 = __ldg(&bias[col]), bv1 = __ldg(&bias[col + 1]);
            if (row < NN)
                *(__nv_bfloat162*)&g_qkv_bf[((size_t)b * NN + row) * C3 + col] =
                    __floats2bfloat162_rn(d[mt][j][0] + bv0, d[mt][j][1] + bv1);
            if (row + 8 < NN)
                *(__nv_bfloat162*)&g_qkv_bf[((size_t)b * NN + row + 8) * C3 + col] =
                    __floats2bfloat162_rn(d[mt][j][2] + bv0, d[mt][j][3] + bv1);
        }
}

// ---------------- kernel 3: agent pooling -> scaled bf16 agents -----------------
__global__ void pool_kernel() {
    int idx = blockIdx.x * 256 + threadIdx.x;
    const int total = BB * AG * CC;
    if (idx >= total) return;
    int c = idx % CC;
    int a = (idx / CC) % AG;
    int b = idx / (CC * AG);
    int py = a / 7, px = a % 7;
    const __nv_bfloat16* q = g_qkv_bf + (size_t)b * NN * C3 + c;
    float s = 0.f;
#pragma unroll
    for (int dy = 0; dy < 8; dy++) {
        int row = (py * 8 + dy) * WW + px * 8;
#pragma unroll
        for (int dx = 0; dx < 8; dx++)
            s += __bfloat162float(q[(size_t)(row + dx) * C3]);
    }
    g_agentbf[idx] = __float2bfloat16_rn(s * 0.015625f * SCALE);
}

// ---------------- kernel 4: stage-1 agent attention via bf16 mma (split-K) ------
__global__ __launch_bounds__(128) void stage1_kernel() {
    __shared__ __nv_bfloat16 sK[2][64 * SKV];
    __shared__ __nv_bfloat16 sV[2][64 * SKV];

    const int tid = threadIdx.x, lane = tid & 31, warp = tid >> 5;
    const int bh = blockIdx.x, seg = blockIdx.y;
    const int b = bh / NH, h = bh % NH;
    const int g = lane >> 2, t = lane & 3;
    const int a_row0 = warp * 16 + g, a_row1 = a_row0 + 8;

    uint32_t skU[2], svU[2];
    skU[0] = smem_u32(sK[0]); skU[1] = smem_u32(sK[1]);
    svU[0] = smem_u32(sV[0]); svU[1] = smem_u32(sV[1]);

    uint32_t afrag[2][4];
    const __nv_bfloat16* agb = g_agentbf + (size_t)b * AG * CC + h * HD;
#pragma unroll
    for (int kt = 0; kt < 2; kt++) {
        int kb = kt * 16 + 2 * t;
        afrag[kt][0] = (a_row0 < AG) ? *(const uint32_t*)(agb + (size_t)a_row0 * CC + kb) : 0u;
        afrag[kt][1] = (a_row1 < AG) ? *(const uint32_t*)(agb + (size_t)a_row1 * CC + kb) : 0u;
        afrag[kt][2] = (a_row0 < AG) ? *(const uint32_t*)(agb + (size_t)a_row0 * CC + kb + 8) : 0u;
        afrag[kt][3] = (a_row1 < AG) ? *(const uint32_t*)(agb + (size_t)a_row1 * CC + kb + 8) : 0u;
    }

    float oacc[4][4];
#pragma unroll
    for (int i = 0; i < 4; i++)
#pragma unroll
        for (int j = 0; j < 4; j++) oacc[i][j] = 0.f;
    float rm0 = -1e30f, rm1 = -1e30f, rl0 = 0.f, rl1 = 0.f;

    const int krow = (lane & 7) + ((lane >> 4) & 1) * 8;
    const int koff = ((lane >> 3) & 1) * 8;
    const int rsel = (lane & 7) + ((lane >> 4) << 3);
    const int csel = ((lane >> 3) & 1) * 8;

    auto issue = [&](int chunk, int buf) {
        int n0 = chunk * 64;
#pragma unroll
        for (int r = 0; r < 2; r++) {
            int c = tid + r * 128;
            int row = c >> 2, sg = c & 3;
            const __nv_bfloat16* gk = g_qkv_bf
                + ((size_t)b * NN + n0 + row) * C3 + CC + h * HD + sg * 8;
            cp16(skU[buf] + (row * SKV + sg * 8) * 2, gk, 16);
            cp16(svU[buf] + (row * SKV + sg * 8) * 2, gk + CC, 16);
        }
        asm volatile("cp.async.commit_group;\n");
    };

    const float* bp0 = g_pb1 + ((size_t)h * AG + (a_row0 < AG ? a_row0 : 0)) * NN;
    const float* bp1 = g_pb1 + ((size_t)h * AG + (a_row1 < AG ? a_row1 : 0)) * NN;

    issue(seg * 7, 0);
    for (int ci = 0; ci < 7; ci++) {
        if (ci < 6) {
            issue(seg * 7 + ci + 1, (ci + 1) & 1);
            asm volatile("cp.async.wait_group 1;\n");
        } else {
            asm volatile("cp.async.wait_group 0;\n");
        }
        __syncthreads();
        const uint32_t sk = skU[ci & 1], sv = svU[ci & 1];
        const int n0 = (seg * 7 + ci) * 64;

        float sc[8][4];
#pragma unroll
        for (int j = 0; j < 8; j++) {
            float2 b0 = (a_row0 < AG) ? *(const float2*)(bp0 + n0 + j * 8 + 2 * t)
                                      : make_float2(0.f, 0.f);
            float2 b1 = (a_row1 < AG) ? *(const float2*)(bp1 + n0 + j * 8 + 2 * t)
                                      : make_float2(0.f, 0.f);
            sc[j][0] = b0.x; sc[j][1] = b0.y; sc[j][2] = b1.x; sc[j][3] = b1.y;
        }
#pragma unroll
        for (int jp = 0; jp < 4; jp++) {
            uint32_t kf0[4], kf1[4];
            ldsm4(kf0, sk + ((jp * 16 + krow) * SKV + koff) * 2);
            ldsm4(kf1, sk + ((jp * 16 + krow) * SKV + 16 + koff) * 2);
            mma_bf16(sc[jp * 2],     afrag[0], kf0[0], kf0[1]);
            mma_bf16(sc[jp * 2],     afrag[1], kf1[0], kf1[1]);
            mma_bf16(sc[jp * 2 + 1], afrag[0], kf0[2], kf0[3]);
            mma_bf16(sc[jp * 2 + 1], afrag[1], kf1[2], kf1[3]);
        }
        float mx0 = sc[0][0], mx1 = sc[0][2];
#pragma unroll
        for (int j = 0; j < 8; j++) {
            mx0 = fmaxf(mx0, fmaxf(sc[j][0], sc[j][1]));
            mx1 = fmaxf(mx1, fmaxf(sc[j][2], sc[j][3]));
        }
        mx0 = fmaxf(mx0, __shfl_xor_sync(0xffffffffu, mx0, 1));
        mx0 = fmaxf(mx0, __shfl_xor_sync(0xffffffffu, mx0, 2));
        mx1 = fmaxf(mx1, __shfl_xor_sync(0xffffffffu, mx1, 1));
        mx1 = fmaxf(mx1, __shfl_xor_sync(0xffffffffu, mx1, 2));
        float nm0 = fmaxf(rm0, mx0), nm1 = fmaxf(rm1, mx1);
        float corr0 = __expf(rm0 - nm0), corr1 = __expf(rm1 - nm1);
        float ls0 = 0.f, ls1 = 0.f;
#pragma unroll
        for (int j = 0; j < 8; j++) {
            sc[j][0] = __expf(sc[j][0] - nm0); ls0 += sc[j][0];
            sc[j][1] = __expf(sc[j][1] - nm0); ls0 += sc[j][1];
            sc[j][2] = __expf(sc[j][2] - nm1); ls1 += sc[j][2];
            sc[j][3] = __expf(sc[j][3] - nm1); ls1 += sc[j][3];
        }
        ls0 += __shfl_xor_sync(0xffffffffu, ls0, 1);
        ls0 += __shfl_xor_sync(0xffffffffu, ls0, 2);
        ls1 += __shfl_xor_sync(0xffffffffu, ls1, 1);
        ls1 += __shfl_xor_sync(0xffffffffu, ls1, 2);
        rl0 = rl0 * corr0 + ls0;
        rl1 = rl1 * corr1 + ls1;
        rm0 = nm0; rm1 = nm1;
#pragma unroll
        for (int nt = 0; nt < 4; nt++) {
            oacc[nt][0] *= corr0; oacc[nt][1] *= corr0;
            oacc[nt][2] *= corr1; oacc[nt][3] *= corr1;
        }
#pragma unroll
        for (int kt = 0; kt < 4; kt++) {
            uint32_t pf[4];
            pf[0] = packbf(sc[2 * kt][0], sc[2 * kt][1]);
            pf[1] = packbf(sc[2 * kt][2], sc[2 * kt][3]);
            pf[2] = packbf(sc[2 * kt + 1][0], sc[2 * kt + 1][1]);
            pf[3] = packbf(sc[2 * kt + 1][2], sc[2 * kt + 1][3]);
            uint32_t vb0[4], vb1[4];
            ldsm4t(vb0, sv + ((kt * 16 + rsel) * SKV + csel) * 2);
            ldsm4t(vb1, sv + ((kt * 16 + rsel) * SKV + 16 + csel) * 2);
            mma_bf16(oacc[0], pf, vb0[0], vb0[2]);
            mma_bf16(oacc[1], pf, vb0[1], vb0[3]);
            mma_bf16(oacc[2], pf, vb1[0], vb1[2]);
            mma_bf16(oacc[3], pf, vb1[1], vb1[3]);
        }
        __syncthreads();
    }

    const size_t base = ((size_t)bh * NSEG + seg) * AG;
#pragma unroll
    for (int nt = 0; nt < 4; nt++) {
        if (a_row0 < AG)
            *(float2*)&g_s1acc[(base + a_row0) * HD + nt * 8 + 2 * t] =
                make_float2(oacc[nt][0], oacc[nt][1]);
        if (a_row1 < AG)
            *(float2*)&g_s1acc[(base + a_row1) * HD + nt * 8 + 2 * t] =
                make_float2(oacc[nt][2], oacc[nt][3]);
    }
    if (t == 0) {
        if (a_row0 < AG) { g_s1m[base + a_row0] = rm0; g_s1l[base + a_row0] = rl0; }
        if (a_row1 < AG) { g_s1m[base + a_row1] = rm1; g_s1l[base + a_row1] = rl1; }
    }
}

// ---------------- kernel 4b: combine split-K partials -> bf16 agent_v -----------
__global__ __launch_bounds__(256) void stage1_reduce_kernel() {
    __shared__ float sW[NSEG][AG];
    __shared__ float sLs[AG];
    const int bh = blockIdx.x;
    const int tid = threadIdx.x;
    const size_t base = (size_t)bh * NSEG * AG;
    if (tid < AG) {
        float M = -1e30f;
#pragma unroll
        for (int s = 0; s < NSEG; s++)
            M = fmaxf(M, g_s1m[base + s * AG + tid]);
        float ls = 0.f;
#pragma unroll
        for (int s = 0; s < NSEG; s++) {
            float wv = __expf(g_s1m[base + s * AG + tid] - M);
            sW[s][tid] = wv;
            ls += wv * g_s1l[base + s * AG + tid];
        }
        sLs[tid] = ls;
    }
    __syncthreads();
    for (int i = tid; i < 64 * HD; i += 256) {
        int a = i >> 5, dd = i & 31;
        float r = 0.f;
        if (a < AG) {
            float acc = 0.f;
#pragma unroll
            for (int s = 0; s < NSEG; s++)
                acc += sW[s][a] * g_s1acc[(base + s * AG + a) * HD + dd];
            r = acc / sLs[a];
        }
        g_agentv_bf[(size_t)bh * 64 * HD + i] = __float2bfloat16_rn(r);
    }
}

// ---------------- kernel 5: stage-2 BM=256, split commit groups -----------------
__global__ __launch_bounds__(256) void stage2_mma_kernel(const float* __restrict__ dwc_w,
                                                         const float* __restrict__ dwc_b) {
    extern __shared__ char dsm[];
    __nv_bfloat16* sQ = (__nv_bfloat16*)(dsm + S2_Q);
    __nv_bfloat16* sA = (__nv_bfloat16*)(dsm + S2_A);
    __nv_bfloat16* sV = (__nv_bfloat16*)(dsm + S2_V);
    uint32_t* sVC = (uint32_t*)(dsm + S2_VC);

    const int b = blockIdx.z, h = blockIdx.y, n0 = blockIdx.x * S2M;
    const int tid = threadIdx.x, lane = tid & 31, warp = tid >> 5;
    const int g = lane >> 2, t = lane & 3;
    const int wm = warp * 32;

    uint32_t sQu = smem_u32(sQ);
    uint32_t sAu = smem_u32(sA);
    uint32_t sVu = smem_u32(sV);
    uint32_t sVCu = smem_u32(sVC);

    // group A: q tile, agents, agent_v (needed for attention compute)
#pragma unroll
    for (int r = 0; r < 4; r++) {
        int c = tid + r * 256;
        int row = c >> 2, sg = c & 3;
        int n = n0 + row;
        cp16(sQu + (row * SAP + sg * 8) * 2,
             g_qkv_bf + ((size_t)b * NN + (n < NN ? n : 0)) * C3 + h * HD + sg * 8,
             n < NN ? 16 : 0);
    }
    if (tid < AG * 4) {
        int row = tid >> 2, sg = tid & 3;
        cp16(sAu + (row * SKV + sg * 8) * 2,
             g_agentbf + ((size_t)b * AG + row) * CC + h * HD + sg * 8, 16);
    }
    {
        int row = tid >> 2, sg = tid & 3;
        cp16(sVu + (row * SKV + sg * 8) * 2,
             g_agentv_bf + ((size_t)(b * NH + h) * 64 + row) * HD + sg * 8, 16);
    }
    asm volatile("cp.async.commit_group;\n");
    // group B: v halo tile (only needed in the dwconv epilogue)
    {
        const __nv_bfloat16* vsrc = g_qkv_bf + (size_t)b * NN * C3 + 2 * CC + h * HD;
        for (int c = tid; c < VROWS * 4; c += 256) {
            int row = c >> 2, sg = c & 3;
            int n = n0 - 57 + row;
            int valid = (n >= 0 && n < NN);
            cp16(sVCu + (row * VSTR + sg * 4) * 4,
                 vsrc + (size_t)(valid ? n : 0) * C3 + sg * 8, valid ? 16 : 0);
        }
    }
    asm volatile("cp.async.commit_group;\n");
    // wait for group A only; group B stays in flight behind the attention math
    asm volatile("cp.async.wait_group 1;\n");
    __syncthreads();

    const int rmA = (lane & 7) + ((lane >> 3) & 1) * 8;
    const int ckA = ((lane >> 4) << 3);
    const int krow = (lane & 7) + ((lane >> 4) & 1) * 8;
    const int koff = ((lane >> 3) & 1) * 8;
    const int rsel = (lane & 7) + ((lane >> 4) << 3);
    const int csel = ((lane >> 3) & 1) * 8;

    float sc[2][8][4];
#pragma unroll
    for (int mt = 0; mt < 2; mt++) {
        int r0 = n0 + wm + mt * 16 + g;
        int r1 = r0 + 8;
        const float* bq0 = g_ab1t + ((size_t)h * NN + (r0 < NN ? r0 : 0)) * 64;
        const float* bq1 = g_ab1t + ((size_t)h * NN + (r1 < NN ? r1 : 0)) * 64;
#pragma unroll
        for (int j = 0; j < 8; j++) {
            float2 v0 = *(const float2*)(bq0 + j * 8 + 2 * t);
            float2 v1 = *(const float2*)(bq1 + j * 8 + 2 * t);
            sc[mt][j][0] = v0.x; sc[mt][j][1] = v0.y;
            sc[mt][j][2] = v1.x; sc[mt][j][3] = v1.y;
        }
    }
#pragma unroll
    for (int kk = 0; kk < 32; kk += 16) {
        uint32_t a[2][4];
#pragma unroll
        for (int mt = 0; mt < 2; mt++)
            ldsm4(a[mt], sQu + ((wm + mt * 16 + rmA) * SAP + kk + ckA) * 2);
#pragma unroll
        for (int jp = 0; jp < 4; jp++) {
            uint32_t bf4[4];
            ldsm4(bf4, sAu + ((jp * 16 + krow) * SKV + kk + koff) * 2);
#pragma unroll
            for (int mt = 0; mt < 2; mt++) {
                mma_bf16(sc[mt][jp * 2],     a[mt], bf4[0], bf4[1]);
                mma_bf16(sc[mt][jp * 2 + 1], a[mt], bf4[2], bf4[3]);
            }
        }
    }
#pragma unroll
    for (int mt = 0; mt < 2; mt++)
#pragma unroll
        for (int j = 0; j < 8; j++) {
            int c0 = j * 8 + 2 * t;
            if (c0 >= AG)     { sc[mt][j][0] = -1e30f; sc[mt][j][2] = -1e30f; }
            if (c0 + 1 >= AG) { sc[mt][j][1] = -1e30f; sc[mt][j][3] = -1e30f; }
        }
#pragma unroll
    for (int mt = 0; mt < 2; mt++) {
        float mx0 = -1e30f, mx1 = -1e30f;
#pragma unroll
        for (int j = 0; j < 8; j++) {
            mx0 = fmaxf(mx0, fmaxf(sc[mt][j][0], sc[mt][j][1]));
            mx1 = fmaxf(mx1, fmaxf(sc[mt][j][2], sc[mt][j][3]));
        }
        mx0 = fmaxf(mx0, __shfl_xor_sync(0xffffffffu, mx0, 1));
        mx0 = fmaxf(mx0, __shfl_xor_sync(0xffffffffu, mx0, 2));
        mx1 = fmaxf(mx1, __shfl_xor_sync(0xffffffffu, mx1, 1));
        mx1 = fmaxf(mx1, __shfl_xor_sync(0xffffffffu, mx1, 2));
        float l0 = 0.f, l1 = 0.f;
#pragma unroll
        for (int j = 0; j < 8; j++) {
            sc[mt][j][0] = __expf(sc[mt][j][0] - mx0); l0 += sc[mt][j][0];
            sc[mt][j][1] = __expf(sc[mt][j][1] - mx0); l0 += sc[mt][j][1];
            sc[mt][j][2] = __expf(sc[mt][j][2] - mx1); l1 += sc[mt][j][2];
            sc[mt][j][3] = __expf(sc[mt][j][3] - mx1); l1 += sc[mt][j][3];
        }
        l0 += __shfl_xor_sync(0xffffffffu, l0, 1);
        l0 += __shfl_xor_sync(0xffffffffu, l0, 2);
        l1 += __shfl_xor_sync(0xffffffffu, l1, 1);
        l1 += __shfl_xor_sync(0xffffffffu, l1, 2);
        float i0 = 1.f / l0, i1 = 1.f / l1;
#pragma unroll
        for (int j = 0; j < 8; j++) {
            sc[mt][j][0] *= i0; sc[mt][j][1] *= i0;
            sc[mt][j][2] *= i1; sc[mt][j][3] *= i1;
        }
    }
    float oacc[2][4][4];
#pragma unroll
    for (int mt = 0; mt < 2; mt++)
#pragma unroll
        for (int j = 0; j < 4; j++)
#pragma unroll
            for (int q = 0; q < 4; q++) oacc[mt][j][q] = 0.f;
#pragma unroll
    for (int kt = 0; kt < 4; kt++) {
        uint32_t vb0[4], vb1[4];
        ldsm4t(vb0, sVu + ((kt * 16 + rsel) * SKV + csel) * 2);
        ldsm4t(vb1, sVu + ((kt * 16 + rsel) * SKV + 16 + csel) * 2);
#pragma unroll
        for (int mt = 0; mt < 2; mt++) {
            uint32_t pf[4];
            pf[0] = packbf(sc[mt][2 * kt][0], sc[mt][2 * kt][1]);
            pf[1] = packbf(sc[mt][2 * kt][2], sc[mt][2 * kt][3]);
            pf[2] = packbf(sc[mt][2 * kt + 1][0], sc[mt][2 * kt + 1][1]);
            pf[3] = packbf(sc[mt][2 * kt + 1][2], sc[mt][2 * kt + 1][3]);
            mma_bf16(oacc[mt][0], pf, vb0[0], vb0[2]);
            mma_bf16(oacc[mt][1], pf, vb0[1], vb0[3]);
            mma_bf16(oacc[mt][2], pf, vb1[0], vb1[2]);
            mma_bf16(oacc[mt][3], pf, vb1[1], vb1[3]);
        }
    }
    // now require the v halo tile (group B) before the dwconv epilogue
    asm volatile("cp.async.wait_group 0;\n");
    __syncthreads();
#pragma unroll
    for (int nt = 0; nt < 4; nt++) {
        int c0l = nt * 8 + 2 * t;
        int c0  = h * HD + c0l;
        int cw  = nt * 4 + t;
        float bw0 = __ldg(&dwc_b[c0]), bw1 = __ldg(&dwc_b[c0 + 1]);
        float w0[9], w1[9];
#pragma unroll
        for (int k = 0; k < 9; k++) {
            w0[k] = __ldg(&dwc_w[c0 * 9 + k]);
            w1[k] = __ldg(&dwc_w[(c0 + 1) * 9 + k]);
        }
#pragma unroll
        for (int mt = 0; mt < 2; mt++)
#pragma unroll
            for (int rr = 0; rr < 2; rr++) {
                int n = n0 + wm + mt * 16 + g + rr * 8;
                if (n >= NN) continue;
                int y = n / WW, x = n % WW;
                float a0 = bw0, a1 = bw1;
#pragma unroll
                for (int ky = 0; ky < 3; ky++) {
                    int yy = y + ky - 1;
                    if (yy < 0 || yy >= HH) continue;
#pragma unroll
                    for (int kx = 0; kx < 3; kx++) {
                        int xx = x + kx - 1;
                        if (xx < 0 || xx >= WW) continue;
                        int tap = (yy * WW + xx) - n0 + 57;
                        uint32_t vw = sVC[tap * VSTR + cw];
                        float2 vf = __bfloat1622float2(*(__nv_bfloat162*)&vw);
                        a0 += vf.x * w0[ky * 3 + kx];
                        a1 += vf.y * w1[ky * 3 + kx];
                    }
                }
                float d0 = oacc[mt][nt][rr * 2] + a0;
                float d1 = oacc[mt][nt][rr * 2 + 1] + a1;
                *(__nv_bfloat162*)&g_omid_bf[((size_t)b * NN + n) * CC + c0] =
                    __floats2bfloat162_rn(d0, d1);
            }
    }
}

// ---------------- kernel 7: proj GEMM via bf16 mma + transposed epilogue --------
__global__ __launch_bounds__(256) void proj_bf16_kernel(const float* __restrict__ bias,
                                                        const float* __restrict__ x,
                                                        float* __restrict__ out) {
    union Sm {
        struct { __nv_bfloat16 As[2][128 * SAP]; __nv_bfloat16 Bs[2][32 * SB]; } p;
        float tile[128 * 33];
    };
    __shared__ Sm sm;
    const int b  = blockIdx.z;
    const int m0 = blockIdx.x * 128;
    const int n0 = blockIdx.y * 128;
    const int tid = threadIdx.x, lane = tid & 31, wid = tid >> 5;
    const int wm = (wid & 1) * 64, wn = (wid >> 1) * 32;
    const int g = lane >> 2, t = lane & 3;

    uint32_t sAu[2], sBu[2];
    sAu[0] = smem_u32(sm.p.As[0]); sAu[1] = smem_u32(sm.p.As[1]);
    sBu[0] = smem_u32(sm.p.Bs[0]); sBu[1] = smem_u32(sm.p.Bs[1]);

    float d[4][4][4];
#pragma unroll
    for (int i = 0; i < 4; i++)
#pragma unroll
        for (int j = 0; j < 4; j++)
#pragma unroll
            for (int q = 0; q < 4; q++) d[i][j][q] = 0.f;

    const __nv_bfloat16* ab = g_omid_bf + ((size_t)b * NN + m0) * CC;

    auto issue = [&](int k0, int buf) {
#pragma unroll
        for (int r = 0; r < 2; r++) {
            int ci = tid + r * 256;
            int rowA = ci >> 2, cA = ci & 3;
            cp16(sAu[buf] + (rowA * SAP + cA * 8) * 2,
                 ab + (size_t)rowA * CC + k0 + cA * 8, (m0 + rowA) < NN ? 16 : 0);
            int rowB = ci >> 4, cB = ci & 15;
            cp16(sBu[buf] + (rowB * SB + cB * 8) * 2,
                 g_projw_bf + (size_t)(k0 + rowB) * CC + n0 + cB * 8, 16);
        }
        asm volatile("cp.async.commit_group;\n");
    };

    issue(0, 0);
    const int rmA = (lane & 7) + ((lane >> 3) & 1) * 8;
    const int ckA = ((lane >> 4) << 3);
    const int rsel = (lane & 7) + ((lane >> 4) << 3);
    const int csel = ((lane >> 3) & 1) * 8;

    for (int s = 0; s < 12; s++) {
        if (s < 11) {
            issue((s + 1) * 32, (s + 1) & 1);
            asm volatile("cp.async.wait_group 1;\n");
        } else {
            asm volatile("cp.async.wait_group 0;\n");
        }
        __syncthreads();
        const uint32_t sa = sAu[s & 1], sb = sBu[s & 1];
#pragma unroll
        for (int kk = 0; kk < 32; kk += 16) {
            uint32_t a[4][4], bfr[2][4];
#pragma unroll
            for (int mt = 0; mt < 4; mt++)
                ldsm4(a[mt], sa + ((wm + mt * 16 + rmA) * SAP + kk + ckA) * 2);
            int rB = kk + rsel;
#pragma unroll
            for (int bt = 0; bt < 2; bt++)
                ldsm4t(bfr[bt], sb + (rB * SB + wn + bt * 16 + csel) * 2);
#pragma unroll
            for (int mt = 0; mt < 4; mt++)
#pragma unroll
                for (int j = 0; j < 4; j++)
                    mma_bf16(d[mt][j], a[mt], bfr[j >> 1][j & 1], bfr[j >> 1][2 + (j & 1)]);
        }
        __syncthreads();
    }

#pragma unroll
    for (int p = 0; p < 4; p++) {
        __syncthreads();
        if ((wid >> 1) == p) {
#pragma unroll
            for (int mt = 0; mt < 4; mt++)
#pragma unroll
                for (int j = 0; j < 4; j++) {
                    int row = wm + mt * 16 + g;
                    int colL = j * 8 + 2 * t;
                    sm.tile[row * 33 + colL]           = d[mt][j][0];
                    sm.tile[row * 33 + colL + 1]       = d[mt][j][1];
                    sm.tile[(row + 8) * 33 + colL]     = d[mt][j][2];
                    sm.tile[(row + 8) * 33 + colL + 1] = d[mt][j][3];
                }
        }
        __syncthreads();
        int colc = tid >> 3;
        int ch = n0 + p * 32 + colc;
        float bvv = __ldg(&bias[ch]);
        size_t obase = ((size_t)b * CC + ch) * NN + m0;
#pragma unroll
        for (int jj = 0; jj < 4; jj++) {
            int m = (tid & 7) * 4 + 32 * jj;
            if (m0 + m + 4 > NN) continue;
            float v0 = sm.tile[(m + 0) * 33 + colc];
            float v1 = sm.tile[(m + 1) * 33 + colc];
            float v2 = sm.tile[(m + 2) * 33 + colc];
            float v3 = sm.tile[(m + 3) * 33 + colc];
            float4 xv = *(const float4*)&x[obase + m];
            float4 o;
            o.x = xv.x / (1.f + __expf(-(v0 + bvv)));
            o.y = xv.y / (1.f + __expf(-(v1 + bvv)));
            o.z = xv.z / (1.f + __expf(-(v2 + bvv)));
            o.w = xv.w / (1.f + __expf(-(v3 + bvv)));
            *(float4*)&out[obase + m] = o;
        }
    }
}

// ---------------- launch -------------------------------------------------------
extern "C" void kernel_launch(void* const* d_in, const int* in_sizes, int n_in,
                              void* d_out, int out_size) {
    const float* x      = (const float*)d_in[0];
    const float* qkv_w  = (const float*)d_in[1];
    const float* qkv_b  = (const float*)d_in[2];
    const float* proj_w = (const float*)d_in[3];
    const float* proj_b = (const float*)d_in[4];
    const float* an     = (const float*)d_in[5];
    const float* na     = (const float*)d_in[6];
    const float* dwc_w  = (const float*)d_in[7];
    const float* dwc_b  = (const float*)d_in[8];
    float* out = (float*)d_out;

    cudaFuncSetAttribute(stage2_mma_kernel,
                         cudaFuncAttributeMaxDynamicSharedMemorySize, S2_TOTAL);

    __nv_bfloat16* xbf; cudaGetSymbolAddress((void**)&xbf, g_x_bf);
    __nv_bfloat16* qwbf; cudaGetSymbolAddress((void**)&qwbf, g_qkvw_bf);
    __nv_bfloat16* pwbf; cudaGetSymbolAddress((void**)&pwbf, g_projw_bf);

    {
        size_t nx = (size_t)BB * CC * NN;
        f2bf_kernel<<<(unsigned)((nx / 4 + 255) / 256), 256>>>(x, xbf, nx);
        size_t nw = (size_t)CC * C3;
        f2bf_kernel<<<(unsigned)((nw / 4 + 255) / 256), 256>>>(qkv_w, qwbf, nw);
        size_t np = (size_t)CC * CC;
        f2bf_kernel<<<(unsigned)((np / 4 + 255) / 256), 256>>>(proj_w, pwbf, np);
    }
    upsample_bias_kernel<<<(NH * AG * NN + 255) / 256, 256>>>(an, na);
    qkv_bf16_kernel<<<dim3((NN + 127) / 128, C3 / 128, BB), 256>>>(qkv_b);
    pool_kernel<<<(BB * AG * CC + 255) / 256, 256>>>();
    stage1_kernel<<<dim3(BB * NH, NSEG), 128>>>();
    stage1_reduce_kernel<<<BB * NH, 256>>>();
    stage2_mma_kernel<<<dim3((NN + S2M - 1) / S2M, NH, BB), 256, S2_TOTAL>>>(dwc_w, dwc_b);
    proj_bf16_kernel<<<dim3((NN + 127) / 128, CC / 128, BB), 256>>>(proj_b, x, out);
}

// round 15
// speedup vs baseline: 1.0683x; 1.0371x over previous
#include <cuda_runtime.h>
#include <cuda_bf16.h>
#include <cstdint>
#include <cstddef>

#define BB 32
#define CC 384
#define C3 1152
#define HH 56
#define WW 56
#define NN 3136
#define NH 12
#define HD 32
#define AG 49
#define NSEG 7
#define SCALE 0.17677669529663687f  // 32^-0.5

#define SA 136   // qkv A smem row stride (bf16)
#define SB 136   // B smem row stride (bf16)
#define SAP 40   // proj/stage2 A smem row stride (bf16)
#define SKV 40   // stage1/2 K/V smem row stride (bf16)

// stage2 BM=256 tile
#define S2M 256
#define VROWS 372   // 256 + 2*57 halo, padded
#define VSTR 20     // v tile row stride in 32-bit words
// dynamic smem offsets (bytes)
#define S2_Q 0
#define S2_A (S2_Q + S2M * SAP * 2)        // 20480
#define S2_V (S2_A + 64 * SKV * 2)         // 25600
#define S2_VC (S2_V + 64 * SKV * 2)        // 30720
#define S2_TOTAL (S2_VC + VROWS * VSTR * 4) // 60480

// ---------------- scratch (device globals; no allocation allowed) ----------------
__device__ __nv_bfloat16 g_qkv_bf[(size_t)BB * NN * C3];   // [b][n][3c] bf16
__device__ __nv_bfloat16 g_agentbf[(size_t)BB * AG * CC];  // agents * SCALE, bf16
__device__ float g_pb1[(size_t)NH * AG * NN];              // stage1 bias [h][a][n]
__device__ float g_ab1t[(size_t)NH * NN * 64];             // stage2 bias [h][n][64pad]
__device__ __nv_bfloat16 g_agentv_bf[(size_t)BB * NH * 64 * HD]; // [b][h][64pad][d]
__device__ __nv_bfloat16 g_x_bf[(size_t)BB * CC * NN];     // bf16 copy of x
__device__ __nv_bfloat16 g_qkvw_bf[(size_t)CC * C3];
__device__ __nv_bfloat16 g_projw_bf[(size_t)CC * CC];
__device__ __nv_bfloat16 g_omid_bf[(size_t)BB * NN * CC];  // attn out + dwconv
// stage-1 split-K partials
__device__ float g_s1m[(size_t)BB * NH * NSEG * AG];
__device__ float g_s1l[(size_t)BB * NH * NSEG * AG];
__device__ float g_s1acc[(size_t)BB * NH * NSEG * AG * HD];

// ---------------- asm helpers ---------------------------------------------------
__device__ __forceinline__ void cp16(uint32_t dst, const void* src, int sz) {
    asm volatile("cp.async.cg.shared.global [%0], [%1], 16, %2;\n"
                 :: "r"(dst), "l"(src), "r"(sz));
}
__device__ __forceinline__ void ldsm4t(uint32_t* r, uint32_t addr) {
    asm volatile("ldmatrix.sync.aligned.m8n8.x4.trans.shared.b16 {%0,%1,%2,%3}, [%4];\n"
                 : "=r"(r[0]), "=r"(r[1]), "=r"(r[2]), "=r"(r[3]) : "r"(addr));
}
__device__ __forceinline__ void ldsm4(uint32_t* r, uint32_t addr) {
    asm volatile("ldmatrix.sync.aligned.m8n8.x4.shared.b16 {%0,%1,%2,%3}, [%4];\n"
                 : "=r"(r[0]), "=r"(r[1]), "=r"(r[2]), "=r"(r[3]) : "r"(addr));
}
__device__ __forceinline__ void mma_bf16(float* d, const uint32_t* a,
                                         uint32_t b0, uint32_t b1) {
    asm volatile(
        "mma.sync.aligned.m16n8k16.row.col.f32.bf16.bf16.f32 "
        "{%0,%1,%2,%3}, {%4,%5,%6,%7}, {%8,%9}, {%0,%1,%2,%3};\n"
        : "+f"(d[0]), "+f"(d[1]), "+f"(d[2]), "+f"(d[3])
        : "r"(a[0]), "r"(a[1]), "r"(a[2]), "r"(a[3]), "r"(b0), "r"(b1));
}
__device__ __forceinline__ uint32_t packbf(float x, float y) {
    __nv_bfloat162 h = __floats2bfloat162_rn(x, y);
    return *(uint32_t*)&h;
}
__device__ __forceinline__ uint32_t smem_u32(const void* p) {
    return (uint32_t)__cvta_generic_to_shared(p);
}

// ---------------- kernel 0: fp32 -> bf16 conversion -----------------------------
__global__ void f2bf_kernel(const float* __restrict__ s, __nv_bfloat16* __restrict__ d,
                            size_t n) {
    size_t i = ((size_t)blockIdx.x * 256 + threadIdx.x) * 4;
    if (i >= n) return;
    float4 v = *(const float4*)(s + i);
    *(__nv_bfloat162*)(d + i)     = __floats2bfloat162_rn(v.x, v.y);
    *(__nv_bfloat162*)(d + i + 2) = __floats2bfloat162_rn(v.z, v.w);
}

// ---------------- kernel 1: bilinear upsample of position biases ----------------
__global__ void upsample_bias_kernel(const float* __restrict__ an,
                                     const float* __restrict__ na) {
    int idx = blockIdx.x * 256 + threadIdx.x;
    const int total = NH * AG * NN;
    if (idx >= total) return;
    int n  = idx % NN;
    int ha = idx / NN;
    int h  = ha / AG, a = ha % AG;
    int x = n % WW, y = n / WW;

    float fy = (y + 0.5f) * 0.125f - 0.5f;
    float fx = (x + 0.5f) * 0.125f - 0.5f;
    int y0 = (int)floorf(fy), x0 = (int)floorf(fx);
    float wy = fy - (float)y0, wx = fx - (float)x0;
    int iy0 = min(max(y0, 0), 6), iy1 = min(max(y0 + 1, 0), 6);
    int ix0 = min(max(x0, 0), 6), ix1 = min(max(x0 + 1, 0), 6);
    float w00 = (1.f - wy) * (1.f - wx), w01 = (1.f - wy) * wx;
    float w10 = wy * (1.f - wx),         w11 = wy * wx;

    const float* a_base = an + (size_t)ha * 49;
    const float* n_base = na + (size_t)ha * 49;
    g_pb1[idx] = w00 * a_base[iy0 * 7 + ix0] + w01 * a_base[iy0 * 7 + ix1]
               + w10 * a_base[iy1 * 7 + ix0] + w11 * a_base[iy1 * 7 + ix1];
    float nb = w00 * n_base[iy0 * 7 + ix0] + w01 * n_base[iy0 * 7 + ix1]
             + w10 * n_base[iy1 * 7 + ix0] + w11 * n_base[iy1 * 7 + ix1];
    g_ab1t[((size_t)h * NN + n) * 64 + a] = nb;
}

// ---------------- kernel 2: qkv GEMM via bf16 mma, coalesced epilogue -----------
__global__ __launch_bounds__(256) void qkv_bf16_kernel(const float* __restrict__ bias) {
    union QSm {
        struct { __nv_bfloat16 As[2][32 * SA]; __nv_bfloat16 Bs[2][32 * SB]; } p;
        __nv_bfloat16 tile[128 * 136];   // 34816 B, same size as As+Bs
    };
    __shared__ QSm sm;
    const int b  = blockIdx.z;
    const int m0 = blockIdx.x * 128;
    const int n0 = blockIdx.y * 128;
    const int tid = threadIdx.x, lane = tid & 31, wid = tid >> 5;
    const int wm = (wid & 1) * 64, wn = (wid >> 1) * 32;
    const int g = lane >> 2, t = lane & 3;
    const __nv_bfloat16* xb = g_x_bf + (size_t)b * CC * NN;

    uint32_t sAu[2], sBu[2];
    sAu[0] = smem_u32(sm.p.As[0]); sAu[1] = smem_u32(sm.p.As[1]);
    sBu[0] = smem_u32(sm.p.Bs[0]); sBu[1] = smem_u32(sm.p.Bs[1]);

    float d[4][4][4];
#pragma unroll
    for (int i = 0; i < 4; i++)
#pragma unroll
        for (int j = 0; j < 4; j++)
#pragma unroll
            for (int q = 0; q < 4; q++) d[i][j][q] = 0.f;

    auto issue = [&](int k0, int buf) {
#pragma unroll
        for (int r = 0; r < 2; r++) {
            int ci = tid + r * 256;
            int row = ci >> 4, c = ci & 15;
            int mcol = m0 + c * 8;
            cp16(sAu[buf] + (row * SA + c * 8) * 2,
                 xb + (size_t)(k0 + row) * NN + mcol, mcol < NN ? 16 : 0);
            cp16(sBu[buf] + (row * SB + c * 8) * 2,
                 g_qkvw_bf + (size_t)(k0 + row) * C3 + n0 + c * 8, 16);
        }
        asm volatile("cp.async.commit_group;\n");
    };

    issue(0, 0);
    const int rsel = (lane & 7) + ((lane >> 4) << 3);
    const int csel = ((lane >> 3) & 1) * 8;

    for (int s = 0; s < 12; s++) {
        if (s < 11) {
            issue((s + 1) * 32, (s + 1) & 1);
            asm volatile("cp.async.wait_group 1;\n");
        } else {
            asm volatile("cp.async.wait_group 0;\n");
        }
        __syncthreads();
        const uint32_t sa = sAu[s & 1], sb = sBu[s & 1];
#pragma unroll
        for (int kk = 0; kk < 32; kk += 16) {
            uint32_t a[4][4], bfr[2][4];
            int rA = kk + rsel;
#pragma unroll
            for (int mt = 0; mt < 4; mt++)
                ldsm4t(a[mt], sa + (rA * SA + wm + mt * 16 + csel) * 2);
#pragma unroll
            for (int bt = 0; bt < 2; bt++)
                ldsm4t(bfr[bt], sb + (rA * SB + wn + bt * 16 + csel) * 2);
#pragma unroll
            for (int mt = 0; mt < 4; mt++)
#pragma unroll
                for (int j = 0; j < 4; j++)
                    mma_bf16(d[mt][j], a[mt], bfr[j >> 1][j & 1], bfr[j >> 1][2 + (j & 1)]);
        }
        __syncthreads();
    }

    // epilogue: bias add into fragments -> smem tile -> coalesced 16B stores
#pragma unroll
    for (int mt = 0; mt < 4; mt++)
#pragma unroll
        for (int j = 0; j < 4; j++) {
            int row = wm + mt * 16 + g;
            int col = wn + j * 8 + 2 * t;
            float bv0 = __ldg(&bias[n0 + col]), bv1 = __ldg(&bias[n0 + col + 1]);
            *(__nv_bfloat162*)&sm.tile[row * 136 + col] =
                __floats2bfloat162_rn(d[mt][j][0] + bv0, d[mt][j][1] + bv1);
            *(__nv_bfloat162*)&sm.tile[(row + 8) * 136 + col] =
                __floats2bfloat162_rn(d[mt][j][2] + bv0, d[mt][j][3] + bv1);
        }
    __syncthreads();
#pragma unroll
    for (int r = 0; r < 8; r++) {
        int i = tid + r * 256;
        int row = i >> 4, cs = i & 15;
        int m = m0 + row;
        if (m < NN)
            *(uint4*)&g_qkv_bf[((size_t)b * NN + m) * C3 + n0 + cs * 8] =
                *(uint4*)&sm.tile[row * 136 + cs * 8];
    }
}

// ---------------- kernel 3: agent pooling -> scaled bf16 agents -----------------
__global__ void pool_kernel() {
    int idx = blockIdx.x * 256 + threadIdx.x;
    const int total = BB * AG * CC;
    if (idx >= total) return;
    int c = idx % CC;
    int a = (idx / CC) % AG;
    int b = idx / (CC * AG);
    int py = a / 7, px = a % 7;
    const __nv_bfloat16* q = g_qkv_bf + (size_t)b * NN * C3 + c;
    float s = 0.f;
#pragma unroll
    for (int dy = 0; dy < 8; dy++) {
        int row = (py * 8 + dy) * WW + px * 8;
#pragma unroll
        for (int dx = 0; dx < 8; dx++)
            s += __bfloat162float(q[(size_t)(row + dx) * C3]);
    }
    g_agentbf[idx] = __float2bfloat16_rn(s * 0.015625f * SCALE);
}

// ---------------- kernel 4: stage-1 agent attention via bf16 mma (split-K) ------
__global__ __launch_bounds__(128) void stage1_kernel() {
    __shared__ __nv_bfloat16 sK[2][64 * SKV];
    __shared__ __nv_bfloat16 sV[2][64 * SKV];

    const int tid = threadIdx.x, lane = tid & 31, warp = tid >> 5;
    const int bh = blockIdx.x, seg = blockIdx.y;
    const int b = bh / NH, h = bh % NH;
    const int g = lane >> 2, t = lane & 3;
    const int a_row0 = warp * 16 + g, a_row1 = a_row0 + 8;

    uint32_t skU[2], svU[2];
    skU[0] = smem_u32(sK[0]); skU[1] = smem_u32(sK[1]);
    svU[0] = smem_u32(sV[0]); svU[1] = smem_u32(sV[1]);

    uint32_t afrag[2][4];
    const __nv_bfloat16* agb = g_agentbf + (size_t)b * AG * CC + h * HD;
#pragma unroll
    for (int kt = 0; kt < 2; kt++) {
        int kb = kt * 16 + 2 * t;
        afrag[kt][0] = (a_row0 < AG) ? *(const uint32_t*)(agb + (size_t)a_row0 * CC + kb) : 0u;
        afrag[kt][1] = (a_row1 < AG) ? *(const uint32_t*)(agb + (size_t)a_row1 * CC + kb) : 0u;
        afrag[kt][2] = (a_row0 < AG) ? *(const uint32_t*)(agb + (size_t)a_row0 * CC + kb + 8) : 0u;
        afrag[kt][3] = (a_row1 < AG) ? *(const uint32_t*)(agb + (size_t)a_row1 * CC + kb + 8) : 0u;
    }

    float oacc[4][4];
#pragma unroll
    for (int i = 0; i < 4; i++)
#pragma unroll
        for (int j = 0; j < 4; j++) oacc[i][j] = 0.f;
    float rm0 = -1e30f, rm1 = -1e30f, rl0 = 0.f, rl1 = 0.f;

    const int krow = (lane & 7) + ((lane >> 4) & 1) * 8;
    const int koff = ((lane >> 3) & 1) * 8;
    const int rsel = (lane & 7) + ((lane >> 4) << 3);
    const int csel = ((lane >> 3) & 1) * 8;

    auto issue = [&](int chunk, int buf) {
        int n0 = chunk * 64;
#pragma unroll
        for (int r = 0; r < 2; r++) {
            int c = tid + r * 128;
            int row = c >> 2, sg = c & 3;
            const __nv_bfloat16* gk = g_qkv_bf
                + ((size_t)b * NN + n0 + row) * C3 + CC + h * HD + sg * 8;
            cp16(skU[buf] + (row * SKV + sg * 8) * 2, gk, 16);
            cp16(svU[buf] + (row * SKV + sg * 8) * 2, gk + CC, 16);
        }
        asm volatile("cp.async.commit_group;\n");
    };

    const float* bp0 = g_pb1 + ((size_t)h * AG + (a_row0 < AG ? a_row0 : 0)) * NN;
    const float* bp1 = g_pb1 + ((size_t)h * AG + (a_row1 < AG ? a_row1 : 0)) * NN;

    issue(seg * 7, 0);
    for (int ci = 0; ci < 7; ci++) {
        if (ci < 6) {
            issue(seg * 7 + ci + 1, (ci + 1) & 1);
            asm volatile("cp.async.wait_group 1;\n");
        } else {
            asm volatile("cp.async.wait_group 0;\n");
        }
        __syncthreads();
        const uint32_t sk = skU[ci & 1], sv = svU[ci & 1];
        const int n0 = (seg * 7 + ci) * 64;

        float sc[8][4];
#pragma unroll
        for (int j = 0; j < 8; j++) {
            float2 b0 = (a_row0 < AG) ? *(const float2*)(bp0 + n0 + j * 8 + 2 * t)
                                      : make_float2(0.f, 0.f);
            float2 b1 = (a_row1 < AG) ? *(const float2*)(bp1 + n0 + j * 8 + 2 * t)
                                      : make_float2(0.f, 0.f);
            sc[j][0] = b0.x; sc[j][1] = b0.y; sc[j][2] = b1.x; sc[j][3] = b1.y;
        }
#pragma unroll
        for (int jp = 0; jp < 4; jp++) {
            uint32_t kf0[4], kf1[4];
            ldsm4(kf0, sk + ((jp * 16 + krow) * SKV + koff) * 2);
            ldsm4(kf1, sk + ((jp * 16 + krow) * SKV + 16 + koff) * 2);
            mma_bf16(sc[jp * 2],     afrag[0], kf0[0], kf0[1]);
            mma_bf16(sc[jp * 2],     afrag[1], kf1[0], kf1[1]);
            mma_bf16(sc[jp * 2 + 1], afrag[0], kf0[2], kf0[3]);
            mma_bf16(sc[jp * 2 + 1], afrag[1], kf1[2], kf1[3]);
        }
        float mx0 = sc[0][0], mx1 = sc[0][2];
#pragma unroll
        for (int j = 0; j < 8; j++) {
            mx0 = fmaxf(mx0, fmaxf(sc[j][0], sc[j][1]));
            mx1 = fmaxf(mx1, fmaxf(sc[j][2], sc[j][3]));
        }
        mx0 = fmaxf(mx0, __shfl_xor_sync(0xffffffffu, mx0, 1));
        mx0 = fmaxf(mx0, __shfl_xor_sync(0xffffffffu, mx0, 2));
        mx1 = fmaxf(mx1, __shfl_xor_sync(0xffffffffu, mx1, 1));
        mx1 = fmaxf(mx1, __shfl_xor_sync(0xffffffffu, mx1, 2));
        float nm0 = fmaxf(rm0, mx0), nm1 = fmaxf(rm1, mx1);
        float corr0 = __expf(rm0 - nm0), corr1 = __expf(rm1 - nm1);
        float ls0 = 0.f, ls1 = 0.f;
#pragma unroll
        for (int j = 0; j < 8; j++) {
            sc[j][0] = __expf(sc[j][0] - nm0); ls0 += sc[j][0];
            sc[j][1] = __expf(sc[j][1] - nm0); ls0 += sc[j][1];
            sc[j][2] = __expf(sc[j][2] - nm1); ls1 += sc[j][2];
            sc[j][3] = __expf(sc[j][3] - nm1); ls1 += sc[j][3];
        }
        ls0 += __shfl_xor_sync(0xffffffffu, ls0, 1);
        ls0 += __shfl_xor_sync(0xffffffffu, ls0, 2);
        ls1 += __shfl_xor_sync(0xffffffffu, ls1, 1);
        ls1 += __shfl_xor_sync(0xffffffffu, ls1, 2);
        rl0 = rl0 * corr0 + ls0;
        rl1 = rl1 * corr1 + ls1;
        rm0 = nm0; rm1 = nm1;
#pragma unroll
        for (int nt = 0; nt < 4; nt++) {
            oacc[nt][0] *= corr0; oacc[nt][1] *= corr0;
            oacc[nt][2] *= corr1; oacc[nt][3] *= corr1;
        }
#pragma unroll
        for (int kt = 0; kt < 4; kt++) {
            uint32_t pf[4];
            pf[0] = packbf(sc[2 * kt][0], sc[2 * kt][1]);
            pf[1] = packbf(sc[2 * kt][2], sc[2 * kt][3]);
            pf[2] = packbf(sc[2 * kt + 1][0], sc[2 * kt + 1][1]);
            pf[3] = packbf(sc[2 * kt + 1][2], sc[2 * kt + 1][3]);
            uint32_t vb0[4], vb1[4];
            ldsm4t(vb0, sv + ((kt * 16 + rsel) * SKV + csel) * 2);
            ldsm4t(vb1, sv + ((kt * 16 + rsel) * SKV + 16 + csel) * 2);
            mma_bf16(oacc[0], pf, vb0[0], vb0[2]);
            mma_bf16(oacc[1], pf, vb0[1], vb0[3]);
            mma_bf16(oacc[2], pf, vb1[0], vb1[2]);
            mma_bf16(oacc[3], pf, vb1[1], vb1[3]);
        }
        __syncthreads();
    }

    const size_t base = ((size_t)bh * NSEG + seg) * AG;
#pragma unroll
    for (int nt = 0; nt < 4; nt++) {
        if (a_row0 < AG)
            *(float2*)&g_s1acc[(base + a_row0) * HD + nt * 8 + 2 * t] =
                make_float2(oacc[nt][0], oacc[nt][1]);
        if (a_row1 < AG)
            *(float2*)&g_s1acc[(base + a_row1) * HD + nt * 8 + 2 * t] =
                make_float2(oacc[nt][2], oacc[nt][3]);
    }
    if (t == 0) {
        if (a_row0 < AG) { g_s1m[base + a_row0] = rm0; g_s1l[base + a_row0] = rl0; }
        if (a_row1 < AG) { g_s1m[base + a_row1] = rm1; g_s1l[base + a_row1] = rl1; }
    }
}

// ---------------- kernel 4b: combine split-K partials -> bf16 agent_v -----------
__global__ __launch_bounds__(256) void stage1_reduce_kernel() {
    __shared__ float sW[NSEG][AG];
    __shared__ float sLs[AG];
    const int bh = blockIdx.x;
    const int tid = threadIdx.x;
    const size_t base = (size_t)bh * NSEG * AG;
    if (tid < AG) {
        float M = -1e30f;
#pragma unroll
        for (int s = 0; s < NSEG; s++)
            M = fmaxf(M, g_s1m[base + s * AG + tid]);
        float ls = 0.f;
#pragma unroll
        for (int s = 0; s < NSEG; s++) {
            float wv = __expf(g_s1m[base + s * AG + tid] - M);
            sW[s][tid] = wv;
            ls += wv * g_s1l[base + s * AG + tid];
        }
        sLs[tid] = ls;
    }
    __syncthreads();
    for (int i = tid; i < 64 * HD; i += 256) {
        int a = i >> 5, dd = i & 31;
        float r = 0.f;
        if (a < AG) {
            float acc = 0.f;
#pragma unroll
            for (int s = 0; s < NSEG; s++)
                acc += sW[s][a] * g_s1acc[(base + s * AG + a) * HD + dd];
            r = acc / sLs[a];
        }
        g_agentv_bf[(size_t)bh * 64 * HD + i] = __float2bfloat16_rn(r);
    }
}

// ---------------- kernel 5: stage-2 BM=256, split commit groups -----------------
__global__ __launch_bounds__(256) void stage2_mma_kernel(const float* __restrict__ dwc_w,
                                                         const float* __restrict__ dwc_b) {
    extern __shared__ char dsm[];
    __nv_bfloat16* sQ = (__nv_bfloat16*)(dsm + S2_Q);
    __nv_bfloat16* sA = (__nv_bfloat16*)(dsm + S2_A);
    __nv_bfloat16* sV = (__nv_bfloat16*)(dsm + S2_V);
    uint32_t* sVC = (uint32_t*)(dsm + S2_VC);

    const int b = blockIdx.z, h = blockIdx.y, n0 = blockIdx.x * S2M;
    const int tid = threadIdx.x, lane = tid & 31, warp = tid >> 5;
    const int g = lane >> 2, t = lane & 3;
    const int wm = warp * 32;

    uint32_t sQu = smem_u32(sQ);
    uint32_t sAu = smem_u32(sA);
    uint32_t sVu = smem_u32(sV);
    uint32_t sVCu = smem_u32(sVC);

    // group A: q tile, agents, agent_v (needed for attention compute)
#pragma unroll
    for (int r = 0; r < 4; r++) {
        int c = tid + r * 256;
        int row = c >> 2, sg = c & 3;
        int n = n0 + row;
        cp16(sQu + (row * SAP + sg * 8) * 2,
             g_qkv_bf + ((size_t)b * NN + (n < NN ? n : 0)) * C3 + h * HD + sg * 8,
             n < NN ? 16 : 0);
    }
    if (tid < AG * 4) {
        int row = tid >> 2, sg = tid & 3;
        cp16(sAu + (row * SKV + sg * 8) * 2,
             g_agentbf + ((size_t)b * AG + row) * CC + h * HD + sg * 8, 16);
    }
    {
        int row = tid >> 2, sg = tid & 3;
        cp16(sVu + (row * SKV + sg * 8) * 2,
             g_agentv_bf + ((size_t)(b * NH + h) * 64 + row) * HD + sg * 8, 16);
    }
    asm volatile("cp.async.commit_group;\n");
    // group B: v halo tile (only needed in the dwconv epilogue)
    {
        const __nv_bfloat16* vsrc = g_qkv_bf + (size_t)b * NN * C3 + 2 * CC + h * HD;
        for (int c = tid; c < VROWS * 4; c += 256) {
            int row = c >> 2, sg = c & 3;
            int n = n0 - 57 + row;
            int valid = (n >= 0 && n < NN);
            cp16(sVCu + (row * VSTR + sg * 4) * 4,
                 vsrc + (size_t)(valid ? n : 0) * C3 + sg * 8, valid ? 16 : 0);
        }
    }
    asm volatile("cp.async.commit_group;\n");
    asm volatile("cp.async.wait_group 1;\n");
    __syncthreads();

    const int rmA = (lane & 7) + ((lane >> 3) & 1) * 8;
    const int ckA = ((lane >> 4) << 3);
    const int krow = (lane & 7) + ((lane >> 4) & 1) * 8;
    const int koff = ((lane >> 3) & 1) * 8;
    const int rsel = (lane & 7) + ((lane >> 4) << 3);
    const int csel = ((lane >> 3) & 1) * 8;

    float sc[2][8][4];
#pragma unroll
    for (int mt = 0; mt < 2; mt++) {
        int r0 = n0 + wm + mt * 16 + g;
        int r1 = r0 + 8;
        const float* bq0 = g_ab1t + ((size_t)h * NN + (r0 < NN ? r0 : 0)) * 64;
        const float* bq1 = g_ab1t + ((size_t)h * NN + (r1 < NN ? r1 : 0)) * 64;
#pragma unroll
        for (int j = 0; j < 8; j++) {
            float2 v0 = *(const float2*)(bq0 + j * 8 + 2 * t);
            float2 v1 = *(const float2*)(bq1 + j * 8 + 2 * t);
            sc[mt][j][0] = v0.x; sc[mt][j][1] = v0.y;
            sc[mt][j][2] = v1.x; sc[mt][j][3] = v1.y;
        }
    }
#pragma unroll
    for (int kk = 0; kk < 32; kk += 16) {
        uint32_t a[2][4];
#pragma unroll
        for (int mt = 0; mt < 2; mt++)
            ldsm4(a[mt], sQu + ((wm + mt * 16 + rmA) * SAP + kk + ckA) * 2);
#pragma unroll
        for (int jp = 0; jp < 4; jp++) {
            uint32_t bf4[4];
            ldsm4(bf4, sAu + ((jp * 16 + krow) * SKV + kk + koff) * 2);
#pragma unroll
            for (int mt = 0; mt < 2; mt++) {
                mma_bf16(sc[mt][jp * 2],     a[mt], bf4[0], bf4[1]);
                mma_bf16(sc[mt][jp * 2 + 1], a[mt], bf4[2], bf4[3]);
            }
        }
    }
#pragma unroll
    for (int mt = 0; mt < 2; mt++)
#pragma unroll
        for (int j = 0; j < 8; j++) {
            int c0 = j * 8 + 2 * t;
            if (c0 >= AG)     { sc[mt][j][0] = -1e30f; sc[mt][j][2] = -1e30f; }
            if (c0 + 1 >= AG) { sc[mt][j][1] = -1e30f; sc[mt][j][3] = -1e30f; }
        }
#pragma unroll
    for (int mt = 0; mt < 2; mt++) {
        float mx0 = -1e30f, mx1 = -1e30f;
#pragma unroll
        for (int j = 0; j < 8; j++) {
            mx0 = fmaxf(mx0, fmaxf(sc[mt][j][0], sc[mt][j][1]));
            mx1 = fmaxf(mx1, fmaxf(sc[mt][j][2], sc[mt][j][3]));
        }
        mx0 = fmaxf(mx0, __shfl_xor_sync(0xffffffffu, mx0, 1));
        mx0 = fmaxf(mx0, __shfl_xor_sync(0xffffffffu, mx0, 2));
        mx1 = fmaxf(mx1, __shfl_xor_sync(0xffffffffu, mx1, 1));
        mx1 = fmaxf(mx1, __shfl_xor_sync(0xffffffffu, mx1, 2));
        float l0 = 0.f, l1 = 0.f;
#pragma unroll
        for (int j = 0; j < 8; j++) {
            sc[mt][j][0] = __expf(sc[mt][j][0] - mx0); l0 += sc[mt][j][0];
            sc[mt][j][1] = __expf(sc[mt][j][1] - mx0); l0 += sc[mt][j][1];
            sc[mt][j][2] = __expf(sc[mt][j][2] - mx1); l1 += sc[mt][j][2];
            sc[mt][j][3] = __expf(sc[mt][j][3] - mx1); l1 += sc[mt][j][3];
        }
        l0 += __shfl_xor_sync(0xffffffffu, l0, 1);
        l0 += __shfl_xor_sync(0xffffffffu, l0, 2);
        l1 += __shfl_xor_sync(0xffffffffu, l1, 1);
        l1 += __shfl_xor_sync(0xffffffffu, l1, 2);
        float i0 = 1.f / l0, i1 = 1.f / l1;
#pragma unroll
        for (int j = 0; j < 8; j++) {
            sc[mt][j][0] *= i0; sc[mt][j][1] *= i0;
            sc[mt][j][2] *= i1; sc[mt][j][3] *= i1;
        }
    }
    float oacc[2][4][4];
#pragma unroll
    for (int mt = 0; mt < 2; mt++)
#pragma unroll
        for (int j = 0; j < 4; j++)
#pragma unroll
            for (int q = 0; q < 4; q++) oacc[mt][j][q] = 0.f;
#pragma unroll
    for (int kt = 0; kt < 4; kt++) {
        uint32_t vb0[4], vb1[4];
        ldsm4t(vb0, sVu + ((kt * 16 + rsel) * SKV + csel) * 2);
        ldsm4t(vb1, sVu + ((kt * 16 + rsel) * SKV + 16 + csel) * 2);
#pragma unroll
        for (int mt = 0; mt < 2; mt++) {
            uint32_t pf[4];
            pf[0] = packbf(sc[mt][2 * kt][0], sc[mt][2 * kt][1]);
            pf[1] = packbf(sc[mt][2 * kt][2], sc[mt][2 * kt][3]);
            pf[2] = packbf(sc[mt][2 * kt + 1][0], sc[mt][2 * kt + 1][1]);
            pf[3] = packbf(sc[mt][2 * kt + 1][2], sc[mt][2 * kt + 1][3]);
            mma_bf16(oacc[mt][0], pf, vb0[0], vb0[2]);
            mma_bf16(oacc[mt][1], pf, vb0[1], vb0[3]);
            mma_bf16(oacc[mt][2], pf, vb1[0], vb1[2]);
            mma_bf16(oacc[mt][3], pf, vb1[1], vb1[3]);
        }
    }
    asm volatile("cp.async.wait_group 0;\n");
    __syncthreads();
#pragma unroll
    for (int nt = 0; nt < 4; nt++) {
        int c0l = nt * 8 + 2 * t;
        int c0  = h * HD + c0l;
        int cw  = nt * 4 + t;
        float bw0 = __ldg(&dwc_b[c0]), bw1 = __ldg(&dwc_b[c0 + 1]);
        float w0[9], w1[9];
#pragma unroll
        for (int k = 0; k < 9; k++) {
            w0[k] = __ldg(&dwc_w[c0 * 9 + k]);
            w1[k] = __ldg(&dwc_w[(c0 + 1) * 9 + k]);
        }
#pragma unroll
        for (int mt = 0; mt < 2; mt++)
#pragma unroll
            for (int rr = 0; rr < 2; rr++) {
                int n = n0 + wm + mt * 16 + g + rr * 8;
                if (n >= NN) continue;
                int y = n / WW, x = n % WW;
                float a0 = bw0, a1 = bw1;
#pragma unroll
                for (int ky = 0; ky < 3; ky++) {
                    int yy = y + ky - 1;
                    if (yy < 0 || yy >= HH) continue;
#pragma unroll
                    for (int kx = 0; kx < 3; kx++) {
                        int xx = x + kx - 1;
                        if (xx < 0 || xx >= WW) continue;
                        int tap = (yy * WW + xx) - n0 + 57;
                        uint32_t vw = sVC[tap * VSTR + cw];
                        float2 vf = __bfloat1622float2(*(__nv_bfloat162*)&vw);
                        a0 += vf.x * w0[ky * 3 + kx];
                        a1 += vf.y * w1[ky * 3 + kx];
                    }
                }
                float d0 = oacc[mt][nt][rr * 2] + a0;
                float d1 = oacc[mt][nt][rr * 2 + 1] + a1;
                *(__nv_bfloat162*)&g_omid_bf[((size_t)b * NN + n) * CC + c0] =
                    __floats2bfloat162_rn(d0, d1);
            }
    }
}

// ---------------- kernel 7: proj GEMM via bf16 mma + transposed epilogue --------
__global__ __launch_bounds__(256) void proj_bf16_kernel(const float* __restrict__ bias,
                                                        const float* __restrict__ x,
                                                        float* __restrict__ out) {
    union Sm {
        struct { __nv_bfloat16 As[2][128 * SAP]; __nv_bfloat16 Bs[2][32 * SB]; } p;
        float tile[128 * 33];
    };
    __shared__ Sm sm;
    const int b  = blockIdx.z;
    const int m0 = blockIdx.x * 128;
    const int n0 = blockIdx.y * 128;
    const int tid = threadIdx.x, lane = tid & 31, wid = tid >> 5;
    const int wm = (wid & 1) * 64, wn = (wid >> 1) * 32;
    const int g = lane >> 2, t = lane & 3;

    uint32_t sAu[2], sBu[2];
    sAu[0] = smem_u32(sm.p.As[0]); sAu[1] = smem_u32(sm.p.As[1]);
    sBu[0] = smem_u32(sm.p.Bs[0]); sBu[1] = smem_u32(sm.p.Bs[1]);

    float d[4][4][4];
#pragma unroll
    for (int i = 0; i < 4; i++)
#pragma unroll
        for (int j = 0; j < 4; j++)
#pragma unroll
            for (int q = 0; q < 4; q++) d[i][j][q] = 0.f;

    const __nv_bfloat16* ab = g_omid_bf + ((size_t)b * NN + m0) * CC;

    auto issue = [&](int k0, int buf) {
#pragma unroll
        for (int r = 0; r < 2; r++) {
            int ci = tid + r * 256;
            int rowA = ci >> 2, cA = ci & 3;
            cp16(sAu[buf] + (rowA * SAP + cA * 8) * 2,
                 ab + (size_t)rowA * CC + k0 + cA * 8, (m0 + rowA) < NN ? 16 : 0);
            int rowB = ci >> 4, cB = ci & 15;
            cp16(sBu[buf] + (rowB * SB + cB * 8) * 2,
                 g_projw_bf + (size_t)(k0 + rowB) * CC + n0 + cB * 8, 16);
        }
        asm volatile("cp.async.commit_group;\n");
    };

    issue(0, 0);
    const int rmA = (lane & 7) + ((lane >> 3) & 1) * 8;
    const int ckA = ((lane >> 4) << 3);
    const int rsel = (lane & 7) + ((lane >> 4) << 3);
    const int csel = ((lane >> 3) & 1) * 8;

    for (int s = 0; s < 12; s++) {
        if (s < 11) {
            issue((s + 1) * 32, (s + 1) & 1);
            asm volatile("cp.async.wait_group 1;\n");
        } else {
            asm volatile("cp.async.wait_group 0;\n");
        }
        __syncthreads();
        const uint32_t sa = sAu[s & 1], sb = sBu[s & 1];
#pragma unroll
        for (int kk = 0; kk < 32; kk += 16) {
            uint32_t a[4][4], bfr[2][4];
#pragma unroll
            for (int mt = 0; mt < 4; mt++)
                ldsm4(a[mt], sa + ((wm + mt * 16 + rmA) * SAP + kk + ckA) * 2);
            int rB = kk + rsel;
#pragma unroll
            for (int bt = 0; bt < 2; bt++)
                ldsm4t(bfr[bt], sb + (rB * SB + wn + bt * 16 + csel) * 2);
#pragma unroll
            for (int mt = 0; mt < 4; mt++)
#pragma unroll
                for (int j = 0; j < 4; j++)
                    mma_bf16(d[mt][j], a[mt], bfr[j >> 1][j & 1], bfr[j >> 1][2 + (j & 1)]);
        }
        __syncthreads();
    }

#pragma unroll
    for (int p = 0; p < 4; p++) {
        __syncthreads();
        if ((wid >> 1) == p) {
#pragma unroll
            for (int mt = 0; mt < 4; mt++)
#pragma unroll
                for (int j = 0; j < 4; j++) {
                    int row = wm + mt * 16 + g;
                    int colL = j * 8 + 2 * t;
                    sm.tile[row * 33 + colL]           = d[mt][j][0];
                    sm.tile[row * 33 + colL + 1]       = d[mt][j][1];
                    sm.tile[(row + 8) * 33 + colL]     = d[mt][j][2];
                    sm.tile[(row + 8) * 33 + colL + 1] = d[mt][j][3];
                }
        }
        __syncthreads();
        int colc = tid >> 3;
        int ch = n0 + p * 32 + colc;
        float bvv = __ldg(&bias[ch]);
        size_t obase = ((size_t)b * CC + ch) * NN + m0;
#pragma unroll
        for (int jj = 0; jj < 4; jj++) {
            int m = (tid & 7) * 4 + 32 * jj;
            if (m0 + m + 4 > NN) continue;
            float v0 = sm.tile[(m + 0) * 33 + colc];
            float v1 = sm.tile[(m + 1) * 33 + colc];
            float v2 = sm.tile[(m + 2) * 33 + colc];
            float v3 = sm.tile[(m + 3) * 33 + colc];
            float4 xv = *(const float4*)&x[obase + m];
            float4 o;
            o.x = xv.x / (1.f + __expf(-(v0 + bvv)));
            o.y = xv.y / (1.f + __expf(-(v1 + bvv)));
            o.z = xv.z / (1.f + __expf(-(v2 + bvv)));
            o.w = xv.w / (1.f + __expf(-(v3 + bvv)));
            *(float4*)&out[obase + m] = o;
        }
    }
}

// ---------------- launch -------------------------------------------------------
extern "C" void kernel_launch(void* const* d_in, const int* in_sizes, int n_in,
                              void* d_out, int out_size) {
    const float* x      = (const float*)d_in[0];
    const float* qkv_w  = (const float*)d_in[1];
    const float* qkv_b  = (const float*)d_in[2];
    const float* proj_w = (const float*)d_in[3];
    const float* proj_b = (const float*)d_in[4];
    const float* an     = (const float*)d_in[5];
    const float* na     = (const float*)d_in[6];
    const float* dwc_w  = (const float*)d_in[7];
    const float* dwc_b  = (const float*)d_in[8];
    float* out = (float*)d_out;

    cudaFuncSetAttribute(stage2_mma_kernel,
                         cudaFuncAttributeMaxDynamicSharedMemorySize, S2_TOTAL);

    __nv_bfloat16* xbf; cudaGetSymbolAddress((void**)&xbf, g_x_bf);
    __nv_bfloat16* qwbf; cudaGetSymbolAddress((void**)&qwbf, g_qkvw_bf);
    __nv_bfloat16* pwbf; cudaGetSymbolAddress((void**)&pwbf, g_projw_bf);

    {
        size_t nx = (size_t)BB * CC * NN;
        f2bf_kernel<<<(unsigned)((nx / 4 + 255) / 256), 256>>>(x, xbf, nx);
        size_t nw = (size_t)CC * C3;
        f2bf_kernel<<<(unsigned)((nw / 4 + 255) / 256), 256>>>(qkv_w, qwbf, nw);
        size_t np = (size_t)CC * CC;
        f2bf_kernel<<<(unsigned)((np / 4 + 255) / 256), 256>>>(proj_w, pwbf, np);
    }
    upsample_bias_kernel<<<(NH * AG * NN + 255) / 256, 256>>>(an, na);
    qkv_bf16_kernel<<<dim3((NN + 127) / 128, C3 / 128, BB), 256>>>(qkv_b);
    pool_kernel<<<(BB * AG * CC + 255) / 256, 256>>>();
    stage1_kernel<<<dim3(BB * NH, NSEG), 128>>>();
    stage1_reduce_kernel<<<BB * NH, 256>>>();
    stage2_mma_kernel<<<dim3((NN + S2M - 1) / S2M, NH, BB), 256, S2_TOTAL>>>(dwc_w, dwc_b);
    proj_bf16_kernel<<<dim3((NN + 127) / 128, CC / 128, BB), 256>>>(proj_b, x, out);
}

// round 16
// speedup vs baseline: 1.0842x; 1.0149x over previous
#include <cuda_runtime.h>
#include <cuda_bf16.h>
#include <cstdint>
#include <cstddef>

#define BB 32
#define CC 384
#define C3 1152
#define HH 56
#define WW 56
#define NN 3136
#define NH 12
#define HD 32
#define AG 49
#define NSEG 7
#define SCALE 0.17677669529663687f  // 32^-0.5

#define SA 136   // qkv A smem row stride (bf16)
#define SB 136   // B smem row stride (bf16)
#define SAP 40   // proj/stage2 A smem row stride (bf16)
#define SKV 40   // stage1/2 K/V smem row stride (bf16)

// stage2 BM=256 tile
#define S2M 256
#define VROWS 372   // 256 + 2*57 halo, padded
#define VSTR 20     // v tile row stride in 32-bit words
// dynamic smem offsets (bytes)
#define S2_Q 0
#define S2_A (S2_Q + S2M * SAP * 2)        // 20480
#define S2_V (S2_A + 64 * SKV * 2)         // 25600
#define S2_VC (S2_V + 64 * SKV * 2)        // 30720
#define S2_TOTAL (S2_VC + VROWS * VSTR * 4) // 60480

// ---------------- scratch (device globals; no allocation allowed) ----------------
__device__ __nv_bfloat16 g_qkv_bf[(size_t)BB * NN * C3];   // [b][n][3c] bf16
__device__ __nv_bfloat16 g_agentbf[(size_t)BB * AG * CC];  // agents * SCALE, bf16
__device__ float g_pb1[(size_t)NH * AG * NN];              // stage1 bias [h][a][n]
__device__ float g_ab1t[(size_t)NH * NN * 64];             // stage2 bias [h][n][64pad]
__device__ __nv_bfloat16 g_agentv_bf[(size_t)BB * NH * 64 * HD]; // [b][h][64pad][d]
__device__ __nv_bfloat16 g_x_bf[(size_t)BB * CC * NN];     // bf16 copy of x
__device__ __nv_bfloat16 g_qkvw_bf[(size_t)CC * C3];
__device__ __nv_bfloat16 g_projw_bf[(size_t)CC * CC];
__device__ __nv_bfloat16 g_omid_bf[(size_t)BB * NN * CC];  // attn out + dwconv
// stage-1 split-K partials
__device__ float g_s1m[(size_t)BB * NH * NSEG * AG];
__device__ float g_s1l[(size_t)BB * NH * NSEG * AG];
__device__ float g_s1acc[(size_t)BB * NH * NSEG * AG * HD];

// ---------------- asm helpers ---------------------------------------------------
__device__ __forceinline__ void cp16(uint32_t dst, const void* src, int sz) {
    asm volatile("cp.async.cg.shared.global [%0], [%1], 16, %2;\n"
                 :: "r"(dst), "l"(src), "r"(sz));
}
__device__ __forceinline__ void ldsm4t(uint32_t* r, uint32_t addr) {
    asm volatile("ldmatrix.sync.aligned.m8n8.x4.trans.shared.b16 {%0,%1,%2,%3}, [%4];\n"
                 : "=r"(r[0]), "=r"(r[1]), "=r"(r[2]), "=r"(r[3]) : "r"(addr));
}
__device__ __forceinline__ void ldsm4(uint32_t* r, uint32_t addr) {
    asm volatile("ldmatrix.sync.aligned.m8n8.x4.shared.b16 {%0,%1,%2,%3}, [%4];\n"
                 : "=r"(r[0]), "=r"(r[1]), "=r"(r[2]), "=r"(r[3]) : "r"(addr));
}
__device__ __forceinline__ void mma_bf16(float* d, const uint32_t* a,
                                         uint32_t b0, uint32_t b1) {
    asm volatile(
        "mma.sync.aligned.m16n8k16.row.col.f32.bf16.bf16.f32 "
        "{%0,%1,%2,%3}, {%4,%5,%6,%7}, {%8,%9}, {%0,%1,%2,%3};\n"
        : "+f"(d[0]), "+f"(d[1]), "+f"(d[2]), "+f"(d[3])
        : "r"(a[0]), "r"(a[1]), "r"(a[2]), "r"(a[3]), "r"(b0), "r"(b1));
}
__device__ __forceinline__ uint32_t packbf(float x, float y) {
    __nv_bfloat162 h = __floats2bfloat162_rn(x, y);
    return *(uint32_t*)&h;
}
__device__ __forceinline__ uint32_t smem_u32(const void* p) {
    return (uint32_t)__cvta_generic_to_shared(p);
}

// ---------------- kernel 0: fp32 -> bf16 conversion -----------------------------
__global__ void f2bf_kernel(const float* __restrict__ s, __nv_bfloat16* __restrict__ d,
                            size_t n) {
    size_t i = ((size_t)blockIdx.x * 256 + threadIdx.x) * 4;
    if (i >= n) return;
    float4 v = *(const float4*)(s + i);
    *(__nv_bfloat162*)(d + i)     = __floats2bfloat162_rn(v.x, v.y);
    *(__nv_bfloat162*)(d + i + 2) = __floats2bfloat162_rn(v.z, v.w);
}

// ---------------- kernel 1: bilinear upsample of position biases ----------------
__global__ void upsample_bias_kernel(const float* __restrict__ an,
                                     const float* __restrict__ na) {
    int idx = blockIdx.x * 256 + threadIdx.x;
    const int total = NH * AG * NN;
    if (idx >= total) return;
    int n  = idx % NN;
    int ha = idx / NN;
    int h  = ha / AG, a = ha % AG;
    int x = n % WW, y = n / WW;

    float fy = (y + 0.5f) * 0.125f - 0.5f;
    float fx = (x + 0.5f) * 0.125f - 0.5f;
    int y0 = (int)floorf(fy), x0 = (int)floorf(fx);
    float wy = fy - (float)y0, wx = fx - (float)x0;
    int iy0 = min(max(y0, 0), 6), iy1 = min(max(y0 + 1, 0), 6);
    int ix0 = min(max(x0, 0), 6), ix1 = min(max(x0 + 1, 0), 6);
    float w00 = (1.f - wy) * (1.f - wx), w01 = (1.f - wy) * wx;
    float w10 = wy * (1.f - wx),         w11 = wy * wx;

    const float* a_base = an + (size_t)ha * 49;
    const float* n_base = na + (size_t)ha * 49;
    g_pb1[idx] = w00 * a_base[iy0 * 7 + ix0] + w01 * a_base[iy0 * 7 + ix1]
               + w10 * a_base[iy1 * 7 + ix0] + w11 * a_base[iy1 * 7 + ix1];
    float nb = w00 * n_base[iy0 * 7 + ix0] + w01 * n_base[iy0 * 7 + ix1]
             + w10 * n_base[iy1 * 7 + ix0] + w11 * n_base[iy1 * 7 + ix1];
    g_ab1t[((size_t)h * NN + n) * 64 + a] = nb;
}

// ---------------- kernel 2: qkv GEMM via bf16 mma, coalesced epilogue -----------
__global__ __launch_bounds__(256) void qkv_bf16_kernel(const float* __restrict__ bias) {
    union QSm {
        struct { __nv_bfloat16 As[2][32 * SA]; __nv_bfloat16 Bs[2][32 * SB]; } p;
        __nv_bfloat16 tile[128 * 136];   // 34816 B, same size as As+Bs
    };
    __shared__ QSm sm;
    const int b  = blockIdx.z;
    const int m0 = blockIdx.x * 128;
    const int n0 = blockIdx.y * 128;
    const int tid = threadIdx.x, lane = tid & 31, wid = tid >> 5;
    const int wm = (wid & 1) * 64, wn = (wid >> 1) * 32;
    const int g = lane >> 2, t = lane & 3;
    const __nv_bfloat16* xb = g_x_bf + (size_t)b * CC * NN;

    uint32_t sAu[2], sBu[2];
    sAu[0] = smem_u32(sm.p.As[0]); sAu[1] = smem_u32(sm.p.As[1]);
    sBu[0] = smem_u32(sm.p.Bs[0]); sBu[1] = smem_u32(sm.p.Bs[1]);

    float d[4][4][4];
#pragma unroll
    for (int i = 0; i < 4; i++)
#pragma unroll
        for (int j = 0; j < 4; j++)
#pragma unroll
            for (int q = 0; q < 4; q++) d[i][j][q] = 0.f;

    auto issue = [&](int k0, int buf) {
#pragma unroll
        for (int r = 0; r < 2; r++) {
            int ci = tid + r * 256;
            int row = ci >> 4, c = ci & 15;
            int mcol = m0 + c * 8;
            cp16(sAu[buf] + (row * SA + c * 8) * 2,
                 xb + (size_t)(k0 + row) * NN + mcol, mcol < NN ? 16 : 0);
            cp16(sBu[buf] + (row * SB + c * 8) * 2,
                 g_qkvw_bf + (size_t)(k0 + row) * C3 + n0 + c * 8, 16);
        }
        asm volatile("cp.async.commit_group;\n");
    };

    issue(0, 0);
    const int rsel = (lane & 7) + ((lane >> 4) << 3);
    const int csel = ((lane >> 3) & 1) * 8;

    for (int s = 0; s < 12; s++) {
        if (s < 11) {
            issue((s + 1) * 32, (s + 1) & 1);
            asm volatile("cp.async.wait_group 1;\n");
        } else {
            asm volatile("cp.async.wait_group 0;\n");
        }
        __syncthreads();
        const uint32_t sa = sAu[s & 1], sb = sBu[s & 1];
#pragma unroll
        for (int kk = 0; kk < 32; kk += 16) {
            uint32_t a[4][4], bfr[2][4];
            int rA = kk + rsel;
#pragma unroll
            for (int mt = 0; mt < 4; mt++)
                ldsm4t(a[mt], sa + (rA * SA + wm + mt * 16 + csel) * 2);
#pragma unroll
            for (int bt = 0; bt < 2; bt++)
                ldsm4t(bfr[bt], sb + (rA * SB + wn + bt * 16 + csel) * 2);
#pragma unroll
            for (int mt = 0; mt < 4; mt++)
#pragma unroll
                for (int j = 0; j < 4; j++)
                    mma_bf16(d[mt][j], a[mt], bfr[j >> 1][j & 1], bfr[j >> 1][2 + (j & 1)]);
        }
        __syncthreads();
    }

    // epilogue: bias add into fragments -> smem tile -> coalesced 16B stores
#pragma unroll
    for (int mt = 0; mt < 4; mt++)
#pragma unroll
        for (int j = 0; j < 4; j++) {
            int row = wm + mt * 16 + g;
            int col = wn + j * 8 + 2 * t;
            float bv0 = __ldg(&bias[n0 + col]), bv1 = __ldg(&bias[n0 + col + 1]);
            *(__nv_bfloat162*)&sm.tile[row * 136 + col] =
                __floats2bfloat162_rn(d[mt][j][0] + bv0, d[mt][j][1] + bv1);
            *(__nv_bfloat162*)&sm.tile[(row + 8) * 136 + col] =
                __floats2bfloat162_rn(d[mt][j][2] + bv0, d[mt][j][3] + bv1);
        }
    __syncthreads();
#pragma unroll
    for (int r = 0; r < 8; r++) {
        int i = tid + r * 256;
        int row = i >> 4, cs = i & 15;
        int m = m0 + row;
        if (m < NN)
            *(uint4*)&g_qkv_bf[((size_t)b * NN + m) * C3 + n0 + cs * 8] =
                *(uint4*)&sm.tile[row * 136 + cs * 8];
    }
}

// ---------------- kernel 3: agent pooling -> scaled bf16 agents -----------------
__global__ void pool_kernel() {
    int idx = blockIdx.x * 256 + threadIdx.x;
    const int total = BB * AG * CC;
    if (idx >= total) return;
    int c = idx % CC;
    int a = (idx / CC) % AG;
    int b = idx / (CC * AG);
    int py = a / 7, px = a % 7;
    const __nv_bfloat16* q = g_qkv_bf + (size_t)b * NN * C3 + c;
    float s = 0.f;
#pragma unroll
    for (int dy = 0; dy < 8; dy++) {
        int row = (py * 8 + dy) * WW + px * 8;
#pragma unroll
        for (int dx = 0; dx < 8; dx++)
            s += __bfloat162float(q[(size_t)(row + dx) * C3]);
    }
    g_agentbf[idx] = __float2bfloat16_rn(s * 0.015625f * SCALE);
}

// ---------------- kernel 4: stage-1 agent attention via bf16 mma (split-K) ------
__global__ __launch_bounds__(128) void stage1_kernel() {
    __shared__ __nv_bfloat16 sK[2][64 * SKV];
    __shared__ __nv_bfloat16 sV[2][64 * SKV];

    const int tid = threadIdx.x, lane = tid & 31, warp = tid >> 5;
    const int bh = blockIdx.x, seg = blockIdx.y;
    const int b = bh / NH, h = bh % NH;
    const int g = lane >> 2, t = lane & 3;
    const int a_row0 = warp * 16 + g, a_row1 = a_row0 + 8;

    uint32_t skU[2], svU[2];
    skU[0] = smem_u32(sK[0]); skU[1] = smem_u32(sK[1]);
    svU[0] = smem_u32(sV[0]); svU[1] = smem_u32(sV[1]);

    uint32_t afrag[2][4];
    const __nv_bfloat16* agb = g_agentbf + (size_t)b * AG * CC + h * HD;
#pragma unroll
    for (int kt = 0; kt < 2; kt++) {
        int kb = kt * 16 + 2 * t;
        afrag[kt][0] = (a_row0 < AG) ? *(const uint32_t*)(agb + (size_t)a_row0 * CC + kb) : 0u;
        afrag[kt][1] = (a_row1 < AG) ? *(const uint32_t*)(agb + (size_t)a_row1 * CC + kb) : 0u;
        afrag[kt][2] = (a_row0 < AG) ? *(const uint32_t*)(agb + (size_t)a_row0 * CC + kb + 8) : 0u;
        afrag[kt][3] = (a_row1 < AG) ? *(const uint32_t*)(agb + (size_t)a_row1 * CC + kb + 8) : 0u;
    }

    float oacc[4][4];
#pragma unroll
    for (int i = 0; i < 4; i++)
#pragma unroll
        for (int j = 0; j < 4; j++) oacc[i][j] = 0.f;
    float rm0 = -1e30f, rm1 = -1e30f, rl0 = 0.f, rl1 = 0.f;

    const int krow = (lane & 7) + ((lane >> 4) & 1) * 8;
    const int koff = ((lane >> 3) & 1) * 8;
    const int rsel = (lane & 7) + ((lane >> 4) << 3);
    const int csel = ((lane >> 3) & 1) * 8;

    auto issue = [&](int chunk, int buf) {
        int n0 = chunk * 64;
#pragma unroll
        for (int r = 0; r < 2; r++) {
            int c = tid + r * 128;
            int row = c >> 2, sg = c & 3;
            const __nv_bfloat16* gk = g_qkv_bf
                + ((size_t)b * NN + n0 + row) * C3 + CC + h * HD + sg * 8;
            cp16(skU[buf] + (row * SKV + sg * 8) * 2, gk, 16);
            cp16(svU[buf] + (row * SKV + sg * 8) * 2, gk + CC, 16);
        }
        asm volatile("cp.async.commit_group;\n");
    };

    const float* bp0 = g_pb1 + ((size_t)h * AG + (a_row0 < AG ? a_row0 : 0)) * NN;
    const float* bp1 = g_pb1 + ((size_t)h * AG + (a_row1 < AG ? a_row1 : 0)) * NN;

    issue(seg * 7, 0);
    for (int ci = 0; ci < 7; ci++) {
        if (ci < 6) {
            issue(seg * 7 + ci + 1, (ci + 1) & 1);
            asm volatile("cp.async.wait_group 1;\n");
        } else {
            asm volatile("cp.async.wait_group 0;\n");
        }
        __syncthreads();
        const uint32_t sk = skU[ci & 1], sv = svU[ci & 1];
        const int n0 = (seg * 7 + ci) * 64;

        float sc[8][4];
#pragma unroll
        for (int j = 0; j < 8; j++) {
            float2 b0 = (a_row0 < AG) ? *(const float2*)(bp0 + n0 + j * 8 + 2 * t)
                                      : make_float2(0.f, 0.f);
            float2 b1 = (a_row1 < AG) ? *(const float2*)(bp1 + n0 + j * 8 + 2 * t)
                                      : make_float2(0.f, 0.f);
            sc[j][0] = b0.x; sc[j][1] = b0.y; sc[j][2] = b1.x; sc[j][3] = b1.y;
        }
#pragma unroll
        for (int jp = 0; jp < 4; jp++) {
            uint32_t kf0[4], kf1[4];
            ldsm4(kf0, sk + ((jp * 16 + krow) * SKV + koff) * 2);
            ldsm4(kf1, sk + ((jp * 16 + krow) * SKV + 16 + koff) * 2);
            mma_bf16(sc[jp * 2],     afrag[0], kf0[0], kf0[1]);
            mma_bf16(sc[jp * 2],     afrag[1], kf1[0], kf1[1]);
            mma_bf16(sc[jp * 2 + 1], afrag[0], kf0[2], kf0[3]);
            mma_bf16(sc[jp * 2 + 1], afrag[1], kf1[2], kf1[3]);
        }
        float mx0 = sc[0][0], mx1 = sc[0][2];
#pragma unroll
        for (int j = 0; j < 8; j++) {
            mx0 = fmaxf(mx0, fmaxf(sc[j][0], sc[j][1]));
            mx1 = fmaxf(mx1, fmaxf(sc[j][2], sc[j][3]));
        }
        mx0 = fmaxf(mx0, __shfl_xor_sync(0xffffffffu, mx0, 1));
        mx0 = fmaxf(mx0, __shfl_xor_sync(0xffffffffu, mx0, 2));
        mx1 = fmaxf(mx1, __shfl_xor_sync(0xffffffffu, mx1, 1));
        mx1 = fmaxf(mx1, __shfl_xor_sync(0xffffffffu, mx1, 2));
        float nm0 = fmaxf(rm0, mx0), nm1 = fmaxf(rm1, mx1);
        float corr0 = __expf(rm0 - nm0), corr1 = __expf(rm1 - nm1);
        float ls0 = 0.f, ls1 = 0.f;
#pragma unroll
        for (int j = 0; j < 8; j++) {
            sc[j][0] = __expf(sc[j][0] - nm0); ls0 += sc[j][0];
            sc[j][1] = __expf(sc[j][1] - nm0); ls0 += sc[j][1];
            sc[j][2] = __expf(sc[j][2] - nm1); ls1 += sc[j][2];
            sc[j][3] = __expf(sc[j][3] - nm1); ls1 += sc[j][3];
        }
        ls0 += __shfl_xor_sync(0xffffffffu, ls0, 1);
        ls0 += __shfl_xor_sync(0xffffffffu, ls0, 2);
        ls1 += __shfl_xor_sync(0xffffffffu, ls1, 1);
        ls1 += __shfl_xor_sync(0xffffffffu, ls1, 2);
        rl0 = rl0 * corr0 + ls0;
        rl1 = rl1 * corr1 + ls1;
        rm0 = nm0; rm1 = nm1;
#pragma unroll
        for (int nt = 0; nt < 4; nt++) {
            oacc[nt][0] *= corr0; oacc[nt][1] *= corr0;
            oacc[nt][2] *= corr1; oacc[nt][3] *= corr1;
        }
#pragma unroll
        for (int kt = 0; kt < 4; kt++) {
            uint32_t pf[4];
            pf[0] = packbf(sc[2 * kt][0], sc[2 * kt][1]);
            pf[1] = packbf(sc[2 * kt][2], sc[2 * kt][3]);
            pf[2] = packbf(sc[2 * kt + 1][0], sc[2 * kt + 1][1]);
            pf[3] = packbf(sc[2 * kt + 1][2], sc[2 * kt + 1][3]);
            uint32_t vb0[4], vb1[4];
            ldsm4t(vb0, sv + ((kt * 16 + rsel) * SKV + csel) * 2);
            ldsm4t(vb1, sv + ((kt * 16 + rsel) * SKV + 16 + csel) * 2);
            mma_bf16(oacc[0], pf, vb0[0], vb0[2]);
            mma_bf16(oacc[1], pf, vb0[1], vb0[3]);
            mma_bf16(oacc[2], pf, vb1[0], vb1[2]);
            mma_bf16(oacc[3], pf, vb1[1], vb1[3]);
        }
        __syncthreads();
    }

    const size_t base = ((size_t)bh * NSEG + seg) * AG;
#pragma unroll
    for (int nt = 0; nt < 4; nt++) {
        if (a_row0 < AG)
            *(float2*)&g_s1acc[(base + a_row0) * HD + nt * 8 + 2 * t] =
                make_float2(oacc[nt][0], oacc[nt][1]);
        if (a_row1 < AG)
            *(float2*)&g_s1acc[(base + a_row1) * HD + nt * 8 + 2 * t] =
                make_float2(oacc[nt][2], oacc[nt][3]);
    }
    if (t == 0) {
        if (a_row0 < AG) { g_s1m[base + a_row0] = rm0; g_s1l[base + a_row0] = rl0; }
        if (a_row1 < AG) { g_s1m[base + a_row1] = rm1; g_s1l[base + a_row1] = rl1; }
    }
}

// ---------------- kernel 4b: combine split-K partials -> bf16 agent_v -----------
__global__ __launch_bounds__(256) void stage1_reduce_kernel() {
    __shared__ float sW[NSEG][AG];
    __shared__ float sLs[AG];
    const int bh = blockIdx.x;
    const int tid = threadIdx.x;
    const size_t base = (size_t)bh * NSEG * AG;
    if (tid < AG) {
        float M = -1e30f;
#pragma unroll
        for (int s = 0; s < NSEG; s++)
            M = fmaxf(M, g_s1m[base + s * AG + tid]);
        float ls = 0.f;
#pragma unroll
        for (int s = 0; s < NSEG; s++) {
            float wv = __expf(g_s1m[base + s * AG + tid] - M);
            sW[s][tid] = wv;
            ls += wv * g_s1l[base + s * AG + tid];
        }
        sLs[tid] = ls;
    }
    __syncthreads();
    for (int i = tid; i < 64 * HD; i += 256) {
        int a = i >> 5, dd = i & 31;
        float r = 0.f;
        if (a < AG) {
            float acc = 0.f;
#pragma unroll
            for (int s = 0; s < NSEG; s++)
                acc += sW[s][a] * g_s1acc[(base + s * AG + a) * HD + dd];
            r = acc / sLs[a];
        }
        g_agentv_bf[(size_t)bh * 64 * HD + i] = __float2bfloat16_rn(r);
    }
}

// ---------------- kernel 5: stage-2 BM=256, staged coalesced output -------------
__global__ __launch_bounds__(256) void stage2_mma_kernel(const float* __restrict__ dwc_w,
                                                         const float* __restrict__ dwc_b) {
    extern __shared__ char dsm[];
    __nv_bfloat16* sQ = (__nv_bfloat16*)(dsm + S2_Q);
    __nv_bfloat16* sA = (__nv_bfloat16*)(dsm + S2_A);
    __nv_bfloat16* sV = (__nv_bfloat16*)(dsm + S2_V);
    uint32_t* sVC = (uint32_t*)(dsm + S2_VC);

    const int b = blockIdx.z, h = blockIdx.y, n0 = blockIdx.x * S2M;
    const int tid = threadIdx.x, lane = tid & 31, warp = tid >> 5;
    const int g = lane >> 2, t = lane & 3;
    const int wm = warp * 32;

    uint32_t sQu = smem_u32(sQ);
    uint32_t sAu = smem_u32(sA);
    uint32_t sVu = smem_u32(sV);
    uint32_t sVCu = smem_u32(sVC);

    // group A: q tile, agents, agent_v (needed for attention compute)
#pragma unroll
    for (int r = 0; r < 4; r++) {
        int c = tid + r * 256;
        int row = c >> 2, sg = c & 3;
        int n = n0 + row;
        cp16(sQu + (row * SAP + sg * 8) * 2,
             g_qkv_bf + ((size_t)b * NN + (n < NN ? n : 0)) * C3 + h * HD + sg * 8,
             n < NN ? 16 : 0);
    }
    if (tid < AG * 4) {
        int row = tid >> 2, sg = tid & 3;
        cp16(sAu + (row * SKV + sg * 8) * 2,
             g_agentbf + ((size_t)b * AG + row) * CC + h * HD + sg * 8, 16);
    }
    {
        int row = tid >> 2, sg = tid & 3;
        cp16(sVu + (row * SKV + sg * 8) * 2,
             g_agentv_bf + ((size_t)(b * NH + h) * 64 + row) * HD + sg * 8, 16);
    }
    asm volatile("cp.async.commit_group;\n");
    // group B: v halo tile (only needed in the dwconv epilogue)
    {
        const __nv_bfloat16* vsrc = g_qkv_bf + (size_t)b * NN * C3 + 2 * CC + h * HD;
        for (int c = tid; c < VROWS * 4; c += 256) {
            int row = c >> 2, sg = c & 3;
            int n = n0 - 57 + row;
            int valid = (n >= 0 && n < NN);
            cp16(sVCu + (row * VSTR + sg * 4) * 4,
                 vsrc + (size_t)(valid ? n : 0) * C3 + sg * 8, valid ? 16 : 0);
        }
    }
    asm volatile("cp.async.commit_group;\n");
    asm volatile("cp.async.wait_group 1;\n");
    __syncthreads();

    const int rmA = (lane & 7) + ((lane >> 3) & 1) * 8;
    const int ckA = ((lane >> 4) << 3);
    const int krow = (lane & 7) + ((lane >> 4) & 1) * 8;
    const int koff = ((lane >> 3) & 1) * 8;
    const int rsel = (lane & 7) + ((lane >> 4) << 3);
    const int csel = ((lane >> 3) & 1) * 8;

    float sc[2][8][4];
#pragma unroll
    for (int mt = 0; mt < 2; mt++) {
        int r0 = n0 + wm + mt * 16 + g;
        int r1 = r0 + 8;
        const float* bq0 = g_ab1t + ((size_t)h * NN + (r0 < NN ? r0 : 0)) * 64;
        const float* bq1 = g_ab1t + ((size_t)h * NN + (r1 < NN ? r1 : 0)) * 64;
#pragma unroll
        for (int j = 0; j < 8; j++) {
            float2 v0 = *(const float2*)(bq0 + j * 8 + 2 * t);
            float2 v1 = *(const float2*)(bq1 + j * 8 + 2 * t);
            sc[mt][j][0] = v0.x; sc[mt][j][1] = v0.y;
            sc[mt][j][2] = v1.x; sc[mt][j][3] = v1.y;
        }
    }
#pragma unroll
    for (int kk = 0; kk < 32; kk += 16) {
        uint32_t a[2][4];
#pragma unroll
        for (int mt = 0; mt < 2; mt++)
            ldsm4(a[mt], sQu + ((wm + mt * 16 + rmA) * SAP + kk + ckA) * 2);
#pragma unroll
        for (int jp = 0; jp < 4; jp++) {
            uint32_t bf4[4];
            ldsm4(bf4, sAu + ((jp * 16 + krow) * SKV + kk + koff) * 2);
#pragma unroll
            for (int mt = 0; mt < 2; mt++) {
                mma_bf16(sc[mt][jp * 2],     a[mt], bf4[0], bf4[1]);
                mma_bf16(sc[mt][jp * 2 + 1], a[mt], bf4[2], bf4[3]);
            }
        }
    }
#pragma unroll
    for (int mt = 0; mt < 2; mt++)
#pragma unroll
        for (int j = 0; j < 8; j++) {
            int c0 = j * 8 + 2 * t;
            if (c0 >= AG)     { sc[mt][j][0] = -1e30f; sc[mt][j][2] = -1e30f; }
            if (c0 + 1 >= AG) { sc[mt][j][1] = -1e30f; sc[mt][j][3] = -1e30f; }
        }
#pragma unroll
    for (int mt = 0; mt < 2; mt++) {
        float mx0 = -1e30f, mx1 = -1e30f;
#pragma unroll
        for (int j = 0; j < 8; j++) {
            mx0 = fmaxf(mx0, fmaxf(sc[mt][j][0], sc[mt][j][1]));
            mx1 = fmaxf(mx1, fmaxf(sc[mt][j][2], sc[mt][j][3]));
        }
        mx0 = fmaxf(mx0, __shfl_xor_sync(0xffffffffu, mx0, 1));
        mx0 = fmaxf(mx0, __shfl_xor_sync(0xffffffffu, mx0, 2));
        mx1 = fmaxf(mx1, __shfl_xor_sync(0xffffffffu, mx1, 1));
        mx1 = fmaxf(mx1, __shfl_xor_sync(0xffffffffu, mx1, 2));
        float l0 = 0.f, l1 = 0.f;
#pragma unroll
        for (int j = 0; j < 8; j++) {
            sc[mt][j][0] = __expf(sc[mt][j][0] - mx0); l0 += sc[mt][j][0];
            sc[mt][j][1] = __expf(sc[mt][j][1] - mx0); l0 += sc[mt][j][1];
            sc[mt][j][2] = __expf(sc[mt][j][2] - mx1); l1 += sc[mt][j][2];
            sc[mt][j][3] = __expf(sc[mt][j][3] - mx1); l1 += sc[mt][j][3];
        }
        l0 += __shfl_xor_sync(0xffffffffu, l0, 1);
        l0 += __shfl_xor_sync(0xffffffffu, l0, 2);
        l1 += __shfl_xor_sync(0xffffffffu, l1, 1);
        l1 += __shfl_xor_sync(0xffffffffu, l1, 2);
        float i0 = 1.f / l0, i1 = 1.f / l1;
#pragma unroll
        for (int j = 0; j < 8; j++) {
            sc[mt][j][0] *= i0; sc[mt][j][1] *= i0;
            sc[mt][j][2] *= i1; sc[mt][j][3] *= i1;
        }
    }
    float oacc[2][4][4];
#pragma unroll
    for (int mt = 0; mt < 2; mt++)
#pragma unroll
        for (int j = 0; j < 4; j++)
#pragma unroll
            for (int q = 0; q < 4; q++) oacc[mt][j][q] = 0.f;
#pragma unroll
    for (int kt = 0; kt < 4; kt++) {
        uint32_t vb0[4], vb1[4];
        ldsm4t(vb0, sVu + ((kt * 16 + rsel) * SKV + csel) * 2);
        ldsm4t(vb1, sVu + ((kt * 16 + rsel) * SKV + 16 + csel) * 2);
#pragma unroll
        for (int mt = 0; mt < 2; mt++) {
            uint32_t pf[4];
            pf[0] = packbf(sc[mt][2 * kt][0], sc[mt][2 * kt][1]);
            pf[1] = packbf(sc[mt][2 * kt][2], sc[mt][2 * kt][3]);
            pf[2] = packbf(sc[mt][2 * kt + 1][0], sc[mt][2 * kt + 1][1]);
            pf[3] = packbf(sc[mt][2 * kt + 1][2], sc[mt][2 * kt + 1][3]);
            mma_bf16(oacc[mt][0], pf, vb0[0], vb0[2]);
            mma_bf16(oacc[mt][1], pf, vb0[1], vb0[3]);
            mma_bf16(oacc[mt][2], pf, vb1[0], vb1[2]);
            mma_bf16(oacc[mt][3], pf, vb1[1], vb1[3]);
        }
    }
    asm volatile("cp.async.wait_group 0;\n");
    __syncthreads();
    // dwconv epilogue -> staging tile in sQ (dead after score mma), stride 40
#pragma unroll
    for (int nt = 0; nt < 4; nt++) {
        int c0l = nt * 8 + 2 * t;
        int c0  = h * HD + c0l;
        int cw  = nt * 4 + t;
        float bw0 = __ldg(&dwc_b[c0]), bw1 = __ldg(&dwc_b[c0 + 1]);
        float w0[9], w1[9];
#pragma unroll
        for (int k = 0; k < 9; k++) {
            w0[k] = __ldg(&dwc_w[c0 * 9 + k]);
            w1[k] = __ldg(&dwc_w[(c0 + 1) * 9 + k]);
        }
#pragma unroll
        for (int mt = 0; mt < 2; mt++)
#pragma unroll
            for (int rr = 0; rr < 2; rr++) {
                int rloc = wm + mt * 16 + g + rr * 8;
                int n = n0 + rloc;
                int y = n / WW, x = n % WW;
                float a0 = bw0, a1 = bw1;
#pragma unroll
                for (int ky = 0; ky < 3; ky++) {
                    int yy = y + ky - 1;
                    if (yy < 0 || yy >= HH) continue;
#pragma unroll
                    for (int kx = 0; kx < 3; kx++) {
                        int xx = x + kx - 1;
                        if (xx < 0 || xx >= WW) continue;
                        int tap = (yy * WW + xx) - n0 + 57;
                        uint32_t vw = sVC[tap * VSTR + cw];
                        float2 vf = __bfloat1622float2(*(__nv_bfloat162*)&vw);
                        a0 += vf.x * w0[ky * 3 + kx];
                        a1 += vf.y * w1[ky * 3 + kx];
                    }
                }
                float d0 = oacc[mt][nt][rr * 2] + a0;
                float d1 = oacc[mt][nt][rr * 2 + 1] + a1;
                *(__nv_bfloat162*)&sQ[rloc * SAP + c0l] = __floats2bfloat162_rn(d0, d1);
            }
    }
    __syncthreads();
    // coalesced 16B stores: 256 rows x 32 ch (64 B per row)
#pragma unroll
    for (int k = 0; k < 4; k++) {
        int i = tid + k * 256;
        int r = i >> 2, cs = i & 3;
        int n = n0 + r;
        if (n < NN)
            *(uint4*)&g_omid_bf[((size_t)b * NN + n) * CC + h * HD + cs * 8] =
                *(uint4*)&sQ[r * SAP + cs * 8];
    }
}

// ---------------- kernel 7: proj GEMM via bf16 mma, 2-pass transposed epilogue --
__global__ __launch_bounds__(256) void proj_bf16_kernel(const float* __restrict__ bias,
                                                        const float* __restrict__ x,
                                                        float* __restrict__ out) {
    union Sm {
        struct { __nv_bfloat16 As[2][128 * SAP]; __nv_bfloat16 Bs[2][32 * SB]; } p;
        float tile[128 * 66];   // 33792 B <= 37888 B
    };
    __shared__ Sm sm;
    const int b  = blockIdx.z;
    const int m0 = blockIdx.x * 128;
    const int n0 = blockIdx.y * 128;
    const int tid = threadIdx.x, lane = tid & 31, wid = tid >> 5;
    const int wm = (wid & 1) * 64, wn = (wid >> 1) * 32;
    const int g = lane >> 2, t = lane & 3;

    uint32_t sAu[2], sBu[2];
    sAu[0] = smem_u32(sm.p.As[0]); sAu[1] = smem_u32(sm.p.As[1]);
    sBu[0] = smem_u32(sm.p.Bs[0]); sBu[1] = smem_u32(sm.p.Bs[1]);

    float d[4][4][4];
#pragma unroll
    for (int i = 0; i < 4; i++)
#pragma unroll
        for (int j = 0; j < 4; j++)
#pragma unroll
            for (int q = 0; q < 4; q++) d[i][j][q] = 0.f;

    const __nv_bfloat16* ab = g_omid_bf + ((size_t)b * NN + m0) * CC;

    auto issue = [&](int k0, int buf) {
#pragma unroll
        for (int r = 0; r < 2; r++) {
            int ci = tid + r * 256;
            int rowA = ci >> 2, cA = ci & 3;
            cp16(sAu[buf] + (rowA * SAP + cA * 8) * 2,
                 ab + (size_t)rowA * CC + k0 + cA * 8, (m0 + rowA) < NN ? 16 : 0);
            int rowB = ci >> 4, cB = ci & 15;
            cp16(sBu[buf] + (rowB * SB + cB * 8) * 2,
                 g_projw_bf + (size_t)(k0 + rowB) * CC + n0 + cB * 8, 16);
        }
        asm volatile("cp.async.commit_group;\n");
    };

    issue(0, 0);
    const int rmA = (lane & 7) + ((lane >> 3) & 1) * 8;
    const int ckA = ((lane >> 4) << 3);
    const int rsel = (lane & 7) + ((lane >> 4) << 3);
    const int csel = ((lane >> 3) & 1) * 8;

    for (int s = 0; s < 12; s++) {
        if (s < 11) {
            issue((s + 1) * 32, (s + 1) & 1);
            asm volatile("cp.async.wait_group 1;\n");
        } else {
            asm volatile("cp.async.wait_group 0;\n");
        }
        __syncthreads();
        const uint32_t sa = sAu[s & 1], sb = sBu[s & 1];
#pragma unroll
        for (int kk = 0; kk < 32; kk += 16) {
            uint32_t a[4][4], bfr[2][4];
#pragma unroll
            for (int mt = 0; mt < 4; mt++)
                ldsm4(a[mt], sa + ((wm + mt * 16 + rmA) * SAP + kk + ckA) * 2);
            int rB = kk + rsel;
#pragma unroll
            for (int bt = 0; bt < 2; bt++)
                ldsm4t(bfr[bt], sb + (rB * SB + wn + bt * 16 + csel) * 2);
#pragma unroll
            for (int mt = 0; mt < 4; mt++)
#pragma unroll
                for (int j = 0; j < 4; j++)
                    mma_bf16(d[mt][j], a[mt], bfr[j >> 1][j & 1], bfr[j >> 1][2 + (j & 1)]);
        }
        __syncthreads();
    }

    // 2-pass transposed epilogue: 64 channels per pass
#pragma unroll
    for (int p = 0; p < 2; p++) {
        __syncthreads();
        if ((wid >> 2) == p) {
#pragma unroll
            for (int mt = 0; mt < 4; mt++)
#pragma unroll
                for (int j = 0; j < 4; j++) {
                    int row = wm + mt * 16 + g;
                    int colL = wn - p * 64 + j * 8 + 2 * t;
                    sm.tile[row * 66 + colL]           = d[mt][j][0];
                    sm.tile[row * 66 + colL + 1]       = d[mt][j][1];
                    sm.tile[(row + 8) * 66 + colL]     = d[mt][j][2];
                    sm.tile[(row + 8) * 66 + colL + 1] = d[mt][j][3];
                }
        }
        __syncthreads();
        int colc = tid >> 2;
        int ch = n0 + p * 64 + colc;
        float bvv = __ldg(&bias[ch]);
        size_t obase = ((size_t)b * CC + ch) * NN + m0;
#pragma unroll
        for (int jj = 0; jj < 8; jj++) {
            int m = (tid & 3) * 4 + 16 * jj;
            if (m0 + m + 4 > NN) continue;
            float v0 = sm.tile[(m + 0) * 66 + colc];
            float v1 = sm.tile[(m + 1) * 66 + colc];
            float v2 = sm.tile[(m + 2) * 66 + colc];
            float v3 = sm.tile[(m + 3) * 66 + colc];
            float4 xv = *(const float4*)&x[obase + m];
            float4 o;
            o.x = xv.x / (1.f + __expf(-(v0 + bvv)));
            o.y = xv.y / (1.f + __expf(-(v1 + bvv)));
            o.z = xv.z / (1.f + __expf(-(v2 + bvv)));
            o.w = xv.w / (1.f + __expf(-(v3 + bvv)));
            *(float4*)&out[obase + m] = o;
        }
    }
}

// ---------------- launch -------------------------------------------------------
extern "C" void kernel_launch(void* const* d_in, const int* in_sizes, int n_in,
                              void* d_out, int out_size) {
    const float* x      = (const float*)d_in[0];
    const float* qkv_w  = (const float*)d_in[1];
    const float* qkv_b  = (const float*)d_in[2];
    const float* proj_w = (const float*)d_in[3];
    const float* proj_b = (const float*)d_in[4];
    const float* an     = (const float*)d_in[5];
    const float* na     = (const float*)d_in[6];
    const float* dwc_w  = (const float*)d_in[7];
    const float* dwc_b  = (const float*)d_in[8];
    float* out = (float*)d_out;

    cudaFuncSetAttribute(stage2_mma_kernel,
                         cudaFuncAttributeMaxDynamicSharedMemorySize, S2_TOTAL);

    __nv_bfloat16* xbf; cudaGetSymbolAddress((void**)&xbf, g_x_bf);
    __nv_bfloat16* qwbf; cudaGetSymbolAddress((void**)&qwbf, g_qkvw_bf);
    __nv_bfloat16* pwbf; cudaGetSymbolAddress((void**)&pwbf, g_projw_bf);

    {
        size_t nx = (size_t)BB * CC * NN;
        f2bf_kernel<<<(unsigned)((nx / 4 + 255) / 256), 256>>>(x, xbf, nx);
        size_t nw = (size_t)CC * C3;
        f2bf_kernel<<<(unsigned)((nw / 4 + 255) / 256), 256>>>(qkv_w, qwbf, nw);
        size_t np = (size_t)CC * CC;
        f2bf_kernel<<<(unsigned)((np / 4 + 255) / 256), 256>>>(proj_w, pwbf, np);
    }
    upsample_bias_kernel<<<(NH * AG * NN + 255) / 256, 256>>>(an, na);
    qkv_bf16_kernel<<<dim3((NN + 127) / 128, C3 / 128, BB), 256>>>(qkv_b);
    pool_kernel<<<(BB * AG * CC + 255) / 256, 256>>>();
    stage1_kernel<<<dim3(BB * NH, NSEG), 128>>>();
    stage1_reduce_kernel<<<BB * NH, 256>>>();
    stage2_mma_kernel<<<dim3((NN + S2M - 1) / S2M, NH, BB), 256, S2_TOTAL>>>(dwc_w, dwc_b);
    proj_bf16_kernel<<<dim3((NN + 127) / 128, CC / 128, BB), 256>>>(proj_b, x, out);
}

// round 17
// speedup vs baseline: 1.0922x; 1.0074x over previous
#include <cuda_runtime.h>
#include <cuda_bf16.h>
#include <cstdint>
#include <cstddef>

#define BB 32
#define CC 384
#define C3 1152
#define HH 56
#define WW 56
#define NN 3136
#define NH 12
#define HD 32
#define AG 49
#define NSEG 7
#define SCALE 0.17677669529663687f  // 32^-0.5

#define SA 136   // qkv A smem row stride (bf16)
#define SB 136   // B smem row stride (bf16)
#define SAP 40   // proj/stage2 A smem row stride (bf16)
#define SKV 40   // stage1/2 K/V smem row stride (bf16)

// stage2 BM=256 tile
#define S2M 256
#define VROWS 372   // 256 + 2*57 halo, padded
#define VSTR 20     // v tile row stride in 32-bit words
// dynamic smem offsets (bytes)
#define S2_Q 0
#define S2_A (S2_Q + S2M * SAP * 2)        // 20480
#define S2_V (S2_A + 64 * SKV * 2)         // 25600
#define S2_VC (S2_V + 64 * SKV * 2)        // 30720
#define S2_TOTAL (S2_VC + VROWS * VSTR * 4) // 60480

// combined prep kernel block partitions (256 threads each, exact divisions)
#define PREP_X  37632   // f2bf x: 38535168/4/256
#define PREP_W  432     // f2bf qkv_w: 442368/4/256
#define PREP_PW 144     // f2bf proj_w: 147456/4/256
#define PREP_UP 7203    // upsample: 1843968/256
#define PREP_TOTAL (PREP_X + PREP_W + PREP_PW + PREP_UP)

// ---------------- scratch (device globals; no allocation allowed) ----------------
__device__ __nv_bfloat16 g_qkv_bf[(size_t)BB * NN * C3];   // [b][n][3c] bf16
__device__ __nv_bfloat16 g_agentbf[(size_t)BB * AG * CC];  // agents * SCALE, bf16
__device__ float g_pb1[(size_t)NH * AG * NN];              // stage1 bias [h][a][n]
__device__ float g_ab1t[(size_t)NH * NN * 64];             // stage2 bias [h][n][64pad]
__device__ __nv_bfloat16 g_agentv_bf[(size_t)BB * NH * 64 * HD]; // [b][h][64pad][d]
__device__ __nv_bfloat16 g_x_bf[(size_t)BB * CC * NN];     // bf16 copy of x
__device__ __nv_bfloat16 g_qkvw_bf[(size_t)CC * C3];
__device__ __nv_bfloat16 g_projw_bf[(size_t)CC * CC];
__device__ __nv_bfloat16 g_omid_bf[(size_t)BB * NN * CC];  // attn out + dwconv
// stage-1 split-K partials
__device__ float g_s1m[(size_t)BB * NH * NSEG * AG];
__device__ float g_s1l[(size_t)BB * NH * NSEG * AG];
__device__ float g_s1acc[(size_t)BB * NH * NSEG * AG * HD];

// ---------------- asm helpers ---------------------------------------------------
__device__ __forceinline__ void cp16(uint32_t dst, const void* src, int sz) {
    asm volatile("cp.async.cg.shared.global [%0], [%1], 16, %2;\n"
                 :: "r"(dst), "l"(src), "r"(sz));
}
__device__ __forceinline__ void ldsm4t(uint32_t* r, uint32_t addr) {
    asm volatile("ldmatrix.sync.aligned.m8n8.x4.trans.shared.b16 {%0,%1,%2,%3}, [%4];\n"
                 : "=r"(r[0]), "=r"(r[1]), "=r"(r[2]), "=r"(r[3]) : "r"(addr));
}
__device__ __forceinline__ void ldsm4(uint32_t* r, uint32_t addr) {
    asm volatile("ldmatrix.sync.aligned.m8n8.x4.shared.b16 {%0,%1,%2,%3}, [%4];\n"
                 : "=r"(r[0]), "=r"(r[1]), "=r"(r[2]), "=r"(r[3]) : "r"(addr));
}
__device__ __forceinline__ void mma_bf16(float* d, const uint32_t* a,
                                         uint32_t b0, uint32_t b1) {
    asm volatile(
        "mma.sync.aligned.m16n8k16.row.col.f32.bf16.bf16.f32 "
        "{%0,%1,%2,%3}, {%4,%5,%6,%7}, {%8,%9}, {%0,%1,%2,%3};\n"
        : "+f"(d[0]), "+f"(d[1]), "+f"(d[2]), "+f"(d[3])
        : "r"(a[0]), "r"(a[1]), "r"(a[2]), "r"(a[3]), "r"(b0), "r"(b1));
}
__device__ __forceinline__ uint32_t packbf(float x, float y) {
    __nv_bfloat162 h = __floats2bfloat162_rn(x, y);
    return *(uint32_t*)&h;
}
__device__ __forceinline__ uint32_t smem_u32(const void* p) {
    return (uint32_t)__cvta_generic_to_shared(p);
}

// ---------------- kernel 0: combined independent preprocessing ------------------
// partitions: [0,PREP_X) f2bf(x) | [..,+PREP_W) f2bf(qkv_w) | [..,+PREP_PW)
// f2bf(proj_w) | [..,+PREP_UP) bias upsample. All mutually independent.
__global__ __launch_bounds__(256) void prep_kernel(const float* __restrict__ x,
                                                   const float* __restrict__ qkv_w,
                                                   const float* __restrict__ proj_w,
                                                   const float* __restrict__ an,
                                                   const float* __restrict__ na) {
    int blk = blockIdx.x;
    if (blk < PREP_X + PREP_W + PREP_PW) {
        const float* s;
        __nv_bfloat16* d;
        size_t i;
        if (blk < PREP_X) {
            s = x; d = g_x_bf;
            i = ((size_t)blk * 256 + threadIdx.x) * 4;
        } else if (blk < PREP_X + PREP_W) {
            s = qkv_w; d = g_qkvw_bf;
            i = ((size_t)(blk - PREP_X) * 256 + threadIdx.x) * 4;
        } else {
            s = proj_w; d = g_projw_bf;
            i = ((size_t)(blk - PREP_X - PREP_W) * 256 + threadIdx.x) * 4;
        }
        float4 v = *(const float4*)(s + i);
        *(__nv_bfloat162*)(d + i)     = __floats2bfloat162_rn(v.x, v.y);
        *(__nv_bfloat162*)(d + i + 2) = __floats2bfloat162_rn(v.z, v.w);
        return;
    }
    // bias upsample partition
    int idx = (blk - PREP_X - PREP_W - PREP_PW) * 256 + threadIdx.x;
    int n  = idx % NN;
    int ha = idx / NN;
    int h  = ha / AG, a = ha % AG;
    int xx0 = n % WW, yy0 = n / WW;

    float fy = (yy0 + 0.5f) * 0.125f - 0.5f;
    float fx = (xx0 + 0.5f) * 0.125f - 0.5f;
    int y0 = (int)floorf(fy), x0 = (int)floorf(fx);
    float wy = fy - (float)y0, wx = fx - (float)x0;
    int iy0 = min(max(y0, 0), 6), iy1 = min(max(y0 + 1, 0), 6);
    int ix0 = min(max(x0, 0), 6), ix1 = min(max(x0 + 1, 0), 6);
    float w00 = (1.f - wy) * (1.f - wx), w01 = (1.f - wy) * wx;
    float w10 = wy * (1.f - wx),         w11 = wy * wx;

    const float* a_base = an + (size_t)ha * 49;
    const float* n_base = na + (size_t)ha * 49;
    g_pb1[idx] = w00 * a_base[iy0 * 7 + ix0] + w01 * a_base[iy0 * 7 + ix1]
               + w10 * a_base[iy1 * 7 + ix0] + w11 * a_base[iy1 * 7 + ix1];
    float nb = w00 * n_base[iy0 * 7 + ix0] + w01 * n_base[iy0 * 7 + ix1]
             + w10 * n_base[iy1 * 7 + ix0] + w11 * n_base[iy1 * 7 + ix1];
    g_ab1t[((size_t)h * NN + n) * 64 + a] = nb;
}

// ---------------- kernel 2: qkv GEMM via bf16 mma, coalesced epilogue -----------
__global__ __launch_bounds__(256) void qkv_bf16_kernel(const float* __restrict__ bias) {
    union QSm {
        struct { __nv_bfloat16 As[2][32 * SA]; __nv_bfloat16 Bs[2][32 * SB]; } p;
        __nv_bfloat16 tile[128 * 136];   // 34816 B, same size as As+Bs
    };
    __shared__ QSm sm;
    const int b  = blockIdx.z;
    const int m0 = blockIdx.x * 128;
    const int n0 = blockIdx.y * 128;
    const int tid = threadIdx.x, lane = tid & 31, wid = tid >> 5;
    const int wm = (wid & 1) * 64, wn = (wid >> 1) * 32;
    const int g = lane >> 2, t = lane & 3;
    const __nv_bfloat16* xb = g_x_bf + (size_t)b * CC * NN;

    uint32_t sAu[2], sBu[2];
    sAu[0] = smem_u32(sm.p.As[0]); sAu[1] = smem_u32(sm.p.As[1]);
    sBu[0] = smem_u32(sm.p.Bs[0]); sBu[1] = smem_u32(sm.p.Bs[1]);

    float d[4][4][4];
#pragma unroll
    for (int i = 0; i < 4; i++)
#pragma unroll
        for (int j = 0; j < 4; j++)
#pragma unroll
            for (int q = 0; q < 4; q++) d[i][j][q] = 0.f;

    auto issue = [&](int k0, int buf) {
#pragma unroll
        for (int r = 0; r < 2; r++) {
            int ci = tid + r * 256;
            int row = ci >> 4, c = ci & 15;
            int mcol = m0 + c * 8;
            cp16(sAu[buf] + (row * SA + c * 8) * 2,
                 xb + (size_t)(k0 + row) * NN + mcol, mcol < NN ? 16 : 0);
            cp16(sBu[buf] + (row * SB + c * 8) * 2,
                 g_qkvw_bf + (size_t)(k0 + row) * C3 + n0 + c * 8, 16);
        }
        asm volatile("cp.async.commit_group;\n");
    };

    issue(0, 0);
    const int rsel = (lane & 7) + ((lane >> 4) << 3);
    const int csel = ((lane >> 3) & 1) * 8;

    for (int s = 0; s < 12; s++) {
        if (s < 11) {
            issue((s + 1) * 32, (s + 1) & 1);
            asm volatile("cp.async.wait_group 1;\n");
        } else {
            asm volatile("cp.async.wait_group 0;\n");
        }
        __syncthreads();
        const uint32_t sa = sAu[s & 1], sb = sBu[s & 1];
#pragma unroll
        for (int kk = 0; kk < 32; kk += 16) {
            uint32_t a[4][4], bfr[2][4];
            int rA = kk + rsel;
#pragma unroll
            for (int mt = 0; mt < 4; mt++)
                ldsm4t(a[mt], sa + (rA * SA + wm + mt * 16 + csel) * 2);
#pragma unroll
            for (int bt = 0; bt < 2; bt++)
                ldsm4t(bfr[bt], sb + (rA * SB + wn + bt * 16 + csel) * 2);
#pragma unroll
            for (int mt = 0; mt < 4; mt++)
#pragma unroll
                for (int j = 0; j < 4; j++)
                    mma_bf16(d[mt][j], a[mt], bfr[j >> 1][j & 1], bfr[j >> 1][2 + (j & 1)]);
        }
        __syncthreads();
    }

    // epilogue: bias add into fragments -> smem tile -> coalesced 16B stores
#pragma unroll
    for (int mt = 0; mt < 4; mt++)
#pragma unroll
        for (int j = 0; j < 4; j++) {
            int row = wm + mt * 16 + g;
            int col = wn + j * 8 + 2 * t;
            float bv0 = __ldg(&bias[n0 + col]), bv1 = __ldg(&bias[n0 + col + 1]);
            *(__nv_bfloat162*)&sm.tile[row * 136 + col] =
                __floats2bfloat162_rn(d[mt][j][0] + bv0, d[mt][j][1] + bv1);
            *(__nv_bfloat162*)&sm.tile[(row + 8) * 136 + col] =
                __floats2bfloat162_rn(d[mt][j][2] + bv0, d[mt][j][3] + bv1);
        }
    __syncthreads();
#pragma unroll
    for (int r = 0; r < 8; r++) {
        int i = tid + r * 256;
        int row = i >> 4, cs = i & 15;
        int m = m0 + row;
        if (m < NN)
            *(uint4*)&g_qkv_bf[((size_t)b * NN + m) * C3 + n0 + cs * 8] =
                *(uint4*)&sm.tile[row * 136 + cs * 8];
    }
}

// ---------------- kernel 3: agent pooling -> scaled bf16 agents -----------------
__global__ void pool_kernel() {
    int idx = blockIdx.x * 256 + threadIdx.x;
    const int total = BB * AG * CC;
    if (idx >= total) return;
    int c = idx % CC;
    int a = (idx / CC) % AG;
    int b = idx / (CC * AG);
    int py = a / 7, px = a % 7;
    const __nv_bfloat16* q = g_qkv_bf + (size_t)b * NN * C3 + c;
    float s = 0.f;
#pragma unroll
    for (int dy = 0; dy < 8; dy++) {
        int row = (py * 8 + dy) * WW + px * 8;
#pragma unroll
        for (int dx = 0; dx < 8; dx++)
            s += __bfloat162float(q[(size_t)(row + dx) * C3]);
    }
    g_agentbf[idx] = __float2bfloat16_rn(s * 0.015625f * SCALE);
}

// ---------------- kernel 4: stage-1 agent attention via bf16 mma (split-K) ------
__global__ __launch_bounds__(128) void stage1_kernel() {
    __shared__ __nv_bfloat16 sK[2][64 * SKV];
    __shared__ __nv_bfloat16 sV[2][64 * SKV];

    const int tid = threadIdx.x, lane = tid & 31, warp = tid >> 5;
    const int bh = blockIdx.x, seg = blockIdx.y;
    const int b = bh / NH, h = bh % NH;
    const int g = lane >> 2, t = lane & 3;
    const int a_row0 = warp * 16 + g, a_row1 = a_row0 + 8;

    uint32_t skU[2], svU[2];
    skU[0] = smem_u32(sK[0]); skU[1] = smem_u32(sK[1]);
    svU[0] = smem_u32(sV[0]); svU[1] = smem_u32(sV[1]);

    uint32_t afrag[2][4];
    const __nv_bfloat16* agb = g_agentbf + (size_t)b * AG * CC + h * HD;
#pragma unroll
    for (int kt = 0; kt < 2; kt++) {
        int kb = kt * 16 + 2 * t;
        afrag[kt][0] = (a_row0 < AG) ? *(const uint32_t*)(agb + (size_t)a_row0 * CC + kb) : 0u;
        afrag[kt][1] = (a_row1 < AG) ? *(const uint32_t*)(agb + (size_t)a_row1 * CC + kb) : 0u;
        afrag[kt][2] = (a_row0 < AG) ? *(const uint32_t*)(agb + (size_t)a_row0 * CC + kb + 8) : 0u;
        afrag[kt][3] = (a_row1 < AG) ? *(const uint32_t*)(agb + (size_t)a_row1 * CC + kb + 8) : 0u;
    }

    float oacc[4][4];
#pragma unroll
    for (int i = 0; i < 4; i++)
#pragma unroll
        for (int j = 0; j < 4; j++) oacc[i][j] = 0.f;
    float rm0 = -1e30f, rm1 = -1e30f, rl0 = 0.f, rl1 = 0.f;

    const int krow = (lane & 7) + ((lane >> 4) & 1) * 8;
    const int koff = ((lane >> 3) & 1) * 8;
    const int rsel = (lane & 7) + ((lane >> 4) << 3);
    const int csel = ((lane >> 3) & 1) * 8;

    auto issue = [&](int chunk, int buf) {
        int n0 = chunk * 64;
#pragma unroll
        for (int r = 0; r < 2; r++) {
            int c = tid + r * 128;
            int row = c >> 2, sg = c & 3;
            const __nv_bfloat16* gk = g_qkv_bf
                + ((size_t)b * NN + n0 + row) * C3 + CC + h * HD + sg * 8;
            cp16(skU[buf] + (row * SKV + sg * 8) * 2, gk, 16);
            cp16(svU[buf] + (row * SKV + sg * 8) * 2, gk + CC, 16);
        }
        asm volatile("cp.async.commit_group;\n");
    };

    const float* bp0 = g_pb1 + ((size_t)h * AG + (a_row0 < AG ? a_row0 : 0)) * NN;
    const float* bp1 = g_pb1 + ((size_t)h * AG + (a_row1 < AG ? a_row1 : 0)) * NN;

    issue(seg * 7, 0);
    for (int ci = 0; ci < 7; ci++) {
        if (ci < 6) {
            issue(seg * 7 + ci + 1, (ci + 1) & 1);
            asm volatile("cp.async.wait_group 1;\n");
        } else {
            asm volatile("cp.async.wait_group 0;\n");
        }
        __syncthreads();
        const uint32_t sk = skU[ci & 1], sv = svU[ci & 1];
        const int n0 = (seg * 7 + ci) * 64;

        float sc[8][4];
#pragma unroll
        for (int j = 0; j < 8; j++) {
            float2 b0 = (a_row0 < AG) ? *(const float2*)(bp0 + n0 + j * 8 + 2 * t)
                                      : make_float2(0.f, 0.f);
            float2 b1 = (a_row1 < AG) ? *(const float2*)(bp1 + n0 + j * 8 + 2 * t)
                                      : make_float2(0.f, 0.f);
            sc[j][0] = b0.x; sc[j][1] = b0.y; sc[j][2] = b1.x; sc[j][3] = b1.y;
        }
#pragma unroll
        for (int jp = 0; jp < 4; jp++) {
            uint32_t kf0[4], kf1[4];
            ldsm4(kf0, sk + ((jp * 16 + krow) * SKV + koff) * 2);
            ldsm4(kf1, sk + ((jp * 16 + krow) * SKV + 16 + koff) * 2);
            mma_bf16(sc[jp * 2],     afrag[0], kf0[0], kf0[1]);
            mma_bf16(sc[jp * 2],     afrag[1], kf1[0], kf1[1]);
            mma_bf16(sc[jp * 2 + 1], afrag[0], kf0[2], kf0[3]);
            mma_bf16(sc[jp * 2 + 1], afrag[1], kf1[2], kf1[3]);
        }
        float mx0 = sc[0][0], mx1 = sc[0][2];
#pragma unroll
        for (int j = 0; j < 8; j++) {
            mx0 = fmaxf(mx0, fmaxf(sc[j][0], sc[j][1]));
            mx1 = fmaxf(mx1, fmaxf(sc[j][2], sc[j][3]));
        }
        mx0 = fmaxf(mx0, __shfl_xor_sync(0xffffffffu, mx0, 1));
        mx0 = fmaxf(mx0, __shfl_xor_sync(0xffffffffu, mx0, 2));
        mx1 = fmaxf(mx1, __shfl_xor_sync(0xffffffffu, mx1, 1));
        mx1 = fmaxf(mx1, __shfl_xor_sync(0xffffffffu, mx1, 2));
        float nm0 = fmaxf(rm0, mx0), nm1 = fmaxf(rm1, mx1);
        float corr0 = __expf(rm0 - nm0), corr1 = __expf(rm1 - nm1);
        float ls0 = 0.f, ls1 = 0.f;
#pragma unroll
        for (int j = 0; j < 8; j++) {
            sc[j][0] = __expf(sc[j][0] - nm0); ls0 += sc[j][0];
            sc[j][1] = __expf(sc[j][1] - nm0); ls0 += sc[j][1];
            sc[j][2] = __expf(sc[j][2] - nm1); ls1 += sc[j][2];
            sc[j][3] = __expf(sc[j][3] - nm1); ls1 += sc[j][3];
        }
        ls0 += __shfl_xor_sync(0xffffffffu, ls0, 1);
        ls0 += __shfl_xor_sync(0xffffffffu, ls0, 2);
        ls1 += __shfl_xor_sync(0xffffffffu, ls1, 1);
        ls1 += __shfl_xor_sync(0xffffffffu, ls1, 2);
        rl0 = rl0 * corr0 + ls0;
        rl1 = rl1 * corr1 + ls1;
        rm0 = nm0; rm1 = nm1;
#pragma unroll
        for (int nt = 0; nt < 4; nt++) {
            oacc[nt][0] *= corr0; oacc[nt][1] *= corr0;
            oacc[nt][2] *= corr1; oacc[nt][3] *= corr1;
        }
#pragma unroll
        for (int kt = 0; kt < 4; kt++) {
            uint32_t pf[4];
            pf[0] = packbf(sc[2 * kt][0], sc[2 * kt][1]);
            pf[1] = packbf(sc[2 * kt][2], sc[2 * kt][3]);
            pf[2] = packbf(sc[2 * kt + 1][0], sc[2 * kt + 1][1]);
            pf[3] = packbf(sc[2 * kt + 1][2], sc[2 * kt + 1][3]);
            uint32_t vb0[4], vb1[4];
            ldsm4t(vb0, sv + ((kt * 16 + rsel) * SKV + csel) * 2);
            ldsm4t(vb1, sv + ((kt * 16 + rsel) * SKV + 16 + csel) * 2);
            mma_bf16(oacc[0], pf, vb0[0], vb0[2]);
            mma_bf16(oacc[1], pf, vb0[1], vb0[3]);
            mma_bf16(oacc[2], pf, vb1[0], vb1[2]);
            mma_bf16(oacc[3], pf, vb1[1], vb1[3]);
        }
        __syncthreads();
    }

    const size_t base = ((size_t)bh * NSEG + seg) * AG;
#pragma unroll
    for (int nt = 0; nt < 4; nt++) {
        if (a_row0 < AG)
            *(float2*)&g_s1acc[(base + a_row0) * HD + nt * 8 + 2 * t] =
                make_float2(oacc[nt][0], oacc[nt][1]);
        if (a_row1 < AG)
            *(float2*)&g_s1acc[(base + a_row1) * HD + nt * 8 + 2 * t] =
                make_float2(oacc[nt][2], oacc[nt][3]);
    }
    if (t == 0) {
        if (a_row0 < AG) { g_s1m[base + a_row0] = rm0; g_s1l[base + a_row0] = rl0; }
        if (a_row1 < AG) { g_s1m[base + a_row1] = rm1; g_s1l[base + a_row1] = rl1; }
    }
}

// ---------------- kernel 4b: combine split-K partials -> bf16 agent_v -----------
__global__ __launch_bounds__(256) void stage1_reduce_kernel() {
    __shared__ float sW[NSEG][AG];
    __shared__ float sLs[AG];
    const int bh = blockIdx.x;
    const int tid = threadIdx.x;
    const size_t base = (size_t)bh * NSEG * AG;
    if (tid < AG) {
        float M = -1e30f;
#pragma unroll
        for (int s = 0; s < NSEG; s++)
            M = fmaxf(M, g_s1m[base + s * AG + tid]);
        float ls = 0.f;
#pragma unroll
        for (int s = 0; s < NSEG; s++) {
            float wv = __expf(g_s1m[base + s * AG + tid] - M);
            sW[s][tid] = wv;
            ls += wv * g_s1l[base + s * AG + tid];
        }
        sLs[tid] = ls;
    }
    __syncthreads();
    for (int i = tid; i < 64 * HD; i += 256) {
        int a = i >> 5, dd = i & 31;
        float r = 0.f;
        if (a < AG) {
            float acc = 0.f;
#pragma unroll
            for (int s = 0; s < NSEG; s++)
                acc += sW[s][a] * g_s1acc[(base + s * AG + a) * HD + dd];
            r = acc / sLs[a];
        }
        g_agentv_bf[(size_t)bh * 64 * HD + i] = __float2bfloat16_rn(r);
    }
}

// ---------------- kernel 5: stage-2 BM=256, staged coalesced output -------------
__global__ __launch_bounds__(256) void stage2_mma_kernel(const float* __restrict__ dwc_w,
                                                         const float* __restrict__ dwc_b) {
    extern __shared__ char dsm[];
    __nv_bfloat16* sQ = (__nv_bfloat16*)(dsm + S2_Q);
    __nv_bfloat16* sA = (__nv_bfloat16*)(dsm + S2_A);
    __nv_bfloat16* sV = (__nv_bfloat16*)(dsm + S2_V);
    uint32_t* sVC = (uint32_t*)(dsm + S2_VC);

    const int b = blockIdx.z, h = blockIdx.y, n0 = blockIdx.x * S2M;
    const int tid = threadIdx.x, lane = tid & 31, warp = tid >> 5;
    const int g = lane >> 2, t = lane & 3;
    const int wm = warp * 32;

    uint32_t sQu = smem_u32(sQ);
    uint32_t sAu = smem_u32(sA);
    uint32_t sVu = smem_u32(sV);
    uint32_t sVCu = smem_u32(sVC);

    // group A: q tile, agents, agent_v (needed for attention compute)
#pragma unroll
    for (int r = 0; r < 4; r++) {
        int c = tid + r * 256;
        int row = c >> 2, sg = c & 3;
        int n = n0 + row;
        cp16(sQu + (row * SAP + sg * 8) * 2,
             g_qkv_bf + ((size_t)b * NN + (n < NN ? n : 0)) * C3 + h * HD + sg * 8,
             n < NN ? 16 : 0);
    }
    if (tid < AG * 4) {
        int row = tid >> 2, sg = tid & 3;
        cp16(sAu + (row * SKV + sg * 8) * 2,
             g_agentbf + ((size_t)b * AG + row) * CC + h * HD + sg * 8, 16);
    }
    {
        int row = tid >> 2, sg = tid & 3;
        cp16(sVu + (row * SKV + sg * 8) * 2,
             g_agentv_bf + ((size_t)(b * NH + h) * 64 + row) * HD + sg * 8, 16);
    }
    asm volatile("cp.async.commit_group;\n");
    // group B: v halo tile (only needed in the dwconv epilogue)
    {
        const __nv_bfloat16* vsrc = g_qkv_bf + (size_t)b * NN * C3 + 2 * CC + h * HD;
        for (int c = tid; c < VROWS * 4; c += 256) {
            int row = c >> 2, sg = c & 3;
            int n = n0 - 57 + row;
            int valid = (n >= 0 && n < NN);
            cp16(sVCu + (row * VSTR + sg * 4) * 4,
                 vsrc + (size_t)(valid ? n : 0) * C3 + sg * 8, valid ? 16 : 0);
        }
    }
    asm volatile("cp.async.commit_group;\n");
    asm volatile("cp.async.wait_group 1;\n");
    __syncthreads();

    const int rmA = (lane & 7) + ((lane >> 3) & 1) * 8;
    const int ckA = ((lane >> 4) << 3);
    const int krow = (lane & 7) + ((lane >> 4) & 1) * 8;
    const int koff = ((lane >> 3) & 1) * 8;
    const int rsel = (lane & 7) + ((lane >> 4) << 3);
    const int csel = ((lane >> 3) & 1) * 8;

    float sc[2][8][4];
#pragma unroll
    for (int mt = 0; mt < 2; mt++) {
        int r0 = n0 + wm + mt * 16 + g;
        int r1 = r0 + 8;
        const float* bq0 = g_ab1t + ((size_t)h * NN + (r0 < NN ? r0 : 0)) * 64;
        const float* bq1 = g_ab1t + ((size_t)h * NN + (r1 < NN ? r1 : 0)) * 64;
#pragma unroll
        for (int j = 0; j < 8; j++) {
            float2 v0 = *(const float2*)(bq0 + j * 8 + 2 * t);
            float2 v1 = *(const float2*)(bq1 + j * 8 + 2 * t);
            sc[mt][j][0] = v0.x; sc[mt][j][1] = v0.y;
            sc[mt][j][2] = v1.x; sc[mt][j][3] = v1.y;
        }
    }
#pragma unroll
    for (int kk = 0; kk < 32; kk += 16) {
        uint32_t a[2][4];
#pragma unroll
        for (int mt = 0; mt < 2; mt++)
            ldsm4(a[mt], sQu + ((wm + mt * 16 + rmA) * SAP + kk + ckA) * 2);
#pragma unroll
        for (int jp = 0; jp < 4; jp++) {
            uint32_t bf4[4];
            ldsm4(bf4, sAu + ((jp * 16 + krow) * SKV + kk + koff) * 2);
#pragma unroll
            for (int mt = 0; mt < 2; mt++) {
                mma_bf16(sc[mt][jp * 2],     a[mt], bf4[0], bf4[1]);
                mma_bf16(sc[mt][jp * 2 + 1], a[mt], bf4[2], bf4[3]);
            }
        }
    }
#pragma unroll
    for (int mt = 0; mt < 2; mt++)
#pragma unroll
        for (int j = 0; j < 8; j++) {
            int c0 = j * 8 + 2 * t;
            if (c0 >= AG)     { sc[mt][j][0] = -1e30f; sc[mt][j][2] = -1e30f; }
            if (c0 + 1 >= AG) { sc[mt][j][1] = -1e30f; sc[mt][j][3] = -1e30f; }
        }
#pragma unroll
    for (int mt = 0; mt < 2; mt++) {
        float mx0 = -1e30f, mx1 = -1e30f;
#pragma unroll
        for (int j = 0; j < 8; j++) {
            mx0 = fmaxf(mx0, fmaxf(sc[mt][j][0], sc[mt][j][1]));
            mx1 = fmaxf(mx1, fmaxf(sc[mt][j][2], sc[mt][j][3]));
        }
        mx0 = fmaxf(mx0, __shfl_xor_sync(0xffffffffu, mx0, 1));
        mx0 = fmaxf(mx0, __shfl_xor_sync(0xffffffffu, mx0, 2));
        mx1 = fmaxf(mx1, __shfl_xor_sync(0xffffffffu, mx1, 1));
        mx1 = fmaxf(mx1, __shfl_xor_sync(0xffffffffu, mx1, 2));
        float l0 = 0.f, l1 = 0.f;
#pragma unroll
        for (int j = 0; j < 8; j++) {
            sc[mt][j][0] = __expf(sc[mt][j][0] - mx0); l0 += sc[mt][j][0];
            sc[mt][j][1] = __expf(sc[mt][j][1] - mx0); l0 += sc[mt][j][1];
            sc[mt][j][2] = __expf(sc[mt][j][2] - mx1); l1 += sc[mt][j][2];
            sc[mt][j][3] = __expf(sc[mt][j][3] - mx1); l1 += sc[mt][j][3];
        }
        l0 += __shfl_xor_sync(0xffffffffu, l0, 1);
        l0 += __shfl_xor_sync(0xffffffffu, l0, 2);
        l1 += __shfl_xor_sync(0xffffffffu, l1, 1);
        l1 += __shfl_xor_sync(0xffffffffu, l1, 2);
        float i0 = 1.f / l0, i1 = 1.f / l1;
#pragma unroll
        for (int j = 0; j < 8; j++) {
            sc[mt][j][0] *= i0; sc[mt][j][1] *= i0;
            sc[mt][j][2] *= i1; sc[mt][j][3] *= i1;
        }
    }
    float oacc[2][4][4];
#pragma unroll
    for (int mt = 0; mt < 2; mt++)
#pragma unroll
        for (int j = 0; j < 4; j++)
#pragma unroll
            for (int q = 0; q < 4; q++) oacc[mt][j][q] = 0.f;
#pragma unroll
    for (int kt = 0; kt < 4; kt++) {
        uint32_t vb0[4], vb1[4];
        ldsm4t(vb0, sVu + ((kt * 16 + rsel) * SKV + csel) * 2);
        ldsm4t(vb1, sVu + ((kt * 16 + rsel) * SKV + 16 + csel) * 2);
#pragma unroll
        for (int mt = 0; mt < 2; mt++) {
            uint32_t pf[4];
            pf[0] = packbf(sc[mt][2 * kt][0], sc[mt][2 * kt][1]);
            pf[1] = packbf(sc[mt][2 * kt][2], sc[mt][2 * kt][3]);
            pf[2] = packbf(sc[mt][2 * kt + 1][0], sc[mt][2 * kt + 1][1]);
            pf[3] = packbf(sc[mt][2 * kt + 1][2], sc[mt][2 * kt + 1][3]);
            mma_bf16(oacc[mt][0], pf, vb0[0], vb0[2]);
            mma_bf16(oacc[mt][1], pf, vb0[1], vb0[3]);
            mma_bf16(oacc[mt][2], pf, vb1[0], vb1[2]);
            mma_bf16(oacc[mt][3], pf, vb1[1], vb1[3]);
        }
    }
    asm volatile("cp.async.wait_group 0;\n");
    __syncthreads();
    // dwconv epilogue -> staging tile in sQ (dead after score mma), stride 40
#pragma unroll
    for (int nt = 0; nt < 4; nt++) {
        int c0l = nt * 8 + 2 * t;
        int c0  = h * HD + c0l;
        int cw  = nt * 4 + t;
        float bw0 = __ldg(&dwc_b[c0]), bw1 = __ldg(&dwc_b[c0 + 1]);
        float w0[9], w1[9];
#pragma unroll
        for (int k = 0; k < 9; k++) {
            w0[k] = __ldg(&dwc_w[c0 * 9 + k]);
            w1[k] = __ldg(&dwc_w[(c0 + 1) * 9 + k]);
        }
#pragma unroll
        for (int mt = 0; mt < 2; mt++)
#pragma unroll
            for (int rr = 0; rr < 2; rr++) {
                int rloc = wm + mt * 16 + g + rr * 8;
                int n = n0 + rloc;
                int y = n / WW, x = n % WW;
                float a0 = bw0, a1 = bw1;
#pragma unroll
                for (int ky = 0; ky < 3; ky++) {
                    int yy = y + ky - 1;
                    if (yy < 0 || yy >= HH) continue;
#pragma unroll
                    for (int kx = 0; kx < 3; kx++) {
                        int xx = x + kx - 1;
                        if (xx < 0 || xx >= WW) continue;
                        int tap = (yy * WW + xx) - n0 + 57;
                        uint32_t vw = sVC[tap * VSTR + cw];
                        float2 vf = __bfloat1622float2(*(__nv_bfloat162*)&vw);
                        a0 += vf.x * w0[ky * 3 + kx];
                        a1 += vf.y * w1[ky * 3 + kx];
                    }
                }
                float d0 = oacc[mt][nt][rr * 2] + a0;
                float d1 = oacc[mt][nt][rr * 2 + 1] + a1;
                *(__nv_bfloat162*)&sQ[rloc * SAP + c0l] = __floats2bfloat162_rn(d0, d1);
            }
    }
    __syncthreads();
    // coalesced 16B stores: 256 rows x 32 ch (64 B per row)
#pragma unroll
    for (int k = 0; k < 4; k++) {
        int i = tid + k * 256;
        int r = i >> 2, cs = i & 3;
        int n = n0 + r;
        if (n < NN)
            *(uint4*)&g_omid_bf[((size_t)b * NN + n) * CC + h * HD + cs * 8] =
                *(uint4*)&sQ[r * SAP + cs * 8];
    }
}

// ---------------- kernel 7: proj GEMM via bf16 mma, 2-pass transposed epilogue --
__global__ __launch_bounds__(256) void proj_bf16_kernel(const float* __restrict__ bias,
                                                        const float* __restrict__ x,
                                                        float* __restrict__ out) {
    union Sm {
        struct { __nv_bfloat16 As[2][128 * SAP]; __nv_bfloat16 Bs[2][32 * SB]; } p;
        float tile[128 * 66];   // 33792 B <= 37888 B
    };
    __shared__ Sm sm;
    const int b  = blockIdx.z;
    const int m0 = blockIdx.x * 128;
    const int n0 = blockIdx.y * 128;
    const int tid = threadIdx.x, lane = tid & 31, wid = tid >> 5;
    const int wm = (wid & 1) * 64, wn = (wid >> 1) * 32;
    const int g = lane >> 2, t = lane & 3;

    uint32_t sAu[2], sBu[2];
    sAu[0] = smem_u32(sm.p.As[0]); sAu[1] = smem_u32(sm.p.As[1]);
    sBu[0] = smem_u32(sm.p.Bs[0]); sBu[1] = smem_u32(sm.p.Bs[1]);

    float d[4][4][4];
#pragma unroll
    for (int i = 0; i < 4; i++)
#pragma unroll
        for (int j = 0; j < 4; j++)
#pragma unroll
            for (int q = 0; q < 4; q++) d[i][j][q] = 0.f;

    const __nv_bfloat16* ab = g_omid_bf + ((size_t)b * NN + m0) * CC;

    auto issue = [&](int k0, int buf) {
#pragma unroll
        for (int r = 0; r < 2; r++) {
            int ci = tid + r * 256;
            int rowA = ci >> 2, cA = ci & 3;
            cp16(sAu[buf] + (rowA * SAP + cA * 8) * 2,
                 ab + (size_t)rowA * CC + k0 + cA * 8, (m0 + rowA) < NN ? 16 : 0);
            int rowB = ci >> 4, cB = ci & 15;
            cp16(sBu[buf] + (rowB * SB + cB * 8) * 2,
                 g_projw_bf + (size_t)(k0 + rowB) * CC + n0 + cB * 8, 16);
        }
        asm volatile("cp.async.commit_group;\n");
    };

    issue(0, 0);
    const int rmA = (lane & 7) + ((lane >> 3) & 1) * 8;
    const int ckA = ((lane >> 4) << 3);
    const int rsel = (lane & 7) + ((lane >> 4) << 3);
    const int csel = ((lane >> 3) & 1) * 8;

    for (int s = 0; s < 12; s++) {
        if (s < 11) {
            issue((s + 1) * 32, (s + 1) & 1);
            asm volatile("cp.async.wait_group 1;\n");
        } else {
            asm volatile("cp.async.wait_group 0;\n");
        }
        __syncthreads();
        const uint32_t sa = sAu[s & 1], sb = sBu[s & 1];
#pragma unroll
        for (int kk = 0; kk < 32; kk += 16) {
            uint32_t a[4][4], bfr[2][4];
#pragma unroll
            for (int mt = 0; mt < 4; mt++)
                ldsm4(a[mt], sa + ((wm + mt * 16 + rmA) * SAP + kk + ckA) * 2);
            int rB = kk + rsel;
#pragma unroll
            for (int bt = 0; bt < 2; bt++)
                ldsm4t(bfr[bt], sb + (rB * SB + wn + bt * 16 + csel) * 2);
#pragma unroll
            for (int mt = 0; mt < 4; mt++)
#pragma unroll
                for (int j = 0; j < 4; j++)
                    mma_bf16(d[mt][j], a[mt], bfr[j >> 1][j & 1], bfr[j >> 1][2 + (j & 1)]);
        }
        __syncthreads();
    }

    // 2-pass transposed epilogue: 64 channels per pass
#pragma unroll
    for (int p = 0; p < 2; p++) {
        __syncthreads();
        if ((wid >> 2) == p) {
#pragma unroll
            for (int mt = 0; mt < 4; mt++)
#pragma unroll
                for (int j = 0; j < 4; j++) {
                    int row = wm + mt * 16 + g;
                    int colL = wn - p * 64 + j * 8 + 2 * t;
                    sm.tile[row * 66 + colL]           = d[mt][j][0];
                    sm.tile[row * 66 + colL + 1]       = d[mt][j][1];
                    sm.tile[(row + 8) * 66 + colL]     = d[mt][j][2];
                    sm.tile[(row + 8) * 66 + colL + 1] = d[mt][j][3];
                }
        }
        __syncthreads();
        int colc = tid >> 2;
        int ch = n0 + p * 64 + colc;
        float bvv = __ldg(&bias[ch]);
        size_t obase = ((size_t)b * CC + ch) * NN + m0;
#pragma unroll
        for (int jj = 0; jj < 8; jj++) {
            int m = (tid & 3) * 4 + 16 * jj;
            if (m0 + m + 4 > NN) continue;
            float v0 = sm.tile[(m + 0) * 66 + colc];
            float v1 = sm.tile[(m + 1) * 66 + colc];
            float v2 = sm.tile[(m + 2) * 66 + colc];
            float v3 = sm.tile[(m + 3) * 66 + colc];
            float4 xv = *(const float4*)&x[obase + m];
            float4 o;
            o.x = xv.x / (1.f + __expf(-(v0 + bvv)));
            o.y = xv.y / (1.f + __expf(-(v1 + bvv)));
            o.z = xv.z / (1.f + __expf(-(v2 + bvv)));
            o.w = xv.w / (1.f + __expf(-(v3 + bvv)));
            *(float4*)&out[obase + m] = o;
        }
    }
}

// ---------------- launch -------------------------------------------------------
extern "C" void kernel_launch(void* const* d_in, const int* in_sizes, int n_in,
                              void* d_out, int out_size) {
    const float* x      = (const float*)d_in[0];
    const float* qkv_w  = (const float*)d_in[1];
    const float* qkv_b  = (const float*)d_in[2];
    const float* proj_w = (const float*)d_in[3];
    const float* proj_b = (const float*)d_in[4];
    const float* an     = (const float*)d_in[5];
    const float* na     = (const float*)d_in[6];
    const float* dwc_w  = (const float*)d_in[7];
    const float* dwc_b  = (const float*)d_in[8];
    float* out = (float*)d_out;

    cudaFuncSetAttribute(stage2_mma_kernel,
                         cudaFuncAttributeMaxDynamicSharedMemorySize, S2_TOTAL);

    prep_kernel<<<PREP_TOTAL, 256>>>(x, qkv_w, proj_w, an, na);
    qkv_bf16_kernel<<<dim3((NN + 127) / 128, C3 / 128, BB), 256>>>(qkv_b);
    pool_kernel<<<(BB * AG * CC + 255) / 256, 256>>>();
    stage1_kernel<<<dim3(BB * NH, NSEG), 128>>>();
    stage1_reduce_kernel<<<BB * NH, 256>>>();
    stage2_mma_kernel<<<dim3((NN + S2M - 1) / S2M, NH, BB), 256, S2_TOTAL>>>(dwc_w, dwc_b);
    proj_bf16_kernel<<<dim3((NN + 127) / 128, CC / 128, BB), 256>>>(proj_b, x, out);
}